// round 1
// baseline (speedup 1.0000x reference)
#include <cuda_runtime.h>
#include <math.h>

// Problem constants
#define TOK   2048          // B*S
#define SEQ   1024
#define DM    768
#define DFF   3072
#define NH    12
#define HDIM  64
#define NV    32000
#define NL    6

// -------------------- scratch (device globals; no allocation allowed) -----
__device__ __align__(16) float g_x [TOK * DM];
__device__ __align__(16) float g_h [TOK * DM];
__device__ __align__(16) float g_q [TOK * DM];
__device__ __align__(16) float g_k [TOK * DM];
__device__ __align__(16) float g_v [TOK * DM];
__device__ __align__(16) float g_at[TOK * DM];
__device__ __align__(16) float g_ff[TOK * DFF];

// -------------------- embedding -------------------------------------------
__global__ void embed_kernel(const int* __restrict__ ctx,
                             const float* __restrict__ tok,
                             const float* __restrict__ pos) {
    int t = blockIdx.x;                 // 0..2047
    int token = ctx[t];
    int s = t & (SEQ - 1);
#pragma unroll
    for (int i = 0; i < 3; i++) {
        int d = threadIdx.x + i * 256;
        g_x[t * DM + d] = tok[token * DM + d] + pos[s * DM + d];
    }
}

// -------------------- layernorm (one block per row) ------------------------
__global__ void ln_kernel(const float* __restrict__ in,
                          const float* __restrict__ gg,
                          const float* __restrict__ bb,
                          float* __restrict__ out) {
    int row = blockIdx.x;
    const float* x = in + row * DM;
    float v[3];
    float s = 0.f, ss = 0.f;
#pragma unroll
    for (int i = 0; i < 3; i++) {
        v[i] = x[threadIdx.x + i * 256];
        s  += v[i];
        ss += v[i] * v[i];
    }
#pragma unroll
    for (int m = 16; m; m >>= 1) {
        s  += __shfl_xor_sync(0xffffffffu, s,  m);
        ss += __shfl_xor_sync(0xffffffffu, ss, m);
    }
    __shared__ float sa[8], sb[8];
    int w = threadIdx.x >> 5, lane = threadIdx.x & 31;
    if (lane == 0) { sa[w] = s; sb[w] = ss; }
    __syncthreads();
    s = 0.f; ss = 0.f;
#pragma unroll
    for (int i = 0; i < 8; i++) { s += sa[i]; ss += sb[i]; }
    float mean = s * (1.0f / DM);
    float var  = ss * (1.0f / DM) - mean * mean;
    float inv  = rsqrtf(var + 1e-5f);
#pragma unroll
    for (int i = 0; i < 3; i++) {
        int d = threadIdx.x + i * 256;
        out[row * DM + d] = (v[i] - mean) * inv * gg[d] + bb[d];
    }
}

// -------------------- SGEMM: C[M,N] = A[M,K] @ W[K,N] (+bias)(+relu)(+res) -
// Tiles: BM=128, BN=64, BK=16; 256 threads; 8x4 per thread.
// All dims used here are exact multiples of the tiles (M=2048; N in {768,3072,32000};
// K in {768,3072}) -> no bounds checks.
__global__ __launch_bounds__(256)
void sgemm_kernel(const float* __restrict__ A, const float* __restrict__ W,
                  const float* __restrict__ bias, const float* __restrict__ res,
                  float* __restrict__ C, int M, int N, int K, int relu) {
    __shared__ float As[16][132];   // transposed A tile, padded
    __shared__ float Bs[16][64];

    int tid = threadIdx.x;
    int tx = tid & 15;              // col group 0..15  -> cols tx*4..+3
    int ty = tid >> 4;              // row group 0..15  -> rows ty*8..+7

    int bm = blockIdx.y, bn = blockIdx.x;

    int a_row = tid >> 2;           // 0..63
    int a_k   = (tid & 3) << 2;     // 0,4,8,12
    const float* Ag = A + (size_t)(bm * 128 + a_row) * K + a_k;

    int b_k = tid >> 4;             // 0..15
    int b_n = (tid & 15) << 2;      // 0..60
    const float* Wg = W + (size_t)b_k * N + bn * 64 + b_n;

    float acc[8][4];
#pragma unroll
    for (int i = 0; i < 8; i++)
#pragma unroll
        for (int j = 0; j < 4; j++) acc[i][j] = 0.f;

    int nIter = K >> 4;
    for (int it = 0; it < nIter; it++) {
        float4 a0 = *(const float4*)Ag;
        float4 a1 = *(const float4*)(Ag + (size_t)64 * K);
        float4 w0 = *(const float4*)Wg;
        As[a_k + 0][a_row]      = a0.x;
        As[a_k + 1][a_row]      = a0.y;
        As[a_k + 2][a_row]      = a0.z;
        As[a_k + 3][a_row]      = a0.w;
        As[a_k + 0][a_row + 64] = a1.x;
        As[a_k + 1][a_row + 64] = a1.y;
        As[a_k + 2][a_row + 64] = a1.z;
        As[a_k + 3][a_row + 64] = a1.w;
        *(float4*)&Bs[b_k][b_n] = w0;
        __syncthreads();
#pragma unroll
        for (int kk = 0; kk < 16; kk++) {
            float4 av0 = *(const float4*)&As[kk][ty * 8];
            float4 av1 = *(const float4*)&As[kk][ty * 8 + 4];
            float4 bv  = *(const float4*)&Bs[kk][tx * 4];
            float a8[8] = {av0.x, av0.y, av0.z, av0.w, av1.x, av1.y, av1.z, av1.w};
            float b4[4] = {bv.x, bv.y, bv.z, bv.w};
#pragma unroll
            for (int i = 0; i < 8; i++)
#pragma unroll
                for (int j = 0; j < 4; j++)
                    acc[i][j] += a8[i] * b4[j];
        }
        __syncthreads();
        Ag += 16;
        Wg += (size_t)16 * N;
    }

    int row0 = bm * 128 + ty * 8;
    int col0 = bn * 64 + tx * 4;
    float4 bv = make_float4(0.f, 0.f, 0.f, 0.f);
    if (bias) bv = *(const float4*)(bias + col0);
#pragma unroll
    for (int i = 0; i < 8; i++) {
        size_t idx = (size_t)(row0 + i) * N + col0;
        float4 v;
        v.x = acc[i][0] + bv.x;
        v.y = acc[i][1] + bv.y;
        v.z = acc[i][2] + bv.z;
        v.w = acc[i][3] + bv.w;
        if (relu) {
            v.x = fmaxf(v.x, 0.f); v.y = fmaxf(v.y, 0.f);
            v.z = fmaxf(v.z, 0.f); v.w = fmaxf(v.w, 0.f);
        }
        if (res) {
            float4 r4 = *(const float4*)(res + idx);
            v.x += r4.x; v.y += r4.y; v.z += r4.z; v.w += r4.w;
        }
        *(float4*)(C + idx) = v;
    }
}

// -------------------- flash attention (causal) -----------------------------
// grid: (S/64, H, B); block 256 threads; 64x64 Q tile vs 64-wide KV tiles.
// Thread (ty,tx): rows ty*4..+3, score cols / out dims tx*4..+3.
#define SP 68
#define ATT_SMEM (4 * 64 * SP * 4)

__global__ __launch_bounds__(256)
void attn_kernel(const float* __restrict__ Q, const float* __restrict__ K,
                 const float* __restrict__ V, float* __restrict__ O) {
    extern __shared__ float sm[];
    float* Qs = sm;
    float* Ks = sm + 64 * SP;
    float* Vs = sm + 2 * 64 * SP;
    float* Ps = sm + 3 * 64 * SP;

    int qt = blockIdx.x, h = blockIdx.y, b = blockIdx.z;
    int tid = threadIdx.x;
    int tx = tid & 15, ty = tid >> 4;
    int r0 = ty * 4, c0 = tx * 4;

    const float scale = 0.125f;   // 1/sqrt(64)
    int base_q = (b * SEQ + qt * 64) * DM + h * HDIM;

    // load Q tile (pre-scaled)
#pragma unroll
    for (int i = 0; i < 4; i++) {
        int idx = tid + i * 256;
        int row = idx >> 4;
        int c4  = (idx & 15) << 2;
        float4 qv = *(const float4*)&Q[base_q + row * DM + c4];
        qv.x *= scale; qv.y *= scale; qv.z *= scale; qv.w *= scale;
        *(float4*)&Qs[row * SP + c4] = qv;
    }

    float o[4][4];
#pragma unroll
    for (int i = 0; i < 4; i++)
#pragma unroll
        for (int j = 0; j < 4; j++) o[i][j] = 0.f;
    float m[4], l[4];
#pragma unroll
    for (int i = 0; i < 4; i++) { m[i] = -INFINITY; l[i] = 0.f; }

    for (int kt = 0; kt <= qt; kt++) {
        __syncthreads();
        int base_k = (b * SEQ + kt * 64) * DM + h * HDIM;
#pragma unroll
        for (int i = 0; i < 4; i++) {
            int idx = tid + i * 256;
            int row = idx >> 4;
            int c4  = (idx & 15) << 2;
            *(float4*)&Ks[row * SP + c4] = *(const float4*)&K[base_k + row * DM + c4];
            *(float4*)&Vs[row * SP + c4] = *(const float4*)&V[base_k + row * DM + c4];
        }
        __syncthreads();

        float s[4][4];
#pragma unroll
        for (int i = 0; i < 4; i++)
#pragma unroll
            for (int j = 0; j < 4; j++) s[i][j] = 0.f;

#pragma unroll
        for (int d4 = 0; d4 < 16; d4++) {
            float4 qv[4], kv[4];
#pragma unroll
            for (int i = 0; i < 4; i++) qv[i] = *(const float4*)&Qs[(r0 + i) * SP + d4 * 4];
#pragma unroll
            for (int j = 0; j < 4; j++) kv[j] = *(const float4*)&Ks[(c0 + j) * SP + d4 * 4];
#pragma unroll
            for (int i = 0; i < 4; i++)
#pragma unroll
                for (int j = 0; j < 4; j++)
                    s[i][j] += qv[i].x * kv[j].x + qv[i].y * kv[j].y +
                               qv[i].z * kv[j].z + qv[i].w * kv[j].w;
        }

        if (kt == qt) {
#pragma unroll
            for (int i = 0; i < 4; i++)
#pragma unroll
                for (int j = 0; j < 4; j++)
                    if (c0 + j > r0 + i) s[i][j] = -INFINITY;
        }

#pragma unroll
        for (int i = 0; i < 4; i++) {
            float mx = fmaxf(fmaxf(s[i][0], s[i][1]), fmaxf(s[i][2], s[i][3]));
#pragma unroll
            for (int mk = 8; mk; mk >>= 1)
                mx = fmaxf(mx, __shfl_xor_sync(0xffffffffu, mx, mk));
            float mnew = fmaxf(m[i], mx);
            float fac = __expf(m[i] - mnew);
            float lsum = 0.f;
#pragma unroll
            for (int j = 0; j < 4; j++) {
                s[i][j] = __expf(s[i][j] - mnew);
                lsum += s[i][j];
            }
#pragma unroll
            for (int mk = 8; mk; mk >>= 1)
                lsum += __shfl_xor_sync(0xffffffffu, lsum, mk);
            l[i] = l[i] * fac + lsum;
            m[i] = mnew;
#pragma unroll
            for (int j = 0; j < 4; j++) o[i][j] *= fac;
            *(float4*)&Ps[(r0 + i) * SP + c0] =
                make_float4(s[i][0], s[i][1], s[i][2], s[i][3]);
        }
        __syncthreads();

#pragma unroll
        for (int k4 = 0; k4 < 16; k4++) {
            float4 pv[4], vv[4];
#pragma unroll
            for (int i = 0; i < 4; i++) pv[i] = *(const float4*)&Ps[(r0 + i) * SP + k4 * 4];
#pragma unroll
            for (int t = 0; t < 4; t++) vv[t] = *(const float4*)&Vs[(k4 * 4 + t) * SP + c0];
#pragma unroll
            for (int i = 0; i < 4; i++) {
                float p0 = pv[i].x, p1 = pv[i].y, p2 = pv[i].z, p3 = pv[i].w;
                o[i][0] += p0 * vv[0].x + p1 * vv[1].x + p2 * vv[2].x + p3 * vv[3].x;
                o[i][1] += p0 * vv[0].y + p1 * vv[1].y + p2 * vv[2].y + p3 * vv[3].y;
                o[i][2] += p0 * vv[0].z + p1 * vv[1].z + p2 * vv[2].z + p3 * vv[3].z;
                o[i][3] += p0 * vv[0].w + p1 * vv[1].w + p2 * vv[2].w + p3 * vv[3].w;
            }
        }
    }

#pragma unroll
    for (int i = 0; i < 4; i++) {
        float inv = 1.f / l[i];
        *(float4*)&O[base_q + (r0 + i) * DM + c0] =
            make_float4(o[i][0] * inv, o[i][1] * inv, o[i][2] * inv, o[i][3] * inv);
    }
}

// -------------------- host orchestration ----------------------------------
extern "C" void kernel_launch(void* const* d_in, const int* in_sizes, int n_in,
                              void* d_out, int out_size) {
    const int*   ctx  = (const int*)  d_in[0];
    const float* tok  = (const float*)d_in[1];
    const float* pos  = (const float*)d_in[2];
    const float* Wq   = (const float*)d_in[3];
    const float* Wk   = (const float*)d_in[4];
    const float* Wv   = (const float*)d_in[5];
    const float* Wo   = (const float*)d_in[6];
    const float* bo   = (const float*)d_in[7];
    const float* ln1g = (const float*)d_in[8];
    const float* ln1b = (const float*)d_in[9];
    const float* W1   = (const float*)d_in[10];
    const float* b1   = (const float*)d_in[11];
    const float* W2   = (const float*)d_in[12];
    const float* b2   = (const float*)d_in[13];
    const float* ln2g = (const float*)d_in[14];
    const float* ln2b = (const float*)d_in[15];
    const float* lnfg = (const float*)d_in[16];
    const float* lnfb = (const float*)d_in[17];
    const float* Wout = (const float*)d_in[18];
    const float* bout = (const float*)d_in[19];

    float *px, *ph, *pq, *pk, *pv, *pat, *pff;
    cudaGetSymbolAddress((void**)&px,  g_x);
    cudaGetSymbolAddress((void**)&ph,  g_h);
    cudaGetSymbolAddress((void**)&pq,  g_q);
    cudaGetSymbolAddress((void**)&pk,  g_k);
    cudaGetSymbolAddress((void**)&pv,  g_v);
    cudaGetSymbolAddress((void**)&pat, g_at);
    cudaGetSymbolAddress((void**)&pff, g_ff);

    cudaFuncSetAttribute(attn_kernel,
                         cudaFuncAttributeMaxDynamicSharedMemorySize, ATT_SMEM);

    embed_kernel<<<TOK, 256>>>(ctx, tok, pos);

    dim3 gD(DM / 64, TOK / 128);     // N=768 GEMMs
    dim3 gF(DFF / 64, TOK / 128);    // N=3072 GEMM
    dim3 gV(NV / 64, TOK / 128);     // final vocab GEMM

    for (int l = 0; l < NL; l++) {
        const float* wq = Wq + (size_t)l * DM * DM;
        const float* wk = Wk + (size_t)l * DM * DM;
        const float* wv = Wv + (size_t)l * DM * DM;
        const float* wo = Wo + (size_t)l * DM * DM;
        const float* w1 = W1 + (size_t)l * DM * DFF;
        const float* w2 = W2 + (size_t)l * DFF * DM;

        ln_kernel<<<TOK, 256>>>(px, ln1g + l * DM, ln1b + l * DM, ph);
        sgemm_kernel<<<gD, 256>>>(ph, wq, nullptr, nullptr, pq, TOK, DM, DM, 0);
        sgemm_kernel<<<gD, 256>>>(ph, wk, nullptr, nullptr, pk, TOK, DM, DM, 0);
        sgemm_kernel<<<gD, 256>>>(ph, wv, nullptr, nullptr, pv, TOK, DM, DM, 0);
        attn_kernel<<<dim3(SEQ / 64, NH, 2), 256, ATT_SMEM>>>(pq, pk, pv, pat);
        sgemm_kernel<<<gD, 256>>>(pat, wo, bo + l * DM, px, px, TOK, DM, DM, 0);
        ln_kernel<<<TOK, 256>>>(px, ln2g + l * DM, ln2b + l * DM, ph);
        sgemm_kernel<<<gF, 256>>>(ph, w1, b1 + (size_t)l * DFF, nullptr, pff,
                                  TOK, DFF, DM, 1);
        sgemm_kernel<<<gD, 256>>>(pff, w2, b2 + l * DM, px, px, TOK, DM, DFF, 0);
    }

    ln_kernel<<<TOK, 256>>>(px, lnfg, lnfb, ph);
    sgemm_kernel<<<gV, 256>>>(ph, Wout, bout, nullptr, (float*)d_out,
                              TOK, NV, DM, 0);
}

// round 2
// speedup vs baseline: 1.8975x; 1.8975x over previous
#include <cuda_runtime.h>
#include <math.h>
#include <stdint.h>

// Problem constants
#define TOK   2048          // B*S
#define SEQ   1024
#define DM    768
#define DFF   3072
#define NH    12
#define HDIM  64
#define NV    32000
#define NL    6

// -------------------- scratch (device globals; no allocation allowed) -----
__device__ __align__(16) float g_x [TOK * DM];
__device__ __align__(16) float g_h [TOK * DM];
__device__ __align__(16) float g_q [TOK * DM];
__device__ __align__(16) float g_k [TOK * DM];
__device__ __align__(16) float g_v [TOK * DM];
__device__ __align__(16) float g_at[TOK * DM];
__device__ __align__(16) float g_ff[TOK * DFF];

// -------------------- embedding -------------------------------------------
__global__ void embed_kernel(const int* __restrict__ ctx,
                             const float* __restrict__ tok,
                             const float* __restrict__ pos) {
    int t = blockIdx.x;
    int token = ctx[t];
    int s = t & (SEQ - 1);
#pragma unroll
    for (int i = 0; i < 3; i++) {
        int d = threadIdx.x + i * 256;
        g_x[t * DM + d] = tok[token * DM + d] + pos[s * DM + d];
    }
}

// -------------------- layernorm (one block per row) ------------------------
__global__ void ln_kernel(const float* __restrict__ in,
                          const float* __restrict__ gg,
                          const float* __restrict__ bb,
                          float* __restrict__ out) {
    int row = blockIdx.x;
    const float* x = in + row * DM;
    float v[3];
    float s = 0.f, ss = 0.f;
#pragma unroll
    for (int i = 0; i < 3; i++) {
        v[i] = x[threadIdx.x + i * 256];
        s  += v[i];
        ss += v[i] * v[i];
    }
#pragma unroll
    for (int m = 16; m; m >>= 1) {
        s  += __shfl_xor_sync(0xffffffffu, s,  m);
        ss += __shfl_xor_sync(0xffffffffu, ss, m);
    }
    __shared__ float sa[8], sb[8];
    int w = threadIdx.x >> 5, lane = threadIdx.x & 31;
    if (lane == 0) { sa[w] = s; sb[w] = ss; }
    __syncthreads();
    s = 0.f; ss = 0.f;
#pragma unroll
    for (int i = 0; i < 8; i++) { s += sa[i]; ss += sb[i]; }
    float mean = s * (1.0f / DM);
    float var  = ss * (1.0f / DM) - mean * mean;
    float inv  = rsqrtf(var + 1e-5f);
#pragma unroll
    for (int i = 0; i < 3; i++) {
        int d = threadIdx.x + i * 256;
        out[row * DM + d] = (v[i] - mean) * inv * gg[d] + bb[d];
    }
}

// -------------------- tf32 tensor-core GEMM --------------------------------
// C[M,N] = A[M,K] @ W[K,N] (+bias)(+relu)(+res)
// mma.sync.m16n8k8.tf32, BK=16, double-buffered smem, 256 threads.
// Warp layout: 2 (m) x 4 (n). BM in {64,128}, BN = 128.
// Smem strides: LDA=20, LDB=136 -> conflict-free fragment LDS (verified mod 32).

__device__ __forceinline__ uint32_t f2tf32(float f) {
    uint32_t u;
    asm("cvt.rna.tf32.f32 %0, %1;" : "=r"(u) : "f"(f));
    return u;
}

__device__ __forceinline__ void mma_tf32(float* c, const uint32_t* a, const uint32_t* b) {
    asm volatile(
        "mma.sync.aligned.m16n8k8.row.col.f32.tf32.tf32.f32 "
        "{%0,%1,%2,%3}, {%4,%5,%6,%7}, {%8,%9}, {%0,%1,%2,%3};"
        : "+f"(c[0]), "+f"(c[1]), "+f"(c[2]), "+f"(c[3])
        : "r"(a[0]), "r"(a[1]), "r"(a[2]), "r"(a[3]), "r"(b[0]), "r"(b[1]));
}

#define LDA 20
#define LDB 136

template<int BM>
__global__ __launch_bounds__(256)
void tgemm(const float* __restrict__ A, const float* __restrict__ W,
           const float* __restrict__ bias, const float* __restrict__ res,
           float* __restrict__ C, int M, int N, int K, int relu) {
    constexpr int BN = 128;
    constexpr int WM = BM / 2;       // 64 or 32
    constexpr int WN = 32;
    constexpr int MT = WM / 16;      // 4 or 2
    constexpr int NT = WN / 8;       // 4
    constexpr int NA = BM / 64;      // float4 A-loads per thread (2 or 1)
    constexpr int NB = 2;            // float4 B-loads per thread

    __shared__ uint32_t As[2][BM][LDA];
    __shared__ uint32_t Bs[2][16][LDB];

    int tid  = threadIdx.x;
    int lane = tid & 31;
    int warp = tid >> 5;
    int warp_m = warp >> 2;          // 0..1
    int warp_n = warp & 3;           // 0..3
    int g = lane >> 2;               // 0..7
    int t = lane & 3;                // 0..3

    int bm = blockIdx.x, bn = blockIdx.y;

    // staging indices
    int arow[NA], akc[NA];
#pragma unroll
    for (int i = 0; i < NA; i++) {
        int idx = tid + i * 256;
        arow[i] = idx >> 2;
        akc[i]  = (idx & 3) << 2;
    }
    int brow[NB], bcol[NB];
#pragma unroll
    for (int i = 0; i < NB; i++) {
        int idx = tid + i * 256;
        brow[i] = idx >> 5;
        bcol[i] = (idx & 31) << 2;
    }

    const float* Ag[NA];
#pragma unroll
    for (int i = 0; i < NA; i++)
        Ag[i] = A + (size_t)(bm * BM + arow[i]) * K + akc[i];
    const float* Wg[NB];
#pragma unroll
    for (int i = 0; i < NB; i++)
        Wg[i] = W + (size_t)brow[i] * N + bn * BN + bcol[i];

    float acc[MT][NT][4];
#pragma unroll
    for (int mi = 0; mi < MT; mi++)
#pragma unroll
        for (int ni = 0; ni < NT; ni++)
#pragma unroll
            for (int j = 0; j < 4; j++) acc[mi][ni][j] = 0.f;

    float4 ar[NA], br[NB];

    // prologue: tile 0
#pragma unroll
    for (int i = 0; i < NA; i++) ar[i] = *(const float4*)Ag[i];
#pragma unroll
    for (int i = 0; i < NB; i++) br[i] = *(const float4*)Wg[i];
#pragma unroll
    for (int i = 0; i < NA; i++) {
        As[0][arow[i]][akc[i] + 0] = f2tf32(ar[i].x);
        As[0][arow[i]][akc[i] + 1] = f2tf32(ar[i].y);
        As[0][arow[i]][akc[i] + 2] = f2tf32(ar[i].z);
        As[0][arow[i]][akc[i] + 3] = f2tf32(ar[i].w);
    }
#pragma unroll
    for (int i = 0; i < NB; i++) {
        Bs[0][brow[i]][bcol[i] + 0] = f2tf32(br[i].x);
        Bs[0][brow[i]][bcol[i] + 1] = f2tf32(br[i].y);
        Bs[0][brow[i]][bcol[i] + 2] = f2tf32(br[i].z);
        Bs[0][brow[i]][bcol[i] + 3] = f2tf32(br[i].w);
    }
    __syncthreads();

    int nIter = K >> 4;
    for (int it = 0; it < nIter; it++) {
        int cur = it & 1;
        bool has_next = (it + 1 < nIter);
        if (has_next) {
#pragma unroll
            for (int i = 0; i < NA; i++) {
                Ag[i] += 16;
                ar[i] = *(const float4*)Ag[i];
            }
#pragma unroll
            for (int i = 0; i < NB; i++) {
                Wg[i] += (size_t)16 * N;
                br[i] = *(const float4*)Wg[i];
            }
        }

        // compute on buffer cur
#pragma unroll
        for (int kk = 0; kk < 2; kk++) {
            uint32_t afr[MT][4];
            uint32_t bfr[NT][2];
            int k8 = kk * 8;
#pragma unroll
            for (int mi = 0; mi < MT; mi++) {
                int row = warp_m * WM + mi * 16 + g;
                afr[mi][0] = As[cur][row    ][k8 + t];
                afr[mi][1] = As[cur][row + 8][k8 + t];
                afr[mi][2] = As[cur][row    ][k8 + t + 4];
                afr[mi][3] = As[cur][row + 8][k8 + t + 4];
            }
#pragma unroll
            for (int ni = 0; ni < NT; ni++) {
                int col = warp_n * WN + ni * 8 + g;
                bfr[ni][0] = Bs[cur][k8 + t    ][col];
                bfr[ni][1] = Bs[cur][k8 + t + 4][col];
            }
#pragma unroll
            for (int mi = 0; mi < MT; mi++)
#pragma unroll
                for (int ni = 0; ni < NT; ni++)
                    mma_tf32(acc[mi][ni], afr[mi], bfr[ni]);
        }

        if (has_next) {
            int nxt = cur ^ 1;
#pragma unroll
            for (int i = 0; i < NA; i++) {
                As[nxt][arow[i]][akc[i] + 0] = f2tf32(ar[i].x);
                As[nxt][arow[i]][akc[i] + 1] = f2tf32(ar[i].y);
                As[nxt][arow[i]][akc[i] + 2] = f2tf32(ar[i].z);
                As[nxt][arow[i]][akc[i] + 3] = f2tf32(ar[i].w);
            }
#pragma unroll
            for (int i = 0; i < NB; i++) {
                Bs[nxt][brow[i]][bcol[i] + 0] = f2tf32(br[i].x);
                Bs[nxt][brow[i]][bcol[i] + 1] = f2tf32(br[i].y);
                Bs[nxt][brow[i]][bcol[i] + 2] = f2tf32(br[i].z);
                Bs[nxt][brow[i]][bcol[i] + 3] = f2tf32(br[i].w);
            }
        }
        __syncthreads();
    }

    // epilogue
#pragma unroll
    for (int mi = 0; mi < MT; mi++) {
        int row0 = bm * BM + warp_m * WM + mi * 16 + g;
#pragma unroll
        for (int ni = 0; ni < NT; ni++) {
            int col = bn * BN + warp_n * WN + ni * 8 + 2 * t;
            float b0 = 0.f, b1 = 0.f;
            if (bias) { b0 = bias[col]; b1 = bias[col + 1]; }
#pragma unroll
            for (int half = 0; half < 2; half++) {
                int row = row0 + half * 8;
                float v0 = acc[mi][ni][half * 2 + 0] + b0;
                float v1 = acc[mi][ni][half * 2 + 1] + b1;
                if (relu) { v0 = fmaxf(v0, 0.f); v1 = fmaxf(v1, 0.f); }
                size_t idx = (size_t)row * N + col;
                if (res) {
                    float2 r2 = *(const float2*)(res + idx);
                    v0 += r2.x; v1 += r2.y;
                }
                *(float2*)(C + idx) = make_float2(v0, v1);
            }
        }
    }
}

// -------------------- flash attention (causal, fp32) -----------------------
#define SP 68
#define ATT_SMEM (4 * 64 * SP * 4)

__global__ __launch_bounds__(256)
void attn_kernel(const float* __restrict__ Q, const float* __restrict__ K,
                 const float* __restrict__ V, float* __restrict__ O) {
    extern __shared__ float sm[];
    float* Qs = sm;
    float* Ks = sm + 64 * SP;
    float* Vs = sm + 2 * 64 * SP;
    float* Ps = sm + 3 * 64 * SP;

    int qt = blockIdx.x, h = blockIdx.y, b = blockIdx.z;
    int tid = threadIdx.x;
    int tx = tid & 15, ty = tid >> 4;
    int r0 = ty * 4, c0 = tx * 4;

    const float scale = 0.125f;
    int base_q = (b * SEQ + qt * 64) * DM + h * HDIM;

#pragma unroll
    for (int i = 0; i < 4; i++) {
        int idx = tid + i * 256;
        int row = idx >> 4;
        int c4  = (idx & 15) << 2;
        float4 qv = *(const float4*)&Q[base_q + row * DM + c4];
        qv.x *= scale; qv.y *= scale; qv.z *= scale; qv.w *= scale;
        *(float4*)&Qs[row * SP + c4] = qv;
    }

    float o[4][4];
#pragma unroll
    for (int i = 0; i < 4; i++)
#pragma unroll
        for (int j = 0; j < 4; j++) o[i][j] = 0.f;
    float m[4], l[4];
#pragma unroll
    for (int i = 0; i < 4; i++) { m[i] = -INFINITY; l[i] = 0.f; }

    for (int kt = 0; kt <= qt; kt++) {
        __syncthreads();
        int base_k = (b * SEQ + kt * 64) * DM + h * HDIM;
#pragma unroll
        for (int i = 0; i < 4; i++) {
            int idx = tid + i * 256;
            int row = idx >> 4;
            int c4  = (idx & 15) << 2;
            *(float4*)&Ks[row * SP + c4] = *(const float4*)&K[base_k + row * DM + c4];
            *(float4*)&Vs[row * SP + c4] = *(const float4*)&V[base_k + row * DM + c4];
        }
        __syncthreads();

        float s[4][4];
#pragma unroll
        for (int i = 0; i < 4; i++)
#pragma unroll
            for (int j = 0; j < 4; j++) s[i][j] = 0.f;

#pragma unroll
        for (int d4 = 0; d4 < 16; d4++) {
            float4 qv[4], kv[4];
#pragma unroll
            for (int i = 0; i < 4; i++) qv[i] = *(const float4*)&Qs[(r0 + i) * SP + d4 * 4];
#pragma unroll
            for (int j = 0; j < 4; j++) kv[j] = *(const float4*)&Ks[(c0 + j) * SP + d4 * 4];
#pragma unroll
            for (int i = 0; i < 4; i++)
#pragma unroll
                for (int j = 0; j < 4; j++)
                    s[i][j] += qv[i].x * kv[j].x + qv[i].y * kv[j].y +
                               qv[i].z * kv[j].z + qv[i].w * kv[j].w;
        }

        if (kt == qt) {
#pragma unroll
            for (int i = 0; i < 4; i++)
#pragma unroll
                for (int j = 0; j < 4; j++)
                    if (c0 + j > r0 + i) s[i][j] = -INFINITY;
        }

#pragma unroll
        for (int i = 0; i < 4; i++) {
            float mx = fmaxf(fmaxf(s[i][0], s[i][1]), fmaxf(s[i][2], s[i][3]));
#pragma unroll
            for (int mk = 8; mk; mk >>= 1)
                mx = fmaxf(mx, __shfl_xor_sync(0xffffffffu, mx, mk));
            float mnew = fmaxf(m[i], mx);
            float fac = __expf(m[i] - mnew);
            float lsum = 0.f;
#pragma unroll
            for (int j = 0; j < 4; j++) {
                s[i][j] = __expf(s[i][j] - mnew);
                lsum += s[i][j];
            }
#pragma unroll
            for (int mk = 8; mk; mk >>= 1)
                lsum += __shfl_xor_sync(0xffffffffu, lsum, mk);
            l[i] = l[i] * fac + lsum;
            m[i] = mnew;
#pragma unroll
            for (int j = 0; j < 4; j++) o[i][j] *= fac;
            *(float4*)&Ps[(r0 + i) * SP + c0] =
                make_float4(s[i][0], s[i][1], s[i][2], s[i][3]);
        }
        __syncthreads();

#pragma unroll
        for (int k4 = 0; k4 < 16; k4++) {
            float4 pv[4], vv[4];
#pragma unroll
            for (int i = 0; i < 4; i++) pv[i] = *(const float4*)&Ps[(r0 + i) * SP + k4 * 4];
#pragma unroll
            for (int tt = 0; tt < 4; tt++) vv[tt] = *(const float4*)&Vs[(k4 * 4 + tt) * SP + c0];
#pragma unroll
            for (int i = 0; i < 4; i++) {
                float p0 = pv[i].x, p1 = pv[i].y, p2 = pv[i].z, p3 = pv[i].w;
                o[i][0] += p0 * vv[0].x + p1 * vv[1].x + p2 * vv[2].x + p3 * vv[3].x;
                o[i][1] += p0 * vv[0].y + p1 * vv[1].y + p2 * vv[2].y + p3 * vv[3].y;
                o[i][2] += p0 * vv[0].z + p1 * vv[1].z + p2 * vv[2].z + p3 * vv[3].z;
                o[i][3] += p0 * vv[0].w + p1 * vv[1].w + p2 * vv[2].w + p3 * vv[3].w;
            }
        }
    }

#pragma unroll
    for (int i = 0; i < 4; i++) {
        float inv = 1.f / l[i];
        *(float4*)&O[base_q + (r0 + i) * DM + c0] =
            make_float4(o[i][0] * inv, o[i][1] * inv, o[i][2] * inv, o[i][3] * inv);
    }
}

// -------------------- host orchestration ----------------------------------
extern "C" void kernel_launch(void* const* d_in, const int* in_sizes, int n_in,
                              void* d_out, int out_size) {
    const int*   ctx  = (const int*)  d_in[0];
    const float* tok  = (const float*)d_in[1];
    const float* pos  = (const float*)d_in[2];
    const float* Wq   = (const float*)d_in[3];
    const float* Wk   = (const float*)d_in[4];
    const float* Wv   = (const float*)d_in[5];
    const float* Wo   = (const float*)d_in[6];
    const float* bo   = (const float*)d_in[7];
    const float* ln1g = (const float*)d_in[8];
    const float* ln1b = (const float*)d_in[9];
    const float* W1   = (const float*)d_in[10];
    const float* b1   = (const float*)d_in[11];
    const float* W2   = (const float*)d_in[12];
    const float* b2   = (const float*)d_in[13];
    const float* ln2g = (const float*)d_in[14];
    const float* ln2b = (const float*)d_in[15];
    const float* lnfg = (const float*)d_in[16];
    const float* lnfb = (const float*)d_in[17];
    const float* Wout = (const float*)d_in[18];
    const float* bout = (const float*)d_in[19];

    float *px, *ph, *pq, *pk, *pv, *pat, *pff;
    cudaGetSymbolAddress((void**)&px,  g_x);
    cudaGetSymbolAddress((void**)&ph,  g_h);
    cudaGetSymbolAddress((void**)&pq,  g_q);
    cudaGetSymbolAddress((void**)&pk,  g_k);
    cudaGetSymbolAddress((void**)&pv,  g_v);
    cudaGetSymbolAddress((void**)&pat, g_at);
    cudaGetSymbolAddress((void**)&pff, g_ff);

    cudaFuncSetAttribute(attn_kernel,
                         cudaFuncAttributeMaxDynamicSharedMemorySize, ATT_SMEM);

    embed_kernel<<<TOK, 256>>>(ctx, tok, pos);

    dim3 gD(TOK / 64,  DM  / 128);   // N=768 GEMMs  (BM=64)  -> 32x6 = 192 CTAs
    dim3 gF(TOK / 128, DFF / 128);   // W1           (BM=128) -> 16x24
    dim3 gV(TOK / 128, NV  / 128);   // vocab        (BM=128) -> 16x250

    for (int l = 0; l < NL; l++) {
        const float* wq = Wq + (size_t)l * DM * DM;
        const float* wk = Wk + (size_t)l * DM * DM;
        const float* wv = Wv + (size_t)l * DM * DM;
        const float* wo = Wo + (size_t)l * DM * DM;
        const float* w1 = W1 + (size_t)l * DM * DFF;
        const float* w2 = W2 + (size_t)l * DFF * DM;

        ln_kernel<<<TOK, 256>>>(px, ln1g + l * DM, ln1b + l * DM, ph);
        tgemm<64><<<gD, 256>>>(ph, wq, nullptr, nullptr, pq, TOK, DM, DM, 0);
        tgemm<64><<<gD, 256>>>(ph, wk, nullptr, nullptr, pk, TOK, DM, DM, 0);
        tgemm<64><<<gD, 256>>>(ph, wv, nullptr, nullptr, pv, TOK, DM, DM, 0);
        attn_kernel<<<dim3(SEQ / 64, NH, 2), 256, ATT_SMEM>>>(pq, pk, pv, pat);
        tgemm<64><<<gD, 256>>>(pat, wo, bo + l * DM, px, px, TOK, DM, DM, 0);
        ln_kernel<<<TOK, 256>>>(px, ln2g + l * DM, ln2b + l * DM, ph);
        tgemm<128><<<gF, 256>>>(ph, w1, b1 + (size_t)l * DFF, nullptr, pff,
                                TOK, DFF, DM, 1);
        tgemm<64><<<gD, 256>>>(pff, w2, b2 + l * DM, px, px, TOK, DM, DFF, 0);
    }

    ln_kernel<<<TOK, 256>>>(px, lnfg, lnfb, ph);
    tgemm<128><<<gV, 256>>>(ph, Wout, bout, nullptr, (float*)d_out,
                            TOK, NV, DM, 0);
}

// round 3
// speedup vs baseline: 2.0032x; 1.0557x over previous
#include <cuda_runtime.h>
#include <cuda_bf16.h>
#include <math.h>
#include <stdint.h>

// Problem constants
#define TOK   2048          // B*S
#define SEQ   1024
#define DM    768
#define DFF   3072
#define NH    12
#define HDIM  64
#define NV    32000
#define NL    6

// -------------------- scratch (device globals; no allocation allowed) -----
__device__ __align__(16) float g_x [TOK * DM];
__device__ __align__(16) float g_h [TOK * DM];
__device__ __align__(16) float g_q [TOK * DM];
__device__ __align__(16) float g_k [TOK * DM];
__device__ __align__(16) float g_v [TOK * DM];
__device__ __align__(16) float g_at[TOK * DM];
__device__ __align__(16) float g_ff[TOK * DFF];

// -------------------- embedding -------------------------------------------
__global__ void embed_kernel(const int* __restrict__ ctx,
                             const float* __restrict__ tok,
                             const float* __restrict__ pos) {
    int t = blockIdx.x;
    int token = ctx[t];
    int s = t & (SEQ - 1);
#pragma unroll
    for (int i = 0; i < 3; i++) {
        int d = threadIdx.x + i * 256;
        g_x[t * DM + d] = tok[token * DM + d] + pos[s * DM + d];
    }
}

// -------------------- layernorm (one block per row) ------------------------
__global__ void ln_kernel(const float* __restrict__ in,
                          const float* __restrict__ gg,
                          const float* __restrict__ bb,
                          float* __restrict__ out) {
    int row = blockIdx.x;
    const float* x = in + row * DM;
    float v[3];
    float s = 0.f, ss = 0.f;
#pragma unroll
    for (int i = 0; i < 3; i++) {
        v[i] = x[threadIdx.x + i * 256];
        s  += v[i];
        ss += v[i] * v[i];
    }
#pragma unroll
    for (int m = 16; m; m >>= 1) {
        s  += __shfl_xor_sync(0xffffffffu, s,  m);
        ss += __shfl_xor_sync(0xffffffffu, ss, m);
    }
    __shared__ float sa[8], sb[8];
    int w = threadIdx.x >> 5, lane = threadIdx.x & 31;
    if (lane == 0) { sa[w] = s; sb[w] = ss; }
    __syncthreads();
    s = 0.f; ss = 0.f;
#pragma unroll
    for (int i = 0; i < 8; i++) { s += sa[i]; ss += sb[i]; }
    float mean = s * (1.0f / DM);
    float var  = ss * (1.0f / DM) - mean * mean;
    float inv  = rsqrtf(var + 1e-5f);
#pragma unroll
    for (int i = 0; i < 3; i++) {
        int d = threadIdx.x + i * 256;
        out[row * DM + d] = (v[i] - mean) * inv * gg[d] + bb[d];
    }
}

// -------------------- bf16-split tensor-core GEMM --------------------------
// C[M,N] = A[M,K] @ W[K,N] (+bias)(+relu)(+res), fp32 in/out.
// Each operand split into bf16 hi+lo; D += Ah*Bh + Ah*Bl + Al*Bh (fp32 accum)
// mma.m16n8k16.bf16 + ldmatrix (A: x4, B: x4.trans so W keeps [K,N] layout).
// BM=BN=128, BK=64, 256 threads, warps 2(m) x 4(n), warp tile 64x32.
// Smem rows: A=128B, B=256B; 16B-chunk xor swizzle -> conflict-free ldmatrix.

__device__ __forceinline__ uint32_t cvta_smem(const void* p) {
    return (uint32_t)__cvta_generic_to_shared(p);
}

__device__ __forceinline__ void ldm_x4(uint32_t* r, uint32_t addr) {
    asm volatile("ldmatrix.sync.aligned.m8n8.x4.shared.b16 {%0,%1,%2,%3},[%4];"
                 : "=r"(r[0]), "=r"(r[1]), "=r"(r[2]), "=r"(r[3]) : "r"(addr));
}
__device__ __forceinline__ void ldm_x4_t(uint32_t* r, uint32_t addr) {
    asm volatile("ldmatrix.sync.aligned.m8n8.x4.trans.shared.b16 {%0,%1,%2,%3},[%4];"
                 : "=r"(r[0]), "=r"(r[1]), "=r"(r[2]), "=r"(r[3]) : "r"(addr));
}

__device__ __forceinline__ void mma_bf16(float* c, const uint32_t* a, const uint32_t* b) {
    asm volatile(
        "mma.sync.aligned.m16n8k16.row.col.f32.bf16.bf16.f32 "
        "{%0,%1,%2,%3},{%4,%5,%6,%7},{%8,%9},{%0,%1,%2,%3};"
        : "+f"(c[0]), "+f"(c[1]), "+f"(c[2]), "+f"(c[3])
        : "r"(a[0]), "r"(a[1]), "r"(a[2]), "r"(a[3]), "r"(b[0]), "r"(b[1]));
}

// split two floats into packed bf16x2 hi and lo parts
__device__ __forceinline__ void split2(float x, float y, uint32_t& h, uint32_t& l) {
    __nv_bfloat162 hh = __floats2bfloat162_rn(x, y);
    float hx = __bfloat162float(hh.x);
    float hy = __bfloat162float(hh.y);
    __nv_bfloat162 ll = __floats2bfloat162_rn(x - hx, y - hy);
    h = *(uint32_t*)&hh;
    l = *(uint32_t*)&ll;
}

// smem layout per stage (65536 B): AHI[16K] ALO[16K] BHI[16K] BLO[16K]
// A tile: 128 rows x 64 bf16 (128B rows). B tile: 64 rows(k) x 128 bf16 (256B rows).
#define GEMM_SMEM (2 * 65536)

__device__ __forceinline__ uint32_t swzA(int row, int kchunk) {
    return (uint32_t)(row * 128 + ((kchunk ^ (row & 7)) << 4));
}
__device__ __forceinline__ uint32_t swzB(int k, int nchunk) {  // nchunk = n/8, 0..15
    int c = ((nchunk & 7) ^ (k & 7)) | (nchunk & 8);
    return (uint32_t)(k * 256 + (c << 4));
}

__global__ __launch_bounds__(256, 1)
void hgemm(const float* __restrict__ A, const float* __restrict__ W,
           const float* __restrict__ bias, const float* __restrict__ res,
           float* __restrict__ C, int M, int N, int K, int relu) {
    extern __shared__ char smc[];
    uint32_t sbase = cvta_smem(smc);

    int tid  = threadIdx.x;
    int lane = tid & 31;
    int warp = tid >> 5;
    int wm = warp >> 2;              // 0..1
    int wn = warp & 3;               // 0..3
    int g  = lane >> 2;              // 0..7
    int tg = lane & 3;               // 0..3

    int bm = blockIdx.x, bn = blockIdx.y;

    // staging coordinates
    int a_row[4], a_kc[4];           // A: 4 units, chunk = row*8 + kc
    int b_k[4],  b_nc[4];            // B: 4 units, chunk = k*16 + nc
#pragma unroll
    for (int u = 0; u < 4; u++) {
        int cu = tid + u * 256;
        a_row[u] = cu >> 3;  a_kc[u] = cu & 7;
        b_k[u]   = cu >> 4;  b_nc[u] = cu & 15;
    }

    float4 ar[8], br[8];
    float acc[4][4][4];
#pragma unroll
    for (int mi = 0; mi < 4; mi++)
#pragma unroll
        for (int ni = 0; ni < 4; ni++)
#pragma unroll
            for (int j = 0; j < 4; j++) acc[mi][ni][j] = 0.f;

    // ---- load / store helpers (inlined manually via macros of loops) ----
#define LOAD_TILES(IT)                                                        \
    {                                                                         \
        _Pragma("unroll")                                                     \
        for (int u = 0; u < 4; u++) {                                         \
            const float* p = A + (size_t)(bm * 128 + a_row[u]) * K            \
                             + (IT) * 64 + a_kc[u] * 8;                       \
            ar[2 * u]     = *(const float4*)p;                                \
            ar[2 * u + 1] = *(const float4*)(p + 4);                          \
        }                                                                     \
        _Pragma("unroll")                                                     \
        for (int u = 0; u < 4; u++) {                                         \
            const float* p = W + (size_t)((IT) * 64 + b_k[u]) * N             \
                             + bn * 128 + b_nc[u] * 8;                        \
            br[2 * u]     = *(const float4*)p;                                \
            br[2 * u + 1] = *(const float4*)(p + 4);                          \
        }                                                                     \
    }

#define STORE_TILES(ST)                                                       \
    {                                                                         \
        char* base = smc + (ST) * 65536;                                      \
        _Pragma("unroll")                                                     \
        for (int u = 0; u < 4; u++) {                                         \
            uint4 h, l;                                                       \
            split2(ar[2*u].x,   ar[2*u].y,   h.x, l.x);                       \
            split2(ar[2*u].z,   ar[2*u].w,   h.y, l.y);                       \
            split2(ar[2*u+1].x, ar[2*u+1].y, h.z, l.z);                       \
            split2(ar[2*u+1].z, ar[2*u+1].w, h.w, l.w);                       \
            uint32_t off = swzA(a_row[u], a_kc[u]);                           \
            *(uint4*)(base + off)         = h;                                \
            *(uint4*)(base + 16384 + off) = l;                                \
        }                                                                     \
        _Pragma("unroll")                                                     \
        for (int u = 0; u < 4; u++) {                                         \
            uint4 h, l;                                                       \
            split2(br[2*u].x,   br[2*u].y,   h.x, l.x);                       \
            split2(br[2*u].z,   br[2*u].w,   h.y, l.y);                       \
            split2(br[2*u+1].x, br[2*u+1].y, h.z, l.z);                       \
            split2(br[2*u+1].z, br[2*u+1].w, h.w, l.w);                       \
            uint32_t off = swzB(b_k[u], b_nc[u]);                             \
            *(uint4*)(base + 32768 + off) = h;                                \
            *(uint4*)(base + 49152 + off) = l;                                \
        }                                                                     \
    }

    int nIter = K >> 6;

    LOAD_TILES(0);
    STORE_TILES(0);
    __syncthreads();

    // per-thread ldmatrix address components (lane-dependent, loop-invariant)
    int a_lrow = wm * 64 + (lane & 15);          // + mi*16
    int a_koff = (lane & 16) ? 1 : 0;            // extra 16B chunk
    int b_lk   = (lane & 15);                    // + k16*16
    int b_noff = (lane & 16) ? 1 : 0;            // + 8 n

    for (int it = 0; it < nIter; it++) {
        int cur = it & 1;
        bool has_next = (it + 1 < nIter);
        if (has_next) LOAD_TILES(it + 1);

        uint32_t abase = sbase + cur * 65536;
        uint32_t bbase = abase + 32768;

#pragma unroll
        for (int k16 = 0; k16 < 4; k16++) {
            uint32_t Ah[4][4], Al[4][4];
            int kchunk = k16 * 2 + a_koff;
#pragma unroll
            for (int mi = 0; mi < 4; mi++) {
                int row = a_lrow + mi * 16;
                uint32_t off = swzA(row, kchunk);
                ldm_x4(Ah[mi], abase + off);
                ldm_x4(Al[mi], abase + 16384 + off);
            }
            uint32_t Bh[4][2], Bl[4][2];
            int kk = k16 * 16 + b_lk;
#pragma unroll
            for (int p = 0; p < 2; p++) {
                int nchunk = (wn * 32 + p * 16) / 8 + b_noff;
                uint32_t off = swzB(kk, nchunk);
                uint32_t r4[4];
                ldm_x4_t(r4, bbase + off);
                Bh[p*2][0] = r4[0]; Bh[p*2][1] = r4[1];
                Bh[p*2+1][0] = r4[2]; Bh[p*2+1][1] = r4[3];
                ldm_x4_t(r4, bbase + 16384 + off);
                Bl[p*2][0] = r4[0]; Bl[p*2][1] = r4[1];
                Bl[p*2+1][0] = r4[2]; Bl[p*2+1][1] = r4[3];
            }
            // three passes spaced to avoid RAW stalls on acc
#pragma unroll
            for (int mi = 0; mi < 4; mi++)
#pragma unroll
                for (int ni = 0; ni < 4; ni++)
                    mma_bf16(acc[mi][ni], Ah[mi], Bh[ni]);
#pragma unroll
            for (int mi = 0; mi < 4; mi++)
#pragma unroll
                for (int ni = 0; ni < 4; ni++)
                    mma_bf16(acc[mi][ni], Ah[mi], Bl[ni]);
#pragma unroll
            for (int mi = 0; mi < 4; mi++)
#pragma unroll
                for (int ni = 0; ni < 4; ni++)
                    mma_bf16(acc[mi][ni], Al[mi], Bh[ni]);
        }

        if (has_next) STORE_TILES(cur ^ 1);
        __syncthreads();
    }

    // epilogue
#pragma unroll
    for (int mi = 0; mi < 4; mi++) {
        int row0 = bm * 128 + wm * 64 + mi * 16 + g;
#pragma unroll
        for (int ni = 0; ni < 4; ni++) {
            int col = bn * 128 + wn * 32 + ni * 8 + 2 * tg;
            float b0 = 0.f, b1 = 0.f;
            if (bias) { b0 = bias[col]; b1 = bias[col + 1]; }
#pragma unroll
            for (int half = 0; half < 2; half++) {
                int row = row0 + half * 8;
                float v0 = acc[mi][ni][half * 2 + 0] + b0;
                float v1 = acc[mi][ni][half * 2 + 1] + b1;
                if (relu) { v0 = fmaxf(v0, 0.f); v1 = fmaxf(v1, 0.f); }
                size_t idx = (size_t)row * N + col;
                if (res) {
                    float2 r2 = *(const float2*)(res + idx);
                    v0 += r2.x; v1 += r2.y;
                }
                *(float2*)(C + idx) = make_float2(v0, v1);
            }
        }
    }
#undef LOAD_TILES
#undef STORE_TILES
}

// -------------------- flash attention (causal, fp32) -----------------------
#define SP 68
#define ATT_SMEM (4 * 64 * SP * 4)

__global__ __launch_bounds__(256)
void attn_kernel(const float* __restrict__ Q, const float* __restrict__ K,
                 const float* __restrict__ V, float* __restrict__ O) {
    extern __shared__ float sm[];
    float* Qs = sm;
    float* Ks = sm + 64 * SP;
    float* Vs = sm + 2 * 64 * SP;
    float* Ps = sm + 3 * 64 * SP;

    int qt = blockIdx.x, h = blockIdx.y, b = blockIdx.z;
    int tid = threadIdx.x;
    int tx = tid & 15, ty = tid >> 4;
    int r0 = ty * 4, c0 = tx * 4;

    const float scale = 0.125f;
    int base_q = (b * SEQ + qt * 64) * DM + h * HDIM;

#pragma unroll
    for (int i = 0; i < 4; i++) {
        int idx = tid + i * 256;
        int row = idx >> 4;
        int c4  = (idx & 15) << 2;
        float4 qv = *(const float4*)&Q[base_q + row * DM + c4];
        qv.x *= scale; qv.y *= scale; qv.z *= scale; qv.w *= scale;
        *(float4*)&Qs[row * SP + c4] = qv;
    }

    float o[4][4];
#pragma unroll
    for (int i = 0; i < 4; i++)
#pragma unroll
        for (int j = 0; j < 4; j++) o[i][j] = 0.f;
    float m[4], l[4];
#pragma unroll
    for (int i = 0; i < 4; i++) { m[i] = -INFINITY; l[i] = 0.f; }

    for (int kt = 0; kt <= qt; kt++) {
        __syncthreads();
        int base_k = (b * SEQ + kt * 64) * DM + h * HDIM;
#pragma unroll
        for (int i = 0; i < 4; i++) {
            int idx = tid + i * 256;
            int row = idx >> 4;
            int c4  = (idx & 15) << 2;
            *(float4*)&Ks[row * SP + c4] = *(const float4*)&K[base_k + row * DM + c4];
            *(float4*)&Vs[row * SP + c4] = *(const float4*)&V[base_k + row * DM + c4];
        }
        __syncthreads();

        float s[4][4];
#pragma unroll
        for (int i = 0; i < 4; i++)
#pragma unroll
            for (int j = 0; j < 4; j++) s[i][j] = 0.f;

#pragma unroll
        for (int d4 = 0; d4 < 16; d4++) {
            float4 qv[4], kv[4];
#pragma unroll
            for (int i = 0; i < 4; i++) qv[i] = *(const float4*)&Qs[(r0 + i) * SP + d4 * 4];
#pragma unroll
            for (int j = 0; j < 4; j++) kv[j] = *(const float4*)&Ks[(c0 + j) * SP + d4 * 4];
#pragma unroll
            for (int i = 0; i < 4; i++)
#pragma unroll
                for (int j = 0; j < 4; j++)
                    s[i][j] += qv[i].x * kv[j].x + qv[i].y * kv[j].y +
                               qv[i].z * kv[j].z + qv[i].w * kv[j].w;
        }

        if (kt == qt) {
#pragma unroll
            for (int i = 0; i < 4; i++)
#pragma unroll
                for (int j = 0; j < 4; j++)
                    if (c0 + j > r0 + i) s[i][j] = -INFINITY;
        }

#pragma unroll
        for (int i = 0; i < 4; i++) {
            float mx = fmaxf(fmaxf(s[i][0], s[i][1]), fmaxf(s[i][2], s[i][3]));
#pragma unroll
            for (int mk = 8; mk; mk >>= 1)
                mx = fmaxf(mx, __shfl_xor_sync(0xffffffffu, mx, mk));
            float mnew = fmaxf(m[i], mx);
            float fac = __expf(m[i] - mnew);
            float lsum = 0.f;
#pragma unroll
            for (int j = 0; j < 4; j++) {
                s[i][j] = __expf(s[i][j] - mnew);
                lsum += s[i][j];
            }
#pragma unroll
            for (int mk = 8; mk; mk >>= 1)
                lsum += __shfl_xor_sync(0xffffffffu, lsum, mk);
            l[i] = l[i] * fac + lsum;
            m[i] = mnew;
#pragma unroll
            for (int j = 0; j < 4; j++) o[i][j] *= fac;
            *(float4*)&Ps[(r0 + i) * SP + c0] =
                make_float4(s[i][0], s[i][1], s[i][2], s[i][3]);
        }
        __syncthreads();

#pragma unroll
        for (int k4 = 0; k4 < 16; k4++) {
            float4 pv[4], vv[4];
#pragma unroll
            for (int i = 0; i < 4; i++) pv[i] = *(const float4*)&Ps[(r0 + i) * SP + k4 * 4];
#pragma unroll
            for (int tt = 0; tt < 4; tt++) vv[tt] = *(const float4*)&Vs[(k4 * 4 + tt) * SP + c0];
#pragma unroll
            for (int i = 0; i < 4; i++) {
                float p0 = pv[i].x, p1 = pv[i].y, p2 = pv[i].z, p3 = pv[i].w;
                o[i][0] += p0 * vv[0].x + p1 * vv[1].x + p2 * vv[2].x + p3 * vv[3].x;
                o[i][1] += p0 * vv[0].y + p1 * vv[1].y + p2 * vv[2].y + p3 * vv[3].y;
                o[i][2] += p0 * vv[0].z + p1 * vv[1].z + p2 * vv[2].z + p3 * vv[3].z;
                o[i][3] += p0 * vv[0].w + p1 * vv[1].w + p2 * vv[2].w + p3 * vv[3].w;
            }
        }
    }

#pragma unroll
    for (int i = 0; i < 4; i++) {
        float inv = 1.f / l[i];
        *(float4*)&O[base_q + (r0 + i) * DM + c0] =
            make_float4(o[i][0] * inv, o[i][1] * inv, o[i][2] * inv, o[i][3] * inv);
    }
}

// -------------------- host orchestration ----------------------------------
extern "C" void kernel_launch(void* const* d_in, const int* in_sizes, int n_in,
                              void* d_out, int out_size) {
    const int*   ctx  = (const int*)  d_in[0];
    const float* tok  = (const float*)d_in[1];
    const float* pos  = (const float*)d_in[2];
    const float* Wq   = (const float*)d_in[3];
    const float* Wk   = (const float*)d_in[4];
    const float* Wv   = (const float*)d_in[5];
    const float* Wo   = (const float*)d_in[6];
    const float* bo   = (const float*)d_in[7];
    const float* ln1g = (const float*)d_in[8];
    const float* ln1b = (const float*)d_in[9];
    const float* W1   = (const float*)d_in[10];
    const float* b1   = (const float*)d_in[11];
    const float* W2   = (const float*)d_in[12];
    const float* b2   = (const float*)d_in[13];
    const float* ln2g = (const float*)d_in[14];
    const float* ln2b = (const float*)d_in[15];
    const float* lnfg = (const float*)d_in[16];
    const float* lnfb = (const float*)d_in[17];
    const float* Wout = (const float*)d_in[18];
    const float* bout = (const float*)d_in[19];

    float *px, *ph, *pq, *pk, *pv, *pat, *pff;
    cudaGetSymbolAddress((void**)&px,  g_x);
    cudaGetSymbolAddress((void**)&ph,  g_h);
    cudaGetSymbolAddress((void**)&pq,  g_q);
    cudaGetSymbolAddress((void**)&pk,  g_k);
    cudaGetSymbolAddress((void**)&pv,  g_v);
    cudaGetSymbolAddress((void**)&pat, g_at);
    cudaGetSymbolAddress((void**)&pff, g_ff);

    cudaFuncSetAttribute(attn_kernel,
                         cudaFuncAttributeMaxDynamicSharedMemorySize, ATT_SMEM);
    cudaFuncSetAttribute(hgemm,
                         cudaFuncAttributeMaxDynamicSharedMemorySize, GEMM_SMEM);

    embed_kernel<<<TOK, 256>>>(ctx, tok, pos);

    dim3 gD(TOK / 128, DM  / 128);   // 16 x 6
    dim3 gF(TOK / 128, DFF / 128);   // 16 x 24
    dim3 gV(TOK / 128, NV  / 128);   // 16 x 250

    for (int l = 0; l < NL; l++) {
        const float* wq = Wq + (size_t)l * DM * DM;
        const float* wk = Wk + (size_t)l * DM * DM;
        const float* wv = Wv + (size_t)l * DM * DM;
        const float* wo = Wo + (size_t)l * DM * DM;
        const float* w1 = W1 + (size_t)l * DM * DFF;
        const float* w2 = W2 + (size_t)l * DFF * DM;

        ln_kernel<<<TOK, 256>>>(px, ln1g + l * DM, ln1b + l * DM, ph);
        hgemm<<<gD, 256, GEMM_SMEM>>>(ph, wq, nullptr, nullptr, pq, TOK, DM, DM, 0);
        hgemm<<<gD, 256, GEMM_SMEM>>>(ph, wk, nullptr, nullptr, pk, TOK, DM, DM, 0);
        hgemm<<<gD, 256, GEMM_SMEM>>>(ph, wv, nullptr, nullptr, pv, TOK, DM, DM, 0);
        attn_kernel<<<dim3(SEQ / 64, NH, 2), 256, ATT_SMEM>>>(pq, pk, pv, pat);
        hgemm<<<gD, 256, GEMM_SMEM>>>(pat, wo, bo + l * DM, px, px, TOK, DM, DM, 0);
        ln_kernel<<<TOK, 256>>>(px, ln2g + l * DM, ln2b + l * DM, ph);
        hgemm<<<gF, 256, GEMM_SMEM>>>(ph, w1, b1 + (size_t)l * DFF, nullptr, pff,
                                      TOK, DFF, DM, 1);
        hgemm<<<gD, 256, GEMM_SMEM>>>(pff, w2, b2 + l * DM, px, px, TOK, DM, DFF, 0);
    }

    ln_kernel<<<TOK, 256>>>(px, lnfg, lnfb, ph);
    hgemm<<<gV, 256, GEMM_SMEM>>>(ph, Wout, bout, nullptr, (float*)d_out,
                                  TOK, NV, DM, 0);
}

// round 4
// speedup vs baseline: 2.3769x; 1.1866x over previous
#include <cuda_runtime.h>
#include <cuda_bf16.h>
#include <math.h>
#include <stdint.h>

// Problem constants
#define TOK   2048          // B*S
#define SEQ   1024
#define DM    768
#define DFF   3072
#define NH    12
#define HDIM  64
#define NV    32000
#define NL    6
#define QKVS  (3 * DM)      // 2304

typedef __nv_bfloat16 bf16;

// -------------------- scratch (device globals; no allocation allowed) -----
__device__ __align__(16) float g_x  [TOK * DM];
__device__ __align__(16) float g_qkv[TOK * QKVS];
__device__ __align__(16) bf16  g_hh [TOK * DM];
__device__ __align__(16) bf16  g_hl [TOK * DM];
__device__ __align__(16) bf16  g_ath[TOK * DM];
__device__ __align__(16) bf16  g_atl[TOK * DM];
__device__ __align__(16) bf16  g_ffh[TOK * DFF];
__device__ __align__(16) bf16  g_ffl[TOK * DFF];
// split weights
__device__ __align__(16) bf16 g_wqkv_h[NL * DM * QKVS];
__device__ __align__(16) bf16 g_wqkv_l[NL * DM * QKVS];
__device__ __align__(16) bf16 g_wo_h [NL * DM * DM];
__device__ __align__(16) bf16 g_wo_l [NL * DM * DM];
__device__ __align__(16) bf16 g_w1_h [NL * DM * DFF];
__device__ __align__(16) bf16 g_w1_l [NL * DM * DFF];
__device__ __align__(16) bf16 g_w2_h [NL * DFF * DM];
__device__ __align__(16) bf16 g_w2_l [NL * DFF * DM];
__device__ __align__(16) bf16 g_wout_h[DM * NV];
__device__ __align__(16) bf16 g_wout_l[DM * NV];

// -------------------- helpers ---------------------------------------------
__device__ __forceinline__ void fsplit(float x, bf16& h, bf16& l) {
    h = __float2bfloat16(x);
    l = __float2bfloat16(x - __bfloat162float(h));
}
__device__ __forceinline__ uint32_t cvta_smem(const void* p) {
    return (uint32_t)__cvta_generic_to_shared(p);
}
__device__ __forceinline__ void cp16(uint32_t s, const void* g) {
    asm volatile("cp.async.cg.shared.global [%0], [%1], 16;" :: "r"(s), "l"(g));
}
__device__ __forceinline__ void ldm_x4(uint32_t* r, uint32_t addr) {
    asm volatile("ldmatrix.sync.aligned.m8n8.x4.shared.b16 {%0,%1,%2,%3},[%4];"
                 : "=r"(r[0]), "=r"(r[1]), "=r"(r[2]), "=r"(r[3]) : "r"(addr));
}
__device__ __forceinline__ void ldm_x4_t(uint32_t* r, uint32_t addr) {
    asm volatile("ldmatrix.sync.aligned.m8n8.x4.trans.shared.b16 {%0,%1,%2,%3},[%4];"
                 : "=r"(r[0]), "=r"(r[1]), "=r"(r[2]), "=r"(r[3]) : "r"(addr));
}
__device__ __forceinline__ void mma_bf16(float* c, const uint32_t* a, const uint32_t* b) {
    asm volatile(
        "mma.sync.aligned.m16n8k16.row.col.f32.bf16.bf16.f32 "
        "{%0,%1,%2,%3},{%4,%5,%6,%7},{%8,%9},{%0,%1,%2,%3};"
        : "+f"(c[0]), "+f"(c[1]), "+f"(c[2]), "+f"(c[3])
        : "r"(a[0]), "r"(a[1]), "r"(a[2]), "r"(a[3]), "r"(b[0]), "r"(b[1]));
}

// -------------------- weight split/pack kernel -----------------------------
// src [R, cols] fp32 -> dh/dl [R, dst_stride] bf16 at column offset cofs
__global__ void wsplit(const float* __restrict__ src, bf16* __restrict__ dh,
                       bf16* __restrict__ dl, int cols, int dst_stride,
                       int cofs, int total4) {
    int i = blockIdx.x * 256 + threadIdx.x;
    if (i >= total4) return;
    int e = i * 4;
    int r = e / cols, c = e - r * cols;
    float4 v = *(const float4*)(src + (size_t)e);
    size_t d = (size_t)r * dst_stride + cofs + c;
    bf16 h0, l0, h1, l1, h2, l2, h3, l3;
    fsplit(v.x, h0, l0); fsplit(v.y, h1, l1);
    fsplit(v.z, h2, l2); fsplit(v.w, h3, l3);
    __nv_bfloat162* H = (__nv_bfloat162*)(dh + d);
    __nv_bfloat162* L = (__nv_bfloat162*)(dl + d);
    H[0] = __nv_bfloat162(h0, h1); H[1] = __nv_bfloat162(h2, h3);
    L[0] = __nv_bfloat162(l0, l1); L[1] = __nv_bfloat162(l2, l3);
}

// -------------------- embedding -------------------------------------------
__global__ void embed_kernel(const int* __restrict__ ctx,
                             const float* __restrict__ tok,
                             const float* __restrict__ pos) {
    int t = blockIdx.x;
    int token = ctx[t];
    int s = t & (SEQ - 1);
#pragma unroll
    for (int i = 0; i < 3; i++) {
        int d = threadIdx.x + i * 256;
        g_x[t * DM + d] = tok[token * DM + d] + pos[s * DM + d];
    }
}

// -------------------- layernorm -> split bf16 ------------------------------
__global__ void ln_split(const float* __restrict__ in,
                         const float* __restrict__ gg,
                         const float* __restrict__ bb,
                         bf16* __restrict__ oh, bf16* __restrict__ ol) {
    int row = blockIdx.x;
    const float* x = in + row * DM;
    float v[3];
    float s = 0.f, ss = 0.f;
#pragma unroll
    for (int i = 0; i < 3; i++) {
        v[i] = x[threadIdx.x + i * 256];
        s  += v[i];
        ss += v[i] * v[i];
    }
#pragma unroll
    for (int m = 16; m; m >>= 1) {
        s  += __shfl_xor_sync(0xffffffffu, s,  m);
        ss += __shfl_xor_sync(0xffffffffu, ss, m);
    }
    __shared__ float sa[8], sb[8];
    int w = threadIdx.x >> 5, lane = threadIdx.x & 31;
    if (lane == 0) { sa[w] = s; sb[w] = ss; }
    __syncthreads();
    s = 0.f; ss = 0.f;
#pragma unroll
    for (int i = 0; i < 8; i++) { s += sa[i]; ss += sb[i]; }
    float mean = s * (1.0f / DM);
    float var  = ss * (1.0f / DM) - mean * mean;
    float inv  = rsqrtf(var + 1e-5f);
#pragma unroll
    for (int i = 0; i < 3; i++) {
        int d = threadIdx.x + i * 256;
        float y = (v[i] - mean) * inv * gg[d] + bb[d];
        bf16 h, l;
        fsplit(y, h, l);
        oh[row * DM + d] = h;
        ol[row * DM + d] = l;
    }
}

// -------------------- bf16-split tensor-core GEMM (cp.async, 3-stage) ------
// C[M,N] = A @ B, A split bf16 [M,K], B split bf16 [K,N].
// BK=32, BN=128, BM template {128,64}. 256 thr, warps 2(m)x4(n).
// A smem rows 64B (4x16B chunks), swizzle kc^((row>>1)&3).
// B smem rows 256B (16 chunks), swizzle ((nc&7)^(k&7))|(nc&8).

__device__ __forceinline__ uint32_t swzA(int row, int kc) {
    return (uint32_t)(row * 64 + ((kc ^ ((row >> 1) & 3)) << 4));
}
__device__ __forceinline__ uint32_t swzB(int k, int nc) {
    return (uint32_t)(k * 256 + ((((nc & 7) ^ (k & 7)) | (nc & 8)) << 4));
}

template<int BM>
__global__ __launch_bounds__(256, 2)
void hgemm(const bf16* __restrict__ Ah, const bf16* __restrict__ Al,
           const bf16* __restrict__ Bh, const bf16* __restrict__ Bl,
           const float* __restrict__ bias, const float* __restrict__ res,
           float* __restrict__ C, bf16* __restrict__ Oh, bf16* __restrict__ Ol,
           int N, int K, int relu) {
    constexpr int WM = BM / 2;
    constexpr int MT = WM / 16;
    constexpr int A_PART = BM * 64;           // bytes per A part per stage
    constexpr int STAGE  = 2 * A_PART + 16384;
    constexpr int NA = BM / 64;               // A 16B chunks per thread per part

    extern __shared__ char smc[];
    uint32_t sbase = cvta_smem(smc);

    int tid  = threadIdx.x;
    int lane = tid & 31;
    int warp = tid >> 5;
    int wm = warp >> 2;
    int wn = warp & 3;
    int g  = lane >> 2;
    int tg = lane & 3;
    int bm = blockIdx.x, bn = blockIdx.y;

    float acc[MT][4][4];
#pragma unroll
    for (int mi = 0; mi < MT; mi++)
#pragma unroll
        for (int ni = 0; ni < 4; ni++)
#pragma unroll
            for (int j = 0; j < 4; j++) acc[mi][ni][j] = 0.f;

#define LOADSTAGE(IT)                                                         \
    {                                                                         \
        int _it = (IT);                                                       \
        uint32_t st = sbase + (_it % 3) * STAGE;                              \
        _Pragma("unroll")                                                     \
        for (int u = 0; u < NA; u++) {                                        \
            int cu = tid + u * 256;                                           \
            int arow = cu >> 2, akc = cu & 3;                                 \
            uint32_t so = st + swzA(arow, akc);                               \
            size_t go = (size_t)(bm * BM + arow) * K + _it * 32 + akc * 8;    \
            cp16(so, Ah + go);                                                \
            cp16(so + A_PART, Al + go);                                       \
        }                                                                     \
        _Pragma("unroll")                                                     \
        for (int u = 0; u < 2; u++) {                                         \
            int cu = tid + u * 256;                                           \
            int bk = cu >> 4, bnc = cu & 15;                                  \
            uint32_t so = st + 2 * A_PART + swzB(bk, bnc);                    \
            size_t go = (size_t)(_it * 32 + bk) * N + bn * 128 + bnc * 8;     \
            cp16(so, Bh + go);                                                \
            cp16(so + 8192, Bl + go);                                         \
        }                                                                     \
    }

    int nIter = K >> 5;
    LOADSTAGE(0); asm volatile("cp.async.commit_group;");
    LOADSTAGE(1); asm volatile("cp.async.commit_group;");

    int a_lrow = wm * WM + (lane & 15);
    int a_koff = (lane >> 4) & 1;
    int b_lk   = lane & 15;
    int b_noff = (lane >> 4) & 1;

    for (int it = 0; it < nIter; it++) {
        asm volatile("cp.async.wait_group 1;");
        __syncthreads();
        uint32_t sb = sbase + (it % 3) * STAGE;

#pragma unroll
        for (int k16 = 0; k16 < 2; k16++) {
            uint32_t Af[MT][4], Lf[MT][4], Bf[4][2];
            int kc = k16 * 2 + a_koff;
#pragma unroll
            for (int mi = 0; mi < MT; mi++) {
                uint32_t off = swzA(a_lrow + mi * 16, kc);
                ldm_x4(Af[mi], sb + off);
                ldm_x4(Lf[mi], sb + A_PART + off);
            }
            int kk = k16 * 16 + b_lk;
#pragma unroll
            for (int p = 0; p < 2; p++) {
                uint32_t r4[4];
                ldm_x4_t(r4, sb + 2 * A_PART + swzB(kk, wn * 4 + p * 2 + b_noff));
                Bf[p*2][0] = r4[0]; Bf[p*2][1] = r4[1];
                Bf[p*2+1][0] = r4[2]; Bf[p*2+1][1] = r4[3];
            }
#pragma unroll
            for (int mi = 0; mi < MT; mi++)
#pragma unroll
                for (int ni = 0; ni < 4; ni++) mma_bf16(acc[mi][ni], Af[mi], Bf[ni]);
#pragma unroll
            for (int mi = 0; mi < MT; mi++)
#pragma unroll
                for (int ni = 0; ni < 4; ni++) mma_bf16(acc[mi][ni], Lf[mi], Bf[ni]);
#pragma unroll
            for (int p = 0; p < 2; p++) {
                uint32_t r4[4];
                ldm_x4_t(r4, sb + 2 * A_PART + 8192 + swzB(kk, wn * 4 + p * 2 + b_noff));
                Bf[p*2][0] = r4[0]; Bf[p*2][1] = r4[1];
                Bf[p*2+1][0] = r4[2]; Bf[p*2+1][1] = r4[3];
            }
#pragma unroll
            for (int mi = 0; mi < MT; mi++)
#pragma unroll
                for (int ni = 0; ni < 4; ni++) mma_bf16(acc[mi][ni], Af[mi], Bf[ni]);
        }

        if (it + 2 < nIter) LOADSTAGE(it + 2);
        asm volatile("cp.async.commit_group;");
    }
#undef LOADSTAGE

    // epilogue
#pragma unroll
    for (int mi = 0; mi < MT; mi++) {
        int row0 = bm * BM + wm * WM + mi * 16 + g;
#pragma unroll
        for (int ni = 0; ni < 4; ni++) {
            int col = bn * 128 + wn * 32 + ni * 8 + 2 * tg;
            float b0 = 0.f, b1 = 0.f;
            if (bias) { b0 = bias[col]; b1 = bias[col + 1]; }
#pragma unroll
            for (int half = 0; half < 2; half++) {
                int row = row0 + half * 8;
                float v0 = acc[mi][ni][half * 2 + 0] + b0;
                float v1 = acc[mi][ni][half * 2 + 1] + b1;
                if (relu) { v0 = fmaxf(v0, 0.f); v1 = fmaxf(v1, 0.f); }
                size_t idx = (size_t)row * N + col;
                if (Oh) {
                    bf16 h0, l0, h1, l1;
                    fsplit(v0, h0, l0); fsplit(v1, h1, l1);
                    *(__nv_bfloat162*)(Oh + idx) = __nv_bfloat162(h0, h1);
                    *(__nv_bfloat162*)(Ol + idx) = __nv_bfloat162(l0, l1);
                } else {
                    if (res) {
                        float2 r2 = *(const float2*)(res + idx);
                        v0 += r2.x; v1 += r2.y;
                    }
                    *(float2*)(C + idx) = make_float2(v0, v1);
                }
            }
        }
    }
}

// -------------------- flash attention (causal, fp32, packed QKV) -----------
#define SP 68
#define ATT_SMEM (4 * 64 * SP * 4)

__global__ __launch_bounds__(256)
void attn_kernel(const float* __restrict__ QKV,
                 bf16* __restrict__ Oh, bf16* __restrict__ Ol) {
    extern __shared__ float sm[];
    float* Qs = sm;
    float* Ks = sm + 64 * SP;
    float* Vs = sm + 2 * 64 * SP;
    float* Ps = sm + 3 * 64 * SP;

    int qt = blockIdx.x, h = blockIdx.y, b = blockIdx.z;
    int tid = threadIdx.x;
    int tx = tid & 15, ty = tid >> 4;
    int r0 = ty * 4, c0 = tx * 4;

    const float scale = 0.125f;
    size_t base_q = (size_t)(b * SEQ + qt * 64) * QKVS + h * HDIM;

#pragma unroll
    for (int i = 0; i < 4; i++) {
        int idx = tid + i * 256;
        int row = idx >> 4;
        int c4  = (idx & 15) << 2;
        float4 qv = *(const float4*)&QKV[base_q + (size_t)row * QKVS + c4];
        qv.x *= scale; qv.y *= scale; qv.z *= scale; qv.w *= scale;
        *(float4*)&Qs[row * SP + c4] = qv;
    }

    float o[4][4];
#pragma unroll
    for (int i = 0; i < 4; i++)
#pragma unroll
        for (int j = 0; j < 4; j++) o[i][j] = 0.f;
    float m[4], l[4];
#pragma unroll
    for (int i = 0; i < 4; i++) { m[i] = -INFINITY; l[i] = 0.f; }

    for (int kt = 0; kt <= qt; kt++) {
        __syncthreads();
        size_t base_k = (size_t)(b * SEQ + kt * 64) * QKVS + DM + h * HDIM;
#pragma unroll
        for (int i = 0; i < 4; i++) {
            int idx = tid + i * 256;
            int row = idx >> 4;
            int c4  = (idx & 15) << 2;
            *(float4*)&Ks[row * SP + c4] =
                *(const float4*)&QKV[base_k + (size_t)row * QKVS + c4];
            *(float4*)&Vs[row * SP + c4] =
                *(const float4*)&QKV[base_k + DM + (size_t)row * QKVS + c4];
        }
        __syncthreads();

        float s[4][4];
#pragma unroll
        for (int i = 0; i < 4; i++)
#pragma unroll
            for (int j = 0; j < 4; j++) s[i][j] = 0.f;

#pragma unroll
        for (int d4 = 0; d4 < 16; d4++) {
            float4 qv[4], kv[4];
#pragma unroll
            for (int i = 0; i < 4; i++) qv[i] = *(const float4*)&Qs[(r0 + i) * SP + d4 * 4];
#pragma unroll
            for (int j = 0; j < 4; j++) kv[j] = *(const float4*)&Ks[(c0 + j) * SP + d4 * 4];
#pragma unroll
            for (int i = 0; i < 4; i++)
#pragma unroll
                for (int j = 0; j < 4; j++)
                    s[i][j] += qv[i].x * kv[j].x + qv[i].y * kv[j].y +
                               qv[i].z * kv[j].z + qv[i].w * kv[j].w;
        }

        if (kt == qt) {
#pragma unroll
            for (int i = 0; i < 4; i++)
#pragma unroll
                for (int j = 0; j < 4; j++)
                    if (c0 + j > r0 + i) s[i][j] = -INFINITY;
        }

#pragma unroll
        for (int i = 0; i < 4; i++) {
            float mx = fmaxf(fmaxf(s[i][0], s[i][1]), fmaxf(s[i][2], s[i][3]));
#pragma unroll
            for (int mk = 8; mk; mk >>= 1)
                mx = fmaxf(mx, __shfl_xor_sync(0xffffffffu, mx, mk));
            float mnew = fmaxf(m[i], mx);
            float fac = __expf(m[i] - mnew);
            float lsum = 0.f;
#pragma unroll
            for (int j = 0; j < 4; j++) {
                s[i][j] = __expf(s[i][j] - mnew);
                lsum += s[i][j];
            }
#pragma unroll
            for (int mk = 8; mk; mk >>= 1)
                lsum += __shfl_xor_sync(0xffffffffu, lsum, mk);
            l[i] = l[i] * fac + lsum;
            m[i] = mnew;
#pragma unroll
            for (int j = 0; j < 4; j++) o[i][j] *= fac;
            *(float4*)&Ps[(r0 + i) * SP + c0] =
                make_float4(s[i][0], s[i][1], s[i][2], s[i][3]);
        }
        __syncthreads();

#pragma unroll
        for (int k4 = 0; k4 < 16; k4++) {
            float4 pv[4], vv[4];
#pragma unroll
            for (int i = 0; i < 4; i++) pv[i] = *(const float4*)&Ps[(r0 + i) * SP + k4 * 4];
#pragma unroll
            for (int tt = 0; tt < 4; tt++) vv[tt] = *(const float4*)&Vs[(k4 * 4 + tt) * SP + c0];
#pragma unroll
            for (int i = 0; i < 4; i++) {
                float p0 = pv[i].x, p1 = pv[i].y, p2 = pv[i].z, p3 = pv[i].w;
                o[i][0] += p0 * vv[0].x + p1 * vv[1].x + p2 * vv[2].x + p3 * vv[3].x;
                o[i][1] += p0 * vv[0].y + p1 * vv[1].y + p2 * vv[2].y + p3 * vv[3].y;
                o[i][2] += p0 * vv[0].z + p1 * vv[1].z + p2 * vv[2].z + p3 * vv[3].z;
                o[i][3] += p0 * vv[0].w + p1 * vv[1].w + p2 * vv[2].w + p3 * vv[3].w;
            }
        }
    }

#pragma unroll
    for (int i = 0; i < 4; i++) {
        float inv = 1.f / l[i];
        size_t idx = (size_t)(b * SEQ + qt * 64 + r0 + i) * DM + h * HDIM + c0;
#pragma unroll
        for (int j = 0; j < 4; j += 2) {
            bf16 h0, l0, h1, l1;
            fsplit(o[i][j] * inv, h0, l0);
            fsplit(o[i][j + 1] * inv, h1, l1);
            *(__nv_bfloat162*)(Oh + idx + j) = __nv_bfloat162(h0, h1);
            *(__nv_bfloat162*)(Ol + idx + j) = __nv_bfloat162(l0, l1);
        }
    }
}

// -------------------- host orchestration ----------------------------------
#define SM128 (3 * (2 * 128 * 64 + 16384))   // 98304
#define SM64  (3 * (2 * 64 * 64 + 16384))    // 73728

extern "C" void kernel_launch(void* const* d_in, const int* in_sizes, int n_in,
                              void* d_out, int out_size) {
    const int*   ctx  = (const int*)  d_in[0];
    const float* tok  = (const float*)d_in[1];
    const float* pos  = (const float*)d_in[2];
    const float* Wq   = (const float*)d_in[3];
    const float* Wk   = (const float*)d_in[4];
    const float* Wv   = (const float*)d_in[5];
    const float* Wo   = (const float*)d_in[6];
    const float* bo   = (const float*)d_in[7];
    const float* ln1g = (const float*)d_in[8];
    const float* ln1b = (const float*)d_in[9];
    const float* W1   = (const float*)d_in[10];
    const float* b1   = (const float*)d_in[11];
    const float* W2   = (const float*)d_in[12];
    const float* b2   = (const float*)d_in[13];
    const float* ln2g = (const float*)d_in[14];
    const float* ln2b = (const float*)d_in[15];
    const float* lnfg = (const float*)d_in[16];
    const float* lnfb = (const float*)d_in[17];
    const float* Wout = (const float*)d_in[18];
    const float* bout = (const float*)d_in[19];

    float *px, *pqkv;
    bf16 *phh, *phl, *path, *patl, *pffh, *pffl;
    bf16 *pwqkv_h, *pwqkv_l, *pwo_h, *pwo_l, *pw1_h, *pw1_l, *pw2_h, *pw2_l;
    bf16 *pwout_h, *pwout_l;
    cudaGetSymbolAddress((void**)&px,   g_x);
    cudaGetSymbolAddress((void**)&pqkv, g_qkv);
    cudaGetSymbolAddress((void**)&phh,  g_hh);
    cudaGetSymbolAddress((void**)&phl,  g_hl);
    cudaGetSymbolAddress((void**)&path, g_ath);
    cudaGetSymbolAddress((void**)&patl, g_atl);
    cudaGetSymbolAddress((void**)&pffh, g_ffh);
    cudaGetSymbolAddress((void**)&pffl, g_ffl);
    cudaGetSymbolAddress((void**)&pwqkv_h, g_wqkv_h);
    cudaGetSymbolAddress((void**)&pwqkv_l, g_wqkv_l);
    cudaGetSymbolAddress((void**)&pwo_h, g_wo_h);
    cudaGetSymbolAddress((void**)&pwo_l, g_wo_l);
    cudaGetSymbolAddress((void**)&pw1_h, g_w1_h);
    cudaGetSymbolAddress((void**)&pw1_l, g_w1_l);
    cudaGetSymbolAddress((void**)&pw2_h, g_w2_h);
    cudaGetSymbolAddress((void**)&pw2_l, g_w2_l);
    cudaGetSymbolAddress((void**)&pwout_h, g_wout_h);
    cudaGetSymbolAddress((void**)&pwout_l, g_wout_l);

    cudaFuncSetAttribute(attn_kernel,
                         cudaFuncAttributeMaxDynamicSharedMemorySize, ATT_SMEM);
    cudaFuncSetAttribute(hgemm<128>,
                         cudaFuncAttributeMaxDynamicSharedMemorySize, SM128);
    cudaFuncSetAttribute(hgemm<64>,
                         cudaFuncAttributeMaxDynamicSharedMemorySize, SM64);

    // ---- weight splitting (every call; deterministic) ----
    int t;
    t = NL * DM * DM / 4;
    wsplit<<<(t + 255) / 256, 256>>>(Wq, pwqkv_h, pwqkv_l, DM, QKVS, 0,      t);
    wsplit<<<(t + 255) / 256, 256>>>(Wk, pwqkv_h, pwqkv_l, DM, QKVS, DM,     t);
    wsplit<<<(t + 255) / 256, 256>>>(Wv, pwqkv_h, pwqkv_l, DM, QKVS, 2 * DM, t);
    wsplit<<<(t + 255) / 256, 256>>>(Wo, pwo_h, pwo_l, DM, DM, 0, t);
    t = NL * DM * DFF / 4;
    wsplit<<<(t + 255) / 256, 256>>>(W1, pw1_h, pw1_l, DFF, DFF, 0, t);
    wsplit<<<(t + 255) / 256, 256>>>(W2, pw2_h, pw2_l, DM, DM, 0, t);
    t = DM * NV / 4;
    wsplit<<<(t + 255) / 256, 256>>>(Wout, pwout_h, pwout_l, NV, NV, 0, t);

    embed_kernel<<<TOK, 256>>>(ctx, tok, pos);

    for (int l = 0; l < NL; l++) {
        size_t oqkv = (size_t)l * DM * QKVS;
        size_t owo  = (size_t)l * DM * DM;
        size_t ow1  = (size_t)l * DM * DFF;
        size_t ow2  = (size_t)l * DFF * DM;

        ln_split<<<TOK, 256>>>(px, ln1g + l * DM, ln1b + l * DM, phh, phl);
        hgemm<128><<<dim3(16, 18), 256, SM128>>>(
            phh, phl, pwqkv_h + oqkv, pwqkv_l + oqkv,
            nullptr, nullptr, pqkv, nullptr, nullptr, QKVS, DM, 0);
        attn_kernel<<<dim3(SEQ / 64, NH, 2), 256, ATT_SMEM>>>(pqkv, path, patl);
        hgemm<64><<<dim3(32, 6), 256, SM64>>>(
            path, patl, pwo_h + owo, pwo_l + owo,
            bo + l * DM, px, px, nullptr, nullptr, DM, DM, 0);
        ln_split<<<TOK, 256>>>(px, ln2g + l * DM, ln2b + l * DM, phh, phl);
        hgemm<128><<<dim3(16, 24), 256, SM128>>>(
            phh, phl, pw1_h + ow1, pw1_l + ow1,
            b1 + (size_t)l * DFF, nullptr, nullptr, pffh, pffl, DFF, DM, 1);
        hgemm<64><<<dim3(32, 6), 256, SM64>>>(
            pffh, pffl, pw2_h + ow2, pw2_l + ow2,
            b2 + l * DM, px, px, nullptr, nullptr, DM, DFF, 0);
    }

    ln_split<<<TOK, 256>>>(px, lnfg, lnfb, phh, phl);
    hgemm<128><<<dim3(16, 250), 256, SM128>>>(
        phh, phl, pwout_h, pwout_l,
        bout, nullptr, (float*)d_out, nullptr, nullptr, NV, DM, 0);
}

// round 6
// speedup vs baseline: 2.8730x; 1.2087x over previous
#include <cuda_runtime.h>
#include <cuda_fp16.h>
#include <math.h>
#include <stdint.h>

// Problem constants
#define TOK   2048          // B*S
#define SEQ   1024
#define DM    768
#define DFF   3072
#define NH    12
#define HDIM  64
#define NV    32000
#define NL    6
#define QKVS  (3 * DM)      // 2304

typedef __half f16;

// -------------------- scratch (device globals; no allocation allowed) -----
__device__ __align__(16) float g_x  [TOK * DM];
__device__ __align__(16) float g_qkv[TOK * QKVS];
__device__ __align__(16) f16   g_h  [TOK * DM];
__device__ __align__(16) f16   g_at [TOK * DM];
__device__ __align__(16) f16   g_ff [TOK * DFF];
// split weights [K,N] fp16 hi/lo
__device__ __align__(16) f16 g_wqkv_h[NL * DM * QKVS];
__device__ __align__(16) f16 g_wqkv_l[NL * DM * QKVS];
__device__ __align__(16) f16 g_wo_h [NL * DM * DM];
__device__ __align__(16) f16 g_wo_l [NL * DM * DM];
__device__ __align__(16) f16 g_w1_h [NL * DM * DFF];
__device__ __align__(16) f16 g_w1_l [NL * DM * DFF];
__device__ __align__(16) f16 g_w2_h [NL * DFF * DM];
__device__ __align__(16) f16 g_w2_l [NL * DFF * DM];
__device__ __align__(16) f16 g_wout_h[DM * NV];
__device__ __align__(16) f16 g_wout_l[DM * NV];

// -------------------- helpers ---------------------------------------------
__device__ __forceinline__ void hsplit(float x, f16& h, f16& l) {
    h = __float2half_rn(x);
    l = __float2half_rn(x - __half2float(h));
}
__device__ __forceinline__ uint32_t cvta_smem(const void* p) {
    return (uint32_t)__cvta_generic_to_shared(p);
}
__device__ __forceinline__ void cp16(uint32_t s, const void* g) {
    asm volatile("cp.async.cg.shared.global [%0], [%1], 16;" :: "r"(s), "l"(g));
}
__device__ __forceinline__ void ldm_x4(uint32_t* r, uint32_t addr) {
    asm volatile("ldmatrix.sync.aligned.m8n8.x4.shared.b16 {%0,%1,%2,%3},[%4];"
                 : "=r"(r[0]), "=r"(r[1]), "=r"(r[2]), "=r"(r[3]) : "r"(addr));
}
__device__ __forceinline__ void ldm_x4_t(uint32_t* r, uint32_t addr) {
    asm volatile("ldmatrix.sync.aligned.m8n8.x4.trans.shared.b16 {%0,%1,%2,%3},[%4];"
                 : "=r"(r[0]), "=r"(r[1]), "=r"(r[2]), "=r"(r[3]) : "r"(addr));
}
__device__ __forceinline__ void mma_f16(float* c, const uint32_t* a, const uint32_t* b) {
    asm volatile(
        "mma.sync.aligned.m16n8k16.row.col.f32.f16.f16.f32 "
        "{%0,%1,%2,%3},{%4,%5,%6,%7},{%8,%9},{%0,%1,%2,%3};"
        : "+f"(c[0]), "+f"(c[1]), "+f"(c[2]), "+f"(c[3])
        : "r"(a[0]), "r"(a[1]), "r"(a[2]), "r"(a[3]), "r"(b[0]), "r"(b[1]));
}

// -------------------- weight split/pack kernel -----------------------------
// src [R, cols] fp32 -> dh/dl [R, dst_stride] f16 at column offset cofs
__global__ void wsplit(const float* __restrict__ src, f16* __restrict__ dh,
                       f16* __restrict__ dl, int cols, int dst_stride,
                       int cofs, int total4) {
    int i = blockIdx.x * 256 + threadIdx.x;
    if (i >= total4) return;
    int e = i * 4;
    int r = e / cols, c = e - r * cols;
    float4 v = *(const float4*)(src + (size_t)e);
    size_t d = (size_t)r * dst_stride + cofs + c;
    f16 h0, l0, h1, l1, h2, l2, h3, l3;
    hsplit(v.x, h0, l0); hsplit(v.y, h1, l1);
    hsplit(v.z, h2, l2); hsplit(v.w, h3, l3);
    __half2* H = (__half2*)(dh + d);
    __half2* L = (__half2*)(dl + d);
    H[0] = __half2(h0, h1); H[1] = __half2(h2, h3);
    L[0] = __half2(l0, l1); L[1] = __half2(l2, l3);
}

// -------------------- embedding -------------------------------------------
__global__ void embed_kernel(const int* __restrict__ ctx,
                             const float* __restrict__ tok,
                             const float* __restrict__ pos) {
    int t = blockIdx.x;
    int token = ctx[t];
    int s = t & (SEQ - 1);
#pragma unroll
    for (int i = 0; i < 3; i++) {
        int d = threadIdx.x + i * 256;
        g_x[t * DM + d] = tok[token * DM + d] + pos[s * DM + d];
    }
}

// -------------------- layernorm -> fp16 ------------------------------------
__global__ void ln_half(const float* __restrict__ in,
                        const float* __restrict__ gg,
                        const float* __restrict__ bb,
                        f16* __restrict__ out) {
    int row = blockIdx.x;
    const float* x = in + row * DM;
    float v[3];
    float s = 0.f, ss = 0.f;
#pragma unroll
    for (int i = 0; i < 3; i++) {
        v[i] = x[threadIdx.x + i * 256];
        s  += v[i];
        ss += v[i] * v[i];
    }
#pragma unroll
    for (int m = 16; m; m >>= 1) {
        s  += __shfl_xor_sync(0xffffffffu, s,  m);
        ss += __shfl_xor_sync(0xffffffffu, ss, m);
    }
    __shared__ float sa[8], sb[8];
    int w = threadIdx.x >> 5, lane = threadIdx.x & 31;
    if (lane == 0) { sa[w] = s; sb[w] = ss; }
    __syncthreads();
    s = 0.f; ss = 0.f;
#pragma unroll
    for (int i = 0; i < 8; i++) { s += sa[i]; ss += sb[i]; }
    float mean = s * (1.0f / DM);
    float var  = ss * (1.0f / DM) - mean * mean;
    float inv  = rsqrtf(var + 1e-5f);
#pragma unroll
    for (int i = 0; i < 3; i++) {
        int d = threadIdx.x + i * 256;
        float y = (v[i] - mean) * inv * gg[d] + bb[d];
        out[row * DM + d] = __float2half_rn(y);
    }
}

// -------------------- fp16 tensor-core GEMM (2-pass weight split) ----------
// C[M,N] = A[M,K] @ (Bh + Bl)[K,N]; A single fp16, B split fp16 hi/lo.
// BK=32, BN=128, BM template {128,64}. 256 thr, warps 2(m)x4(n), 3-stage cp.async.
// A smem rows 64B (4x16B chunks), swizzle kc^((row>>1)&3).
// B smem rows 256B (16 chunks), swizzle ((nc&7)^(k&7))|(nc&8).

__device__ __forceinline__ uint32_t swzA(int row, int kc) {
    return (uint32_t)(row * 64 + ((kc ^ ((row >> 1) & 3)) << 4));
}
__device__ __forceinline__ uint32_t swzB(int k, int nc) {
    return (uint32_t)(k * 256 + ((((nc & 7) ^ (k & 7)) | (nc & 8)) << 4));
}

template<int BM>
__global__ __launch_bounds__(256, 2)
void hgemm(const f16* __restrict__ A,
           const f16* __restrict__ Bh, const f16* __restrict__ Bl,
           const float* __restrict__ bias, const float* __restrict__ res,
           float* __restrict__ C, f16* __restrict__ Oh,
           int N, int K, int relu) {
    constexpr int WM = BM / 2;
    constexpr int MT = WM / 16;
    constexpr int ABYTES = BM * 64;           // A tile bytes per stage
    constexpr int STAGE  = ABYTES + 16384;    // + Bh(8192) + Bl(8192)
    constexpr int NA = BM / 64;               // A 16B chunks per thread

    extern __shared__ char smc[];
    uint32_t sbase = cvta_smem(smc);

    int tid  = threadIdx.x;
    int lane = tid & 31;
    int warp = tid >> 5;
    int wm = warp >> 2;
    int wn = warp & 3;
    int g  = lane >> 2;
    int tg = lane & 3;
    int bm = blockIdx.x, bn = blockIdx.y;

    float acc[MT][4][4];
#pragma unroll
    for (int mi = 0; mi < MT; mi++)
#pragma unroll
        for (int ni = 0; ni < 4; ni++)
#pragma unroll
            for (int j = 0; j < 4; j++) acc[mi][ni][j] = 0.f;

#define LOADSTAGE(IT)                                                         \
    {                                                                         \
        int _it = (IT);                                                       \
        uint32_t st = sbase + (_it % 3) * STAGE;                              \
        _Pragma("unroll")                                                     \
        for (int u = 0; u < NA; u++) {                                        \
            int cu = tid + u * 256;                                           \
            int arow = cu >> 2, akc = cu & 3;                                 \
            uint32_t so = st + swzA(arow, akc);                               \
            size_t go = (size_t)(bm * BM + arow) * K + _it * 32 + akc * 8;    \
            cp16(so, A + go);                                                 \
        }                                                                     \
        _Pragma("unroll")                                                     \
        for (int u = 0; u < 2; u++) {                                         \
            int cu = tid + u * 256;                                           \
            int bk = cu >> 4, bnc = cu & 15;                                  \
            uint32_t so = st + ABYTES + swzB(bk, bnc);                        \
            size_t go = (size_t)(_it * 32 + bk) * N + bn * 128 + bnc * 8;     \
            cp16(so, Bh + go);                                                \
            cp16(so + 8192, Bl + go);                                         \
        }                                                                     \
    }

    int nIter = K >> 5;
    LOADSTAGE(0); asm volatile("cp.async.commit_group;");
    LOADSTAGE(1); asm volatile("cp.async.commit_group;");

    int a_lrow = wm * WM + (lane & 15);
    int a_koff = (lane >> 4) & 1;
    int b_lk   = lane & 15;
    int b_noff = (lane >> 4) & 1;

    for (int it = 0; it < nIter; it++) {
        asm volatile("cp.async.wait_group 1;");
        __syncthreads();
        uint32_t sb = sbase + (it % 3) * STAGE;

#pragma unroll
        for (int k16 = 0; k16 < 2; k16++) {
            uint32_t Af[MT][4], Bf[4][2];
            int kc = k16 * 2 + a_koff;
#pragma unroll
            for (int mi = 0; mi < MT; mi++)
                ldm_x4(Af[mi], sb + swzA(a_lrow + mi * 16, kc));
            int kk = k16 * 16 + b_lk;
#pragma unroll
            for (int p = 0; p < 2; p++) {
                uint32_t r4[4];
                ldm_x4_t(r4, sb + ABYTES + swzB(kk, wn * 4 + p * 2 + b_noff));
                Bf[p*2][0] = r4[0]; Bf[p*2][1] = r4[1];
                Bf[p*2+1][0] = r4[2]; Bf[p*2+1][1] = r4[3];
            }
#pragma unroll
            for (int mi = 0; mi < MT; mi++)
#pragma unroll
                for (int ni = 0; ni < 4; ni++) mma_f16(acc[mi][ni], Af[mi], Bf[ni]);
#pragma unroll
            for (int p = 0; p < 2; p++) {
                uint32_t r4[4];
                ldm_x4_t(r4, sb + ABYTES + 8192 + swzB(kk, wn * 4 + p * 2 + b_noff));
                Bf[p*2][0] = r4[0]; Bf[p*2][1] = r4[1];
                Bf[p*2+1][0] = r4[2]; Bf[p*2+1][1] = r4[3];
            }
#pragma unroll
            for (int mi = 0; mi < MT; mi++)
#pragma unroll
                for (int ni = 0; ni < 4; ni++) mma_f16(acc[mi][ni], Af[mi], Bf[ni]);
        }

        if (it + 2 < nIter) LOADSTAGE(it + 2);
        asm volatile("cp.async.commit_group;");
    }
#undef LOADSTAGE

    // epilogue
#pragma unroll
    for (int mi = 0; mi < MT; mi++) {
        int row0 = bm * BM + wm * WM + mi * 16 + g;
#pragma unroll
        for (int ni = 0; ni < 4; ni++) {
            int col = bn * 128 + wn * 32 + ni * 8 + 2 * tg;
            float b0 = 0.f, b1 = 0.f;
            if (bias) { b0 = bias[col]; b1 = bias[col + 1]; }
#pragma unroll
            for (int half = 0; half < 2; half++) {
                int row = row0 + half * 8;
                float v0 = acc[mi][ni][half * 2 + 0] + b0;
                float v1 = acc[mi][ni][half * 2 + 1] + b1;
                if (relu) { v0 = fmaxf(v0, 0.f); v1 = fmaxf(v1, 0.f); }
                size_t idx = (size_t)row * N + col;
                if (Oh) {
                    *(__half2*)(Oh + idx) =
                        __half2(__float2half_rn(v0), __float2half_rn(v1));
                } else {
                    if (res) {
                        float2 r2 = *(const float2*)(res + idx);
                        v0 += r2.x; v1 += r2.y;
                    }
                    *(float2*)(C + idx) = make_float2(v0, v1);
                }
            }
        }
    }
}

// -------------------- flash attention (causal, fp32, packed QKV) -----------
#define SP 68
#define ATT_SMEM (4 * 64 * SP * 4)

__global__ __launch_bounds__(256)
void attn_kernel(const float* __restrict__ QKV, f16* __restrict__ O) {
    extern __shared__ float sm[];
    float* Qs = sm;
    float* Ks = sm + 64 * SP;
    float* Vs = sm + 2 * 64 * SP;
    float* Ps = sm + 3 * 64 * SP;

    int qt = blockIdx.x, h = blockIdx.y, b = blockIdx.z;
    int tid = threadIdx.x;
    int tx = tid & 15, ty = tid >> 4;
    int r0 = ty * 4, c0 = tx * 4;

    const float scale = 0.125f;
    size_t base_q = (size_t)(b * SEQ + qt * 64) * QKVS + h * HDIM;

#pragma unroll
    for (int i = 0; i < 4; i++) {
        int idx = tid + i * 256;
        int row = idx >> 4;
        int c4  = (idx & 15) << 2;
        float4 qv = *(const float4*)&QKV[base_q + (size_t)row * QKVS + c4];
        qv.x *= scale; qv.y *= scale; qv.z *= scale; qv.w *= scale;
        *(float4*)&Qs[row * SP + c4] = qv;
    }

    float o[4][4];
#pragma unroll
    for (int i = 0; i < 4; i++)
#pragma unroll
        for (int j = 0; j < 4; j++) o[i][j] = 0.f;
    float m[4], l[4];
#pragma unroll
    for (int i = 0; i < 4; i++) { m[i] = -INFINITY; l[i] = 0.f; }

    for (int kt = 0; kt <= qt; kt++) {
        __syncthreads();
        size_t base_k = (size_t)(b * SEQ + kt * 64) * QKVS + DM + h * HDIM;
#pragma unroll
        for (int i = 0; i < 4; i++) {
            int idx = tid + i * 256;
            int row = idx >> 4;
            int c4  = (idx & 15) << 2;
            *(float4*)&Ks[row * SP + c4] =
                *(const float4*)&QKV[base_k + (size_t)row * QKVS + c4];
            *(float4*)&Vs[row * SP + c4] =
                *(const float4*)&QKV[base_k + DM + (size_t)row * QKVS + c4];
        }
        __syncthreads();

        float s[4][4];
#pragma unroll
        for (int i = 0; i < 4; i++)
#pragma unroll
            for (int j = 0; j < 4; j++) s[i][j] = 0.f;

#pragma unroll
        for (int d4 = 0; d4 < 16; d4++) {
            float4 qv[4], kv[4];
#pragma unroll
            for (int i = 0; i < 4; i++) qv[i] = *(const float4*)&Qs[(r0 + i) * SP + d4 * 4];
#pragma unroll
            for (int j = 0; j < 4; j++) kv[j] = *(const float4*)&Ks[(c0 + j) * SP + d4 * 4];
#pragma unroll
            for (int i = 0; i < 4; i++)
#pragma unroll
                for (int j = 0; j < 4; j++)
                    s[i][j] += qv[i].x * kv[j].x + qv[i].y * kv[j].y +
                               qv[i].z * kv[j].z + qv[i].w * kv[j].w;
        }

        if (kt == qt) {
#pragma unroll
            for (int i = 0; i < 4; i++)
#pragma unroll
                for (int j = 0; j < 4; j++)
                    if (c0 + j > r0 + i) s[i][j] = -INFINITY;
        }

#pragma unroll
        for (int i = 0; i < 4; i++) {
            float mx = fmaxf(fmaxf(s[i][0], s[i][1]), fmaxf(s[i][2], s[i][3]));
#pragma unroll
            for (int mk = 8; mk; mk >>= 1)
                mx = fmaxf(mx, __shfl_xor_sync(0xffffffffu, mx, mk));
            float mnew = fmaxf(m[i], mx);
            float fac = __expf(m[i] - mnew);
            float lsum = 0.f;
#pragma unroll
            for (int j = 0; j < 4; j++) {
                s[i][j] = __expf(s[i][j] - mnew);
                lsum += s[i][j];
            }
#pragma unroll
            for (int mk = 8; mk; mk >>= 1)
                lsum += __shfl_xor_sync(0xffffffffu, lsum, mk);
            l[i] = l[i] * fac + lsum;
            m[i] = mnew;
#pragma unroll
            for (int j = 0; j < 4; j++) o[i][j] *= fac;
            *(float4*)&Ps[(r0 + i) * SP + c0] =
                make_float4(s[i][0], s[i][1], s[i][2], s[i][3]);
        }
        __syncthreads();

#pragma unroll
        for (int k4 = 0; k4 < 16; k4++) {
            float4 pv[4], vv[4];
#pragma unroll
            for (int i = 0; i < 4; i++) pv[i] = *(const float4*)&Ps[(r0 + i) * SP + k4 * 4];
#pragma unroll
            for (int tt = 0; tt < 4; tt++) vv[tt] = *(const float4*)&Vs[(k4 * 4 + tt) * SP + c0];
#pragma unroll
            for (int i = 0; i < 4; i++) {
                float p0 = pv[i].x, p1 = pv[i].y, p2 = pv[i].z, p3 = pv[i].w;
                o[i][0] += p0 * vv[0].x + p1 * vv[1].x + p2 * vv[2].x + p3 * vv[3].x;
                o[i][1] += p0 * vv[0].y + p1 * vv[1].y + p2 * vv[2].y + p3 * vv[3].y;
                o[i][2] += p0 * vv[0].z + p1 * vv[1].z + p2 * vv[2].z + p3 * vv[3].z;
                o[i][3] += p0 * vv[0].w + p1 * vv[1].w + p2 * vv[2].w + p3 * vv[3].w;
            }
        }
    }

#pragma unroll
    for (int i = 0; i < 4; i++) {
        float inv = 1.f / l[i];
        size_t idx = (size_t)(b * SEQ + qt * 64 + r0 + i) * DM + h * HDIM + c0;
#pragma unroll
        for (int j = 0; j < 4; j += 2) {
            *(__half2*)(O + idx + j) =
                __half2(__float2half_rn(o[i][j] * inv),
                        __float2half_rn(o[i][j + 1] * inv));
        }
    }
}

// -------------------- host orchestration ----------------------------------
#define SM128 (3 * (128 * 64 + 16384))   // 73728
#define SM64  (3 * (64 * 64 + 16384))    // 61440

extern "C" void kernel_launch(void* const* d_in, const int* in_sizes, int n_in,
                              void* d_out, int out_size) {
    const int*   ctx  = (const int*)  d_in[0];
    const float* tok  = (const float*)d_in[1];
    const float* pos  = (const float*)d_in[2];
    const float* Wq   = (const float*)d_in[3];
    const float* Wk   = (const float*)d_in[4];
    const float* Wv   = (const float*)d_in[5];
    const float* Wo   = (const float*)d_in[6];
    const float* bo   = (const float*)d_in[7];
    const float* ln1g = (const float*)d_in[8];
    const float* ln1b = (const float*)d_in[9];
    const float* W1   = (const float*)d_in[10];
    const float* b1   = (const float*)d_in[11];
    const float* W2   = (const float*)d_in[12];
    const float* b2   = (const float*)d_in[13];
    const float* ln2g = (const float*)d_in[14];
    const float* ln2b = (const float*)d_in[15];
    const float* lnfg = (const float*)d_in[16];
    const float* lnfb = (const float*)d_in[17];
    const float* Wout = (const float*)d_in[18];
    const float* bout = (const float*)d_in[19];

    float *px, *pqkv;
    f16 *ph, *pat, *pff;
    f16 *pwqkv_h, *pwqkv_l, *pwo_h, *pwo_l, *pw1_h, *pw1_l, *pw2_h, *pw2_l;
    f16 *pwout_h, *pwout_l;
    cudaGetSymbolAddress((void**)&px,   g_x);
    cudaGetSymbolAddress((void**)&pqkv, g_qkv);
    cudaGetSymbolAddress((void**)&ph,   g_h);
    cudaGetSymbolAddress((void**)&pat,  g_at);
    cudaGetSymbolAddress((void**)&pff,  g_ff);
    cudaGetSymbolAddress((void**)&pwqkv_h, g_wqkv_h);
    cudaGetSymbolAddress((void**)&pwqkv_l, g_wqkv_l);
    cudaGetSymbolAddress((void**)&pwo_h, g_wo_h);
    cudaGetSymbolAddress((void**)&pwo_l, g_wo_l);
    cudaGetSymbolAddress((void**)&pw1_h, g_w1_h);
    cudaGetSymbolAddress((void**)&pw1_l, g_w1_l);
    cudaGetSymbolAddress((void**)&pw2_h, g_w2_h);
    cudaGetSymbolAddress((void**)&pw2_l, g_w2_l);
    cudaGetSymbolAddress((void**)&pwout_h, g_wout_h);
    cudaGetSymbolAddress((void**)&pwout_l, g_wout_l);

    cudaFuncSetAttribute(attn_kernel,
                         cudaFuncAttributeMaxDynamicSharedMemorySize, ATT_SMEM);
    cudaFuncSetAttribute(hgemm<128>,
                         cudaFuncAttributeMaxDynamicSharedMemorySize, SM128);
    cudaFuncSetAttribute(hgemm<64>,
                         cudaFuncAttributeMaxDynamicSharedMemorySize, SM64);

    // ---- weight splitting ----
    int t;
    t = NL * DM * DM / 4;
    wsplit<<<(t + 255) / 256, 256>>>(Wq, pwqkv_h, pwqkv_l, DM, QKVS, 0,      t);
    wsplit<<<(t + 255) / 256, 256>>>(Wk, pwqkv_h, pwqkv_l, DM, QKVS, DM,     t);
    wsplit<<<(t + 255) / 256, 256>>>(Wv, pwqkv_h, pwqkv_l, DM, QKVS, 2 * DM, t);
    wsplit<<<(t + 255) / 256, 256>>>(Wo, pwo_h, pwo_l, DM, DM, 0, t);
    t = NL * DM * DFF / 4;
    wsplit<<<(t + 255) / 256, 256>>>(W1, pw1_h, pw1_l, DFF, DFF, 0, t);
    wsplit<<<(t + 255) / 256, 256>>>(W2, pw2_h, pw2_l, DM, DM, 0, t);
    t = DM * NV / 4;
    wsplit<<<(t + 255) / 256, 256>>>(Wout, pwout_h, pwout_l, NV, NV, 0, t);

    embed_kernel<<<TOK, 256>>>(ctx, tok, pos);

    for (int l = 0; l < NL; l++) {
        size_t oqkv = (size_t)l * DM * QKVS;
        size_t owo  = (size_t)l * DM * DM;
        size_t ow1  = (size_t)l * DM * DFF;
        size_t ow2  = (size_t)l * DFF * DM;

        ln_half<<<TOK, 256>>>(px, ln1g + l * DM, ln1b + l * DM, ph);
        hgemm<128><<<dim3(16, 18), 256, SM128>>>(
            ph, pwqkv_h + oqkv, pwqkv_l + oqkv,
            nullptr, nullptr, pqkv, nullptr, QKVS, DM, 0);
        attn_kernel<<<dim3(SEQ / 64, NH, 2), 256, ATT_SMEM>>>(pqkv, pat);
        hgemm<64><<<dim3(32, 6), 256, SM64>>>(
            pat, pwo_h + owo, pwo_l + owo,
            bo + l * DM, px, px, nullptr, DM, DM, 0);
        ln_half<<<TOK, 256>>>(px, ln2g + l * DM, ln2b + l * DM, ph);
        hgemm<128><<<dim3(16, 24), 256, SM128>>>(
            ph, pw1_h + ow1, pw1_l + ow1,
            b1 + (size_t)l * DFF, nullptr, nullptr, pff, DFF, DM, 1);
        hgemm<64><<<dim3(32, 6), 256, SM64>>>(
            pff, pw2_h + ow2, pw2_l + ow2,
            b2 + l * DM, px, px, nullptr, DM, DFF, 0);
    }

    ln_half<<<TOK, 256>>>(px, lnfg, lnfb, ph);
    hgemm<128><<<dim3(16, 250), 256, SM128>>>(
        ph, pwout_h, pwout_l,
        bout, nullptr, (float*)d_out, nullptr, NV, DM, 0);
}

// round 7
// speedup vs baseline: 4.7681x; 1.6596x over previous
#include <cuda_runtime.h>
#include <cuda_fp16.h>
#include <math.h>
#include <stdint.h>

// Problem constants
#define TOK   2048          // B*S
#define SEQ   1024
#define DM    768
#define DFF   3072
#define NH    12
#define HDIM  64
#define NV    32000
#define NL    6
#define QKVS  (3 * DM)      // 2304

typedef __half f16;

// -------------------- scratch (device globals; no allocation allowed) -----
__device__ __align__(16) float g_x  [TOK * DM];
__device__ __align__(16) f16   g_qkv[TOK * QKVS];
__device__ __align__(16) f16   g_h  [TOK * DM];
__device__ __align__(16) f16   g_at [TOK * DM];
__device__ __align__(16) f16   g_ff [TOK * DFF];
// split weights [K,N] fp16 hi/lo
__device__ __align__(16) f16 g_wqkv_h[NL * DM * QKVS];
__device__ __align__(16) f16 g_wqkv_l[NL * DM * QKVS];
__device__ __align__(16) f16 g_wo_h [NL * DM * DM];
__device__ __align__(16) f16 g_wo_l [NL * DM * DM];
__device__ __align__(16) f16 g_w1_h [NL * DM * DFF];
__device__ __align__(16) f16 g_w1_l [NL * DM * DFF];
__device__ __align__(16) f16 g_w2_h [NL * DFF * DM];
__device__ __align__(16) f16 g_w2_l [NL * DFF * DM];
__device__ __align__(16) f16 g_wout_h[DM * NV];
__device__ __align__(16) f16 g_wout_l[DM * NV];

// -------------------- helpers ---------------------------------------------
__device__ __forceinline__ void hsplit(float x, f16& h, f16& l) {
    h = __float2half_rn(x);
    l = __float2half_rn(x - __half2float(h));
}
__device__ __forceinline__ uint32_t cvta_smem(const void* p) {
    return (uint32_t)__cvta_generic_to_shared(p);
}
__device__ __forceinline__ void cp16(uint32_t s, const void* g) {
    asm volatile("cp.async.cg.shared.global [%0], [%1], 16;" :: "r"(s), "l"(g));
}
__device__ __forceinline__ void ldm_x4(uint32_t* r, uint32_t addr) {
    asm volatile("ldmatrix.sync.aligned.m8n8.x4.shared.b16 {%0,%1,%2,%3},[%4];"
                 : "=r"(r[0]), "=r"(r[1]), "=r"(r[2]), "=r"(r[3]) : "r"(addr));
}
__device__ __forceinline__ void ldm_x4_t(uint32_t* r, uint32_t addr) {
    asm volatile("ldmatrix.sync.aligned.m8n8.x4.trans.shared.b16 {%0,%1,%2,%3},[%4];"
                 : "=r"(r[0]), "=r"(r[1]), "=r"(r[2]), "=r"(r[3]) : "r"(addr));
}
__device__ __forceinline__ void mma_f16(float* c, const uint32_t* a, const uint32_t* b) {
    asm volatile(
        "mma.sync.aligned.m16n8k16.row.col.f32.f16.f16.f32 "
        "{%0,%1,%2,%3},{%4,%5,%6,%7},{%8,%9},{%0,%1,%2,%3};"
        : "+f"(c[0]), "+f"(c[1]), "+f"(c[2]), "+f"(c[3])
        : "r"(a[0]), "r"(a[1]), "r"(a[2]), "r"(a[3]), "r"(b[0]), "r"(b[1]));
}
__device__ __forceinline__ uint32_t pack_h2(float a, float b) {
    __half2 h = __floats2half2_rn(a, b);
    return *(uint32_t*)&h;
}

// -------------------- weight split/pack kernel -----------------------------
__global__ void wsplit(const float* __restrict__ src, f16* __restrict__ dh,
                       f16* __restrict__ dl, int cols, int dst_stride,
                       int cofs, int total4) {
    int i = blockIdx.x * 256 + threadIdx.x;
    if (i >= total4) return;
    int e = i * 4;
    int r = e / cols, c = e - r * cols;
    float4 v = *(const float4*)(src + (size_t)e);
    size_t d = (size_t)r * dst_stride + cofs + c;
    f16 h0, l0, h1, l1, h2, l2, h3, l3;
    hsplit(v.x, h0, l0); hsplit(v.y, h1, l1);
    hsplit(v.z, h2, l2); hsplit(v.w, h3, l3);
    __half2* H = (__half2*)(dh + d);
    __half2* L = (__half2*)(dl + d);
    H[0] = __half2(h0, h1); H[1] = __half2(h2, h3);
    L[0] = __half2(l0, l1); L[1] = __half2(l2, l3);
}

// -------------------- embedding -------------------------------------------
__global__ void embed_kernel(const int* __restrict__ ctx,
                             const float* __restrict__ tok,
                             const float* __restrict__ pos) {
    int t = blockIdx.x;
    int token = ctx[t];
    int s = t & (SEQ - 1);
#pragma unroll
    for (int i = 0; i < 3; i++) {
        int d = threadIdx.x + i * 256;
        g_x[t * DM + d] = tok[token * DM + d] + pos[s * DM + d];
    }
}

// -------------------- layernorm -> fp16 ------------------------------------
__global__ void ln_half(const float* __restrict__ in,
                        const float* __restrict__ gg,
                        const float* __restrict__ bb,
                        f16* __restrict__ out) {
    int row = blockIdx.x;
    const float* x = in + row * DM;
    float v[3];
    float s = 0.f, ss = 0.f;
#pragma unroll
    for (int i = 0; i < 3; i++) {
        v[i] = x[threadIdx.x + i * 256];
        s  += v[i];
        ss += v[i] * v[i];
    }
#pragma unroll
    for (int m = 16; m; m >>= 1) {
        s  += __shfl_xor_sync(0xffffffffu, s,  m);
        ss += __shfl_xor_sync(0xffffffffu, ss, m);
    }
    __shared__ float sa[8], sb[8];
    int w = threadIdx.x >> 5, lane = threadIdx.x & 31;
    if (lane == 0) { sa[w] = s; sb[w] = ss; }
    __syncthreads();
    s = 0.f; ss = 0.f;
#pragma unroll
    for (int i = 0; i < 8; i++) { s += sa[i]; ss += sb[i]; }
    float mean = s * (1.0f / DM);
    float var  = ss * (1.0f / DM) - mean * mean;
    float inv  = rsqrtf(var + 1e-5f);
#pragma unroll
    for (int i = 0; i < 3; i++) {
        int d = threadIdx.x + i * 256;
        float y = (v[i] - mean) * inv * gg[d] + bb[d];
        out[row * DM + d] = __float2half_rn(y);
    }
}

// -------------------- fp16 tensor-core GEMM (2-pass weight split) ----------
__device__ __forceinline__ uint32_t swzA(int row, int kc) {
    return (uint32_t)(row * 64 + ((kc ^ ((row >> 1) & 3)) << 4));
}
__device__ __forceinline__ uint32_t swzB(int k, int nc) {
    return (uint32_t)(k * 256 + ((((nc & 7) ^ (k & 7)) | (nc & 8)) << 4));
}

template<int BM>
__global__ __launch_bounds__(256, 2)
void hgemm(const f16* __restrict__ A,
           const f16* __restrict__ Bh, const f16* __restrict__ Bl,
           const float* __restrict__ bias, const float* __restrict__ res,
           float* __restrict__ C, f16* __restrict__ Oh,
           int N, int K, int relu) {
    constexpr int WM = BM / 2;
    constexpr int MT = WM / 16;
    constexpr int ABYTES = BM * 64;
    constexpr int STAGE  = ABYTES + 16384;
    constexpr int NA = BM / 64;

    extern __shared__ char smc[];
    uint32_t sbase = cvta_smem(smc);

    int tid  = threadIdx.x;
    int lane = tid & 31;
    int warp = tid >> 5;
    int wm = warp >> 2;
    int wn = warp & 3;
    int g  = lane >> 2;
    int tg = lane & 3;
    int bm = blockIdx.x, bn = blockIdx.y;

    float acc[MT][4][4];
#pragma unroll
    for (int mi = 0; mi < MT; mi++)
#pragma unroll
        for (int ni = 0; ni < 4; ni++)
#pragma unroll
            for (int j = 0; j < 4; j++) acc[mi][ni][j] = 0.f;

#define LOADSTAGE(IT)                                                         \
    {                                                                         \
        int _it = (IT);                                                       \
        uint32_t st = sbase + (_it % 3) * STAGE;                              \
        _Pragma("unroll")                                                     \
        for (int u = 0; u < NA; u++) {                                        \
            int cu = tid + u * 256;                                           \
            int arow = cu >> 2, akc = cu & 3;                                 \
            uint32_t so = st + swzA(arow, akc);                               \
            size_t go = (size_t)(bm * BM + arow) * K + _it * 32 + akc * 8;    \
            cp16(so, A + go);                                                 \
        }                                                                     \
        _Pragma("unroll")                                                     \
        for (int u = 0; u < 2; u++) {                                         \
            int cu = tid + u * 256;                                           \
            int bk = cu >> 4, bnc = cu & 15;                                  \
            uint32_t so = st + ABYTES + swzB(bk, bnc);                        \
            size_t go = (size_t)(_it * 32 + bk) * N + bn * 128 + bnc * 8;     \
            cp16(so, Bh + go);                                                \
            cp16(so + 8192, Bl + go);                                         \
        }                                                                     \
    }

    int nIter = K >> 5;
    LOADSTAGE(0); asm volatile("cp.async.commit_group;");
    LOADSTAGE(1); asm volatile("cp.async.commit_group;");

    int a_lrow = wm * WM + (lane & 15);
    int a_koff = (lane >> 4) & 1;
    int b_lk   = lane & 15;
    int b_noff = (lane >> 4) & 1;

    for (int it = 0; it < nIter; it++) {
        asm volatile("cp.async.wait_group 1;");
        __syncthreads();
        uint32_t sb = sbase + (it % 3) * STAGE;

#pragma unroll
        for (int k16 = 0; k16 < 2; k16++) {
            uint32_t Af[MT][4], Bf[4][2];
            int kc = k16 * 2 + a_koff;
#pragma unroll
            for (int mi = 0; mi < MT; mi++)
                ldm_x4(Af[mi], sb + swzA(a_lrow + mi * 16, kc));
            int kk = k16 * 16 + b_lk;
#pragma unroll
            for (int p = 0; p < 2; p++) {
                uint32_t r4[4];
                ldm_x4_t(r4, sb + ABYTES + swzB(kk, wn * 4 + p * 2 + b_noff));
                Bf[p*2][0] = r4[0]; Bf[p*2][1] = r4[1];
                Bf[p*2+1][0] = r4[2]; Bf[p*2+1][1] = r4[3];
            }
#pragma unroll
            for (int mi = 0; mi < MT; mi++)
#pragma unroll
                for (int ni = 0; ni < 4; ni++) mma_f16(acc[mi][ni], Af[mi], Bf[ni]);
#pragma unroll
            for (int p = 0; p < 2; p++) {
                uint32_t r4[4];
                ldm_x4_t(r4, sb + ABYTES + 8192 + swzB(kk, wn * 4 + p * 2 + b_noff));
                Bf[p*2][0] = r4[0]; Bf[p*2][1] = r4[1];
                Bf[p*2+1][0] = r4[2]; Bf[p*2+1][1] = r4[3];
            }
#pragma unroll
            for (int mi = 0; mi < MT; mi++)
#pragma unroll
                for (int ni = 0; ni < 4; ni++) mma_f16(acc[mi][ni], Af[mi], Bf[ni]);
        }

        if (it + 2 < nIter) LOADSTAGE(it + 2);
        asm volatile("cp.async.commit_group;");
    }
#undef LOADSTAGE

#pragma unroll
    for (int mi = 0; mi < MT; mi++) {
        int row0 = bm * BM + wm * WM + mi * 16 + g;
#pragma unroll
        for (int ni = 0; ni < 4; ni++) {
            int col = bn * 128 + wn * 32 + ni * 8 + 2 * tg;
            float b0 = 0.f, b1 = 0.f;
            if (bias) { b0 = bias[col]; b1 = bias[col + 1]; }
#pragma unroll
            for (int half = 0; half < 2; half++) {
                int row = row0 + half * 8;
                float v0 = acc[mi][ni][half * 2 + 0] + b0;
                float v1 = acc[mi][ni][half * 2 + 1] + b1;
                if (relu) { v0 = fmaxf(v0, 0.f); v1 = fmaxf(v1, 0.f); }
                size_t idx = (size_t)row * N + col;
                if (Oh) {
                    *(__half2*)(Oh + idx) =
                        __half2(__float2half_rn(v0), __float2half_rn(v1));
                } else {
                    if (res) {
                        float2 r2 = *(const float2*)(res + idx);
                        v0 += r2.x; v1 += r2.y;
                    }
                    *(float2*)(C + idx) = make_float2(v0, v1);
                }
            }
        }
    }
}

// -------------------- fp16 tensor-core flash attention ----------------------
// 128 threads / 4 warps; each warp owns 16 Q rows. KV tiles 64 rows, 3-stage
// cp.async. S = Q*K^T via mma (fp32 acc); P stays in registers as the A-frag
// of P*V. K loaded with ldmatrix (its [kv][hd] layout is B col-major);
// V with ldmatrix.trans. Softmax fp32.
#define AQ_BYTES 8192
#define AKV_STAGE 16384
#define ATT_SMEM (AQ_BYTES + 3 * AKV_STAGE)

__device__ __forceinline__ uint32_t swzR(int row, int c) {   // 128B rows
    return (uint32_t)(row * 128 + ((c ^ (row & 7)) << 4));
}

__global__ __launch_bounds__(128)
void attn_f16(const f16* __restrict__ QKV, f16* __restrict__ O) {
    extern __shared__ char smc[];
    uint32_t sb = cvta_smem(smc);

    int qt = blockIdx.x, h = blockIdx.y, b = blockIdx.z;
    int tid = threadIdx.x, lane = tid & 31, warp = tid >> 5;
    int g = lane >> 2, tg = lane & 3;
    int wrow = warp * 16;
    int nT = qt + 1;

    const f16* Qg = QKV + (size_t)(b * SEQ + qt * 64) * QKVS + h * HDIM;

#define LOADQ()                                                               \
    {                                                                         \
        _Pragma("unroll")                                                     \
        for (int u = 0; u < 4; u++) {                                         \
            int idx = tid + u * 128;                                          \
            int row = idx >> 3, c = idx & 7;                                  \
            cp16(sb + swzR(row, c), Qg + (size_t)row * QKVS + c * 8);         \
        }                                                                     \
    }
#define LOADKV(SLOT, KT)                                                      \
    {                                                                         \
        uint32_t st = sb + AQ_BYTES + ((SLOT) % 3) * AKV_STAGE;               \
        const f16* Kg = QKV + (size_t)(b * SEQ + (KT) * 64) * QKVS            \
                        + DM + h * HDIM;                                      \
        _Pragma("unroll")                                                     \
        for (int u = 0; u < 4; u++) {                                         \
            int idx = tid + u * 128;                                          \
            int row = idx >> 3, c = idx & 7;                                  \
            uint32_t so = st + swzR(row, c);                                  \
            size_t go = (size_t)row * QKVS + c * 8;                           \
            cp16(so, Kg + go);                                                \
            cp16(so + 8192, Kg + DM + go);                                    \
        }                                                                     \
    }

    LOADQ(); LOADKV(0, 0);
    asm volatile("cp.async.commit_group;");
    if (1 < nT) LOADKV(1, 1);
    asm volatile("cp.async.commit_group;");

    float o[8][4];
#pragma unroll
    for (int nt = 0; nt < 8; nt++)
#pragma unroll
        for (int j = 0; j < 4; j++) o[nt][j] = 0.f;
    float m[2] = {-INFINITY, -INFINITY}, l[2] = {0.f, 0.f};
    uint32_t qf[4][4];

    for (int kt = 0; kt < nT; kt++) {
        asm volatile("cp.async.wait_group 1;");
        __syncthreads();

        if (kt == 0) {
#pragma unroll
            for (int i = 0; i < 4; i++) {
                int row = wrow + (lane & 15);
                int c = 2 * i + (lane >> 4);
                ldm_x4(qf[i], sb + swzR(row, c));
            }
        }

        // issue stage kt+2 into buffer (kt+2)%3 (consumed at kt-1; safe)
        if (kt + 2 < nT) LOADKV(kt + 2, kt + 2);
        asm volatile("cp.async.commit_group;");

        uint32_t kb = sb + AQ_BYTES + (kt % 3) * AKV_STAGE;
        float s[8][4];
#pragma unroll
        for (int nt = 0; nt < 8; nt++)
#pragma unroll
            for (int j = 0; j < 4; j++) s[nt][j] = 0.f;

#pragma unroll
        for (int ntp = 0; ntp < 4; ntp++) {
            int krow = ntp * 16 + (lane & 7) + ((lane >> 4) << 3);
#pragma unroll
            for (int i = 0; i < 4; i++) {
                uint32_t r4[4];
                int c = 2 * i + ((lane >> 3) & 1);
                ldm_x4(r4, kb + swzR(krow, c));
                mma_f16(s[2 * ntp],     qf[i], r4);
                mma_f16(s[2 * ntp + 1], qf[i], r4 + 2);
            }
        }

        // scale + causal mask
#pragma unroll
        for (int nt = 0; nt < 8; nt++)
#pragma unroll
            for (int j = 0; j < 4; j++) s[nt][j] *= 0.125f;
        if (kt == qt) {
            int rA = wrow + g, rB = rA + 8;
#pragma unroll
            for (int nt = 0; nt < 8; nt++) {
                int cc = nt * 8 + 2 * tg;
                if (cc     > rA) s[nt][0] = -1e30f;
                if (cc + 1 > rA) s[nt][1] = -1e30f;
                if (cc     > rB) s[nt][2] = -1e30f;
                if (cc + 1 > rB) s[nt][3] = -1e30f;
            }
        }

        // online softmax (rows g and g+8)
        float mxA = -1e30f, mxB = -1e30f;
#pragma unroll
        for (int nt = 0; nt < 8; nt++) {
            mxA = fmaxf(mxA, fmaxf(s[nt][0], s[nt][1]));
            mxB = fmaxf(mxB, fmaxf(s[nt][2], s[nt][3]));
        }
        mxA = fmaxf(mxA, __shfl_xor_sync(0xffffffffu, mxA, 1));
        mxA = fmaxf(mxA, __shfl_xor_sync(0xffffffffu, mxA, 2));
        mxB = fmaxf(mxB, __shfl_xor_sync(0xffffffffu, mxB, 1));
        mxB = fmaxf(mxB, __shfl_xor_sync(0xffffffffu, mxB, 2));
        float mnA = fmaxf(m[0], mxA), mnB = fmaxf(m[1], mxB);
        float fA = __expf(m[0] - mnA), fB = __expf(m[1] - mnB);
        float sA = 0.f, sB = 0.f;
#pragma unroll
        for (int nt = 0; nt < 8; nt++) {
            s[nt][0] = __expf(s[nt][0] - mnA);
            s[nt][1] = __expf(s[nt][1] - mnA);
            s[nt][2] = __expf(s[nt][2] - mnB);
            s[nt][3] = __expf(s[nt][3] - mnB);
            sA += s[nt][0] + s[nt][1];
            sB += s[nt][2] + s[nt][3];
        }
        sA += __shfl_xor_sync(0xffffffffu, sA, 1);
        sA += __shfl_xor_sync(0xffffffffu, sA, 2);
        sB += __shfl_xor_sync(0xffffffffu, sB, 1);
        sB += __shfl_xor_sync(0xffffffffu, sB, 2);
        l[0] = l[0] * fA + sA; m[0] = mnA;
        l[1] = l[1] * fB + sB; m[1] = mnB;
#pragma unroll
        for (int nt = 0; nt < 8; nt++) {
            o[nt][0] *= fA; o[nt][1] *= fA;
            o[nt][2] *= fB; o[nt][3] *= fB;
        }

        // P fragments (A-operand of PV) directly from S fragments
        uint32_t pk[4][4];
#pragma unroll
        for (int i = 0; i < 4; i++) {
            pk[i][0] = pack_h2(s[2*i][0],   s[2*i][1]);
            pk[i][1] = pack_h2(s[2*i][2],   s[2*i][3]);
            pk[i][2] = pack_h2(s[2*i+1][0], s[2*i+1][1]);
            pk[i][3] = pack_h2(s[2*i+1][2], s[2*i+1][3]);
        }

        uint32_t vb = kb + 8192;
#pragma unroll
        for (int i = 0; i < 4; i++) {
            int vrow = i * 16 + (lane & 15);
#pragma unroll
            for (int hdp = 0; hdp < 4; hdp++) {
                uint32_t r4[4];
                int c = 2 * hdp + (lane >> 4);
                ldm_x4_t(r4, vb + swzR(vrow, c));
                mma_f16(o[2 * hdp],     pk[i], r4);
                mma_f16(o[2 * hdp + 1], pk[i], r4 + 2);
            }
        }
    }
#undef LOADQ
#undef LOADKV

    float iA = 1.f / l[0], iB = 1.f / l[1];
    size_t rowA = (size_t)(b * SEQ + qt * 64 + wrow + g);
    f16* oA = O + rowA * DM + h * HDIM;
    f16* oB = oA + (size_t)8 * DM;
#pragma unroll
    for (int nt = 0; nt < 8; nt++) {
        int cc = nt * 8 + 2 * tg;
        *(__half2*)(oA + cc) = __floats2half2_rn(o[nt][0] * iA, o[nt][1] * iA);
        *(__half2*)(oB + cc) = __floats2half2_rn(o[nt][2] * iB, o[nt][3] * iB);
    }
}

// -------------------- host orchestration ----------------------------------
#define SM128 (3 * (128 * 64 + 16384))   // 73728
#define SM64  (3 * (64 * 64 + 16384))    // 61440

extern "C" void kernel_launch(void* const* d_in, const int* in_sizes, int n_in,
                              void* d_out, int out_size) {
    const int*   ctx  = (const int*)  d_in[0];
    const float* tok  = (const float*)d_in[1];
    const float* pos  = (const float*)d_in[2];
    const float* Wq   = (const float*)d_in[3];
    const float* Wk   = (const float*)d_in[4];
    const float* Wv   = (const float*)d_in[5];
    const float* Wo   = (const float*)d_in[6];
    const float* bo   = (const float*)d_in[7];
    const float* ln1g = (const float*)d_in[8];
    const float* ln1b = (const float*)d_in[9];
    const float* W1   = (const float*)d_in[10];
    const float* b1   = (const float*)d_in[11];
    const float* W2   = (const float*)d_in[12];
    const float* b2   = (const float*)d_in[13];
    const float* ln2g = (const float*)d_in[14];
    const float* ln2b = (const float*)d_in[15];
    const float* lnfg = (const float*)d_in[16];
    const float* lnfb = (const float*)d_in[17];
    const float* Wout = (const float*)d_in[18];
    const float* bout = (const float*)d_in[19];

    float* px;
    f16 *pqkv, *ph, *pat, *pff;
    f16 *pwqkv_h, *pwqkv_l, *pwo_h, *pwo_l, *pw1_h, *pw1_l, *pw2_h, *pw2_l;
    f16 *pwout_h, *pwout_l;
    cudaGetSymbolAddress((void**)&px,   g_x);
    cudaGetSymbolAddress((void**)&pqkv, g_qkv);
    cudaGetSymbolAddress((void**)&ph,   g_h);
    cudaGetSymbolAddress((void**)&pat,  g_at);
    cudaGetSymbolAddress((void**)&pff,  g_ff);
    cudaGetSymbolAddress((void**)&pwqkv_h, g_wqkv_h);
    cudaGetSymbolAddress((void**)&pwqkv_l, g_wqkv_l);
    cudaGetSymbolAddress((void**)&pwo_h, g_wo_h);
    cudaGetSymbolAddress((void**)&pwo_l, g_wo_l);
    cudaGetSymbolAddress((void**)&pw1_h, g_w1_h);
    cudaGetSymbolAddress((void**)&pw1_l, g_w1_l);
    cudaGetSymbolAddress((void**)&pw2_h, g_w2_h);
    cudaGetSymbolAddress((void**)&pw2_l, g_w2_l);
    cudaGetSymbolAddress((void**)&pwout_h, g_wout_h);
    cudaGetSymbolAddress((void**)&pwout_l, g_wout_l);

    cudaFuncSetAttribute(attn_f16,
                         cudaFuncAttributeMaxDynamicSharedMemorySize, ATT_SMEM);
    cudaFuncSetAttribute(hgemm<128>,
                         cudaFuncAttributeMaxDynamicSharedMemorySize, SM128);
    cudaFuncSetAttribute(hgemm<64>,
                         cudaFuncAttributeMaxDynamicSharedMemorySize, SM64);

    // ---- weight splitting ----
    int t;
    t = NL * DM * DM / 4;
    wsplit<<<(t + 255) / 256, 256>>>(Wq, pwqkv_h, pwqkv_l, DM, QKVS, 0,      t);
    wsplit<<<(t + 255) / 256, 256>>>(Wk, pwqkv_h, pwqkv_l, DM, QKVS, DM,     t);
    wsplit<<<(t + 255) / 256, 256>>>(Wv, pwqkv_h, pwqkv_l, DM, QKVS, 2 * DM, t);
    wsplit<<<(t + 255) / 256, 256>>>(Wo, pwo_h, pwo_l, DM, DM, 0, t);
    t = NL * DM * DFF / 4;
    wsplit<<<(t + 255) / 256, 256>>>(W1, pw1_h, pw1_l, DFF, DFF, 0, t);
    wsplit<<<(t + 255) / 256, 256>>>(W2, pw2_h, pw2_l, DM, DM, 0, t);
    t = DM * NV / 4;
    wsplit<<<(t + 255) / 256, 256>>>(Wout, pwout_h, pwout_l, NV, NV, 0, t);

    embed_kernel<<<TOK, 256>>>(ctx, tok, pos);

    for (int l = 0; l < NL; l++) {
        size_t oqkv = (size_t)l * DM * QKVS;
        size_t owo  = (size_t)l * DM * DM;
        size_t ow1  = (size_t)l * DM * DFF;
        size_t ow2  = (size_t)l * DFF * DM;

        ln_half<<<TOK, 256>>>(px, ln1g + l * DM, ln1b + l * DM, ph);
        hgemm<128><<<dim3(16, 18), 256, SM128>>>(
            ph, pwqkv_h + oqkv, pwqkv_l + oqkv,
            nullptr, nullptr, nullptr, pqkv, QKVS, DM, 0);
        attn_f16<<<dim3(SEQ / 64, NH, 2), 128, ATT_SMEM>>>(pqkv, pat);
        hgemm<64><<<dim3(32, 6), 256, SM64>>>(
            pat, pwo_h + owo, pwo_l + owo,
            bo + l * DM, px, px, nullptr, DM, DM, 0);
        ln_half<<<TOK, 256>>>(px, ln2g + l * DM, ln2b + l * DM, ph);
        hgemm<128><<<dim3(16, 24), 256, SM128>>>(
            ph, pw1_h + ow1, pw1_l + ow1,
            b1 + (size_t)l * DFF, nullptr, nullptr, pff, DFF, DM, 1);
        hgemm<64><<<dim3(32, 6), 256, SM64>>>(
            pff, pw2_h + ow2, pw2_l + ow2,
            b2 + l * DM, px, px, nullptr, DM, DFF, 0);
    }

    ln_half<<<TOK, 256>>>(px, lnfg, lnfb, ph);
    hgemm<128><<<dim3(16, 250), 256, SM128>>>(
        ph, pwout_h, pwout_l,
        bout, nullptr, (float*)d_out, nullptr, NV, DM, 0);
}

// round 8
// speedup vs baseline: 5.2326x; 1.0974x over previous
#include <cuda_runtime.h>
#include <cuda_fp16.h>
#include <math.h>
#include <stdint.h>

// Problem constants
#define TOK   2048          // B*S
#define SEQ   1024
#define DM    768
#define DFF   3072
#define NH    12
#define HDIM  64
#define NV    32000
#define NL    6
#define QKVS  (3 * DM)      // 2304

typedef __half f16;

// -------------------- scratch (device globals; no allocation allowed) -----
__device__ __align__(16) float g_x  [TOK * DM];
__device__ __align__(16) f16   g_qkv[TOK * QKVS];
__device__ __align__(16) f16   g_h  [TOK * DM];
__device__ __align__(16) f16   g_at [TOK * DM];
__device__ __align__(16) f16   g_ff [TOK * DFF];
// split weights [K,N] fp16 hi/lo
__device__ __align__(16) f16 g_wqkv_h[NL * DM * QKVS];
__device__ __align__(16) f16 g_wqkv_l[NL * DM * QKVS];
__device__ __align__(16) f16 g_wo_h [NL * DM * DM];
__device__ __align__(16) f16 g_wo_l [NL * DM * DM];
__device__ __align__(16) f16 g_w1_h [NL * DM * DFF];
__device__ __align__(16) f16 g_w1_l [NL * DM * DFF];
__device__ __align__(16) f16 g_w2_h [NL * DFF * DM];
__device__ __align__(16) f16 g_w2_l [NL * DFF * DM];
__device__ __align__(16) f16 g_wout_h[DM * NV];

// -------------------- helpers ---------------------------------------------
__device__ __forceinline__ void hsplit(float x, f16& h, f16& l) {
    h = __float2half_rn(x);
    l = __float2half_rn(x - __half2float(h));
}
__device__ __forceinline__ uint32_t cvta_smem(const void* p) {
    return (uint32_t)__cvta_generic_to_shared(p);
}
__device__ __forceinline__ void cp16(uint32_t s, const void* g) {
    asm volatile("cp.async.cg.shared.global [%0], [%1], 16;" :: "r"(s), "l"(g));
}
__device__ __forceinline__ void ldm_x4(uint32_t* r, uint32_t addr) {
    asm volatile("ldmatrix.sync.aligned.m8n8.x4.shared.b16 {%0,%1,%2,%3},[%4];"
                 : "=r"(r[0]), "=r"(r[1]), "=r"(r[2]), "=r"(r[3]) : "r"(addr));
}
__device__ __forceinline__ void ldm_x4_t(uint32_t* r, uint32_t addr) {
    asm volatile("ldmatrix.sync.aligned.m8n8.x4.trans.shared.b16 {%0,%1,%2,%3},[%4];"
                 : "=r"(r[0]), "=r"(r[1]), "=r"(r[2]), "=r"(r[3]) : "r"(addr));
}
__device__ __forceinline__ void mma_f16(float* c, const uint32_t* a, const uint32_t* b) {
    asm volatile(
        "mma.sync.aligned.m16n8k16.row.col.f32.f16.f16.f32 "
        "{%0,%1,%2,%3},{%4,%5,%6,%7},{%8,%9},{%0,%1,%2,%3};"
        : "+f"(c[0]), "+f"(c[1]), "+f"(c[2]), "+f"(c[3])
        : "r"(a[0]), "r"(a[1]), "r"(a[2]), "r"(a[3]), "r"(b[0]), "r"(b[1]));
}
__device__ __forceinline__ uint32_t pack_h2(float a, float b) {
    __half2 h = __floats2half2_rn(a, b);
    return *(uint32_t*)&h;
}

// -------------------- weight split kernels ----------------------------------
// 8 elements per thread, 16B stores to both hi and lo streams.
__global__ void wsplit(const float* __restrict__ src, f16* __restrict__ dh,
                       f16* __restrict__ dl, int cols, int dst_stride,
                       int cofs, int total8) {
    int i = blockIdx.x * 256 + threadIdx.x;
    if (i >= total8) return;
    int e = i * 8;
    int r = e / cols, c = e - r * cols;
    float4 v0 = *(const float4*)(src + (size_t)e);
    float4 v1 = *(const float4*)(src + (size_t)e + 4);
    size_t d = (size_t)r * dst_stride + cofs + c;
    f16 h[8], l[8];
    hsplit(v0.x, h[0], l[0]); hsplit(v0.y, h[1], l[1]);
    hsplit(v0.z, h[2], l[2]); hsplit(v0.w, h[3], l[3]);
    hsplit(v1.x, h[4], l[4]); hsplit(v1.y, h[5], l[5]);
    hsplit(v1.z, h[6], l[6]); hsplit(v1.w, h[7], l[7]);
    *(uint4*)(dh + d) = *(uint4*)h;
    *(uint4*)(dl + d) = *(uint4*)l;
}

// hi-only convert (for Wout; no lo stream)
__global__ void wconv(const float* __restrict__ src, f16* __restrict__ dh,
                      int total8) {
    int i = blockIdx.x * 256 + threadIdx.x;
    if (i >= total8) return;
    size_t e = (size_t)i * 8;
    float4 v0 = *(const float4*)(src + e);
    float4 v1 = *(const float4*)(src + e + 4);
    f16 h[8];
    h[0] = __float2half_rn(v0.x); h[1] = __float2half_rn(v0.y);
    h[2] = __float2half_rn(v0.z); h[3] = __float2half_rn(v0.w);
    h[4] = __float2half_rn(v1.x); h[5] = __float2half_rn(v1.y);
    h[6] = __float2half_rn(v1.z); h[7] = __float2half_rn(v1.w);
    *(uint4*)(dh + e) = *(uint4*)h;
}

// -------------------- embedding -------------------------------------------
__global__ void embed_kernel(const int* __restrict__ ctx,
                             const float* __restrict__ tok,
                             const float* __restrict__ pos) {
    int t = blockIdx.x;
    int token = ctx[t];
    int s = t & (SEQ - 1);
#pragma unroll
    for (int i = 0; i < 3; i++) {
        int d = threadIdx.x + i * 256;
        g_x[t * DM + d] = tok[token * DM + d] + pos[s * DM + d];
    }
}

// -------------------- layernorm -> fp16 ------------------------------------
__global__ void ln_half(const float* __restrict__ in,
                        const float* __restrict__ gg,
                        const float* __restrict__ bb,
                        f16* __restrict__ out) {
    int row = blockIdx.x;
    const float* x = in + row * DM;
    float v[3];
    float s = 0.f, ss = 0.f;
#pragma unroll
    for (int i = 0; i < 3; i++) {
        v[i] = x[threadIdx.x + i * 256];
        s  += v[i];
        ss += v[i] * v[i];
    }
#pragma unroll
    for (int m = 16; m; m >>= 1) {
        s  += __shfl_xor_sync(0xffffffffu, s,  m);
        ss += __shfl_xor_sync(0xffffffffu, ss, m);
    }
    __shared__ float sa[8], sb[8];
    int w = threadIdx.x >> 5, lane = threadIdx.x & 31;
    if (lane == 0) { sa[w] = s; sb[w] = ss; }
    __syncthreads();
    s = 0.f; ss = 0.f;
#pragma unroll
    for (int i = 0; i < 8; i++) { s += sa[i]; ss += sb[i]; }
    float mean = s * (1.0f / DM);
    float var  = ss * (1.0f / DM) - mean * mean;
    float inv  = rsqrtf(var + 1e-5f);
#pragma unroll
    for (int i = 0; i < 3; i++) {
        int d = threadIdx.x + i * 256;
        float y = (v[i] - mean) * inv * gg[d] + bb[d];
        out[row * DM + d] = __float2half_rn(y);
    }
}

// -------------------- fp16 tensor-core GEMM --------------------------------
// C[M,N] = A[M,K] @ B[K,N]; A fp16; B fp16 (SPLIT: hi+lo 2-pass, else 1-pass).
__device__ __forceinline__ uint32_t swzA(int row, int kc) {
    return (uint32_t)(row * 64 + ((kc ^ ((row >> 1) & 3)) << 4));
}
__device__ __forceinline__ uint32_t swzB(int k, int nc) {
    return (uint32_t)(k * 256 + ((((nc & 7) ^ (k & 7)) | (nc & 8)) << 4));
}

template<int BM, bool SPLIT>
__global__ __launch_bounds__(256, 2)
void hgemm(const f16* __restrict__ A,
           const f16* __restrict__ Bh, const f16* __restrict__ Bl,
           const float* __restrict__ bias, const float* __restrict__ res,
           float* __restrict__ C, f16* __restrict__ Oh,
           int N, int K, int relu) {
    constexpr int WM = BM / 2;
    constexpr int MT = WM / 16;
    constexpr int ABYTES = BM * 64;
    constexpr int BBYTES = SPLIT ? 16384 : 8192;
    constexpr int STAGE  = ABYTES + BBYTES;
    constexpr int NA = BM / 64;

    extern __shared__ char smc[];
    uint32_t sbase = cvta_smem(smc);

    int tid  = threadIdx.x;
    int lane = tid & 31;
    int warp = tid >> 5;
    int wm = warp >> 2;
    int wn = warp & 3;
    int g  = lane >> 2;
    int tg = lane & 3;
    int bm = blockIdx.x, bn = blockIdx.y;

    float acc[MT][4][4];
#pragma unroll
    for (int mi = 0; mi < MT; mi++)
#pragma unroll
        for (int ni = 0; ni < 4; ni++)
#pragma unroll
            for (int j = 0; j < 4; j++) acc[mi][ni][j] = 0.f;

#define LOADSTAGE(IT)                                                         \
    {                                                                         \
        int _it = (IT);                                                       \
        uint32_t st = sbase + (_it % 3) * STAGE;                              \
        _Pragma("unroll")                                                     \
        for (int u = 0; u < NA; u++) {                                        \
            int cu = tid + u * 256;                                           \
            int arow = cu >> 2, akc = cu & 3;                                 \
            uint32_t so = st + swzA(arow, akc);                               \
            size_t go = (size_t)(bm * BM + arow) * K + _it * 32 + akc * 8;    \
            cp16(so, A + go);                                                 \
        }                                                                     \
        _Pragma("unroll")                                                     \
        for (int u = 0; u < 2; u++) {                                         \
            int cu = tid + u * 256;                                           \
            int bk = cu >> 4, bnc = cu & 15;                                  \
            uint32_t so = st + ABYTES + swzB(bk, bnc);                        \
            size_t go = (size_t)(_it * 32 + bk) * N + bn * 128 + bnc * 8;     \
            cp16(so, Bh + go);                                                \
            if (SPLIT) cp16(so + 8192, Bl + go);                              \
        }                                                                     \
    }

    int nIter = K >> 5;
    LOADSTAGE(0); asm volatile("cp.async.commit_group;");
    LOADSTAGE(1); asm volatile("cp.async.commit_group;");

    int a_lrow = wm * WM + (lane & 15);
    int a_koff = (lane >> 4) & 1;
    int b_lk   = lane & 15;
    int b_noff = (lane >> 4) & 1;

    for (int it = 0; it < nIter; it++) {
        asm volatile("cp.async.wait_group 1;");
        __syncthreads();
        uint32_t sb = sbase + (it % 3) * STAGE;

#pragma unroll
        for (int k16 = 0; k16 < 2; k16++) {
            uint32_t Af[MT][4], Bf[4][2];
            int kc = k16 * 2 + a_koff;
#pragma unroll
            for (int mi = 0; mi < MT; mi++)
                ldm_x4(Af[mi], sb + swzA(a_lrow + mi * 16, kc));
            int kk = k16 * 16 + b_lk;
#pragma unroll
            for (int p = 0; p < 2; p++) {
                uint32_t r4[4];
                ldm_x4_t(r4, sb + ABYTES + swzB(kk, wn * 4 + p * 2 + b_noff));
                Bf[p*2][0] = r4[0]; Bf[p*2][1] = r4[1];
                Bf[p*2+1][0] = r4[2]; Bf[p*2+1][1] = r4[3];
            }
#pragma unroll
            for (int mi = 0; mi < MT; mi++)
#pragma unroll
                for (int ni = 0; ni < 4; ni++) mma_f16(acc[mi][ni], Af[mi], Bf[ni]);
            if (SPLIT) {
#pragma unroll
                for (int p = 0; p < 2; p++) {
                    uint32_t r4[4];
                    ldm_x4_t(r4, sb + ABYTES + 8192 + swzB(kk, wn * 4 + p * 2 + b_noff));
                    Bf[p*2][0] = r4[0]; Bf[p*2][1] = r4[1];
                    Bf[p*2+1][0] = r4[2]; Bf[p*2+1][1] = r4[3];
                }
#pragma unroll
                for (int mi = 0; mi < MT; mi++)
#pragma unroll
                    for (int ni = 0; ni < 4; ni++) mma_f16(acc[mi][ni], Af[mi], Bf[ni]);
            }
        }

        if (it + 2 < nIter) LOADSTAGE(it + 2);
        asm volatile("cp.async.commit_group;");
    }
#undef LOADSTAGE

#pragma unroll
    for (int mi = 0; mi < MT; mi++) {
        int row0 = bm * BM + wm * WM + mi * 16 + g;
#pragma unroll
        for (int ni = 0; ni < 4; ni++) {
            int col = bn * 128 + wn * 32 + ni * 8 + 2 * tg;
            float b0 = 0.f, b1 = 0.f;
            if (bias) { b0 = bias[col]; b1 = bias[col + 1]; }
#pragma unroll
            for (int half = 0; half < 2; half++) {
                int row = row0 + half * 8;
                float v0 = acc[mi][ni][half * 2 + 0] + b0;
                float v1 = acc[mi][ni][half * 2 + 1] + b1;
                if (relu) { v0 = fmaxf(v0, 0.f); v1 = fmaxf(v1, 0.f); }
                size_t idx = (size_t)row * N + col;
                if (Oh) {
                    *(__half2*)(Oh + idx) =
                        __half2(__float2half_rn(v0), __float2half_rn(v1));
                } else {
                    if (res) {
                        float2 r2 = *(const float2*)(res + idx);
                        v0 += r2.x; v1 += r2.y;
                    }
                    *(float2*)(C + idx) = make_float2(v0, v1);
                }
            }
        }
    }
}

// -------------------- fp16 tensor-core flash attention ----------------------
#define AQ_BYTES 8192
#define AKV_STAGE 16384
#define ATT_SMEM (AQ_BYTES + 3 * AKV_STAGE)

__device__ __forceinline__ uint32_t swzR(int row, int c) {   // 128B rows
    return (uint32_t)(row * 128 + ((c ^ (row & 7)) << 4));
}

__global__ __launch_bounds__(128)
void attn_f16(const f16* __restrict__ QKV, f16* __restrict__ O) {
    extern __shared__ char smc[];
    uint32_t sb = cvta_smem(smc);

    int qt = blockIdx.x, h = blockIdx.y, b = blockIdx.z;
    int tid = threadIdx.x, lane = tid & 31, warp = tid >> 5;
    int g = lane >> 2, tg = lane & 3;
    int wrow = warp * 16;
    int nT = qt + 1;

    const f16* Qg = QKV + (size_t)(b * SEQ + qt * 64) * QKVS + h * HDIM;

#define LOADQ()                                                               \
    {                                                                         \
        _Pragma("unroll")                                                     \
        for (int u = 0; u < 4; u++) {                                         \
            int idx = tid + u * 128;                                          \
            int row = idx >> 3, c = idx & 7;                                  \
            cp16(sb + swzR(row, c), Qg + (size_t)row * QKVS + c * 8);         \
        }                                                                     \
    }
#define LOADKV(SLOT, KT)                                                      \
    {                                                                         \
        uint32_t st = sb + AQ_BYTES + ((SLOT) % 3) * AKV_STAGE;               \
        const f16* Kg = QKV + (size_t)(b * SEQ + (KT) * 64) * QKVS            \
                        + DM + h * HDIM;                                      \
        _Pragma("unroll")                                                     \
        for (int u = 0; u < 4; u++) {                                         \
            int idx = tid + u * 128;                                          \
            int row = idx >> 3, c = idx & 7;                                  \
            uint32_t so = st + swzR(row, c);                                  \
            size_t go = (size_t)row * QKVS + c * 8;                           \
            cp16(so, Kg + go);                                                \
            cp16(so + 8192, Kg + DM + go);                                    \
        }                                                                     \
    }

    LOADQ(); LOADKV(0, 0);
    asm volatile("cp.async.commit_group;");
    if (1 < nT) LOADKV(1, 1);
    asm volatile("cp.async.commit_group;");

    float o[8][4];
#pragma unroll
    for (int nt = 0; nt < 8; nt++)
#pragma unroll
        for (int j = 0; j < 4; j++) o[nt][j] = 0.f;
    float m[2] = {-INFINITY, -INFINITY}, l[2] = {0.f, 0.f};
    uint32_t qf[4][4];

    for (int kt = 0; kt < nT; kt++) {
        asm volatile("cp.async.wait_group 1;");
        __syncthreads();

        if (kt == 0) {
#pragma unroll
            for (int i = 0; i < 4; i++) {
                int row = wrow + (lane & 15);
                int c = 2 * i + (lane >> 4);
                ldm_x4(qf[i], sb + swzR(row, c));
            }
        }

        if (kt + 2 < nT) LOADKV(kt + 2, kt + 2);
        asm volatile("cp.async.commit_group;");

        uint32_t kb = sb + AQ_BYTES + (kt % 3) * AKV_STAGE;
        float s[8][4];
#pragma unroll
        for (int nt = 0; nt < 8; nt++)
#pragma unroll
            for (int j = 0; j < 4; j++) s[nt][j] = 0.f;

#pragma unroll
        for (int ntp = 0; ntp < 4; ntp++) {
            int krow = ntp * 16 + (lane & 7) + ((lane >> 4) << 3);
#pragma unroll
            for (int i = 0; i < 4; i++) {
                uint32_t r4[4];
                int c = 2 * i + ((lane >> 3) & 1);
                ldm_x4(r4, kb + swzR(krow, c));
                mma_f16(s[2 * ntp],     qf[i], r4);
                mma_f16(s[2 * ntp + 1], qf[i], r4 + 2);
            }
        }

#pragma unroll
        for (int nt = 0; nt < 8; nt++)
#pragma unroll
            for (int j = 0; j < 4; j++) s[nt][j] *= 0.125f;
        if (kt == qt) {
            int rA = wrow + g, rB = rA + 8;
#pragma unroll
            for (int nt = 0; nt < 8; nt++) {
                int cc = nt * 8 + 2 * tg;
                if (cc     > rA) s[nt][0] = -1e30f;
                if (cc + 1 > rA) s[nt][1] = -1e30f;
                if (cc     > rB) s[nt][2] = -1e30f;
                if (cc + 1 > rB) s[nt][3] = -1e30f;
            }
        }

        float mxA = -1e30f, mxB = -1e30f;
#pragma unroll
        for (int nt = 0; nt < 8; nt++) {
            mxA = fmaxf(mxA, fmaxf(s[nt][0], s[nt][1]));
            mxB = fmaxf(mxB, fmaxf(s[nt][2], s[nt][3]));
        }
        mxA = fmaxf(mxA, __shfl_xor_sync(0xffffffffu, mxA, 1));
        mxA = fmaxf(mxA, __shfl_xor_sync(0xffffffffu, mxA, 2));
        mxB = fmaxf(mxB, __shfl_xor_sync(0xffffffffu, mxB, 1));
        mxB = fmaxf(mxB, __shfl_xor_sync(0xffffffffu, mxB, 2));
        float mnA = fmaxf(m[0], mxA), mnB = fmaxf(m[1], mxB);
        float fA = __expf(m[0] - mnA), fB = __expf(m[1] - mnB);
        float sA = 0.f, sB = 0.f;
#pragma unroll
        for (int nt = 0; nt < 8; nt++) {
            s[nt][0] = __expf(s[nt][0] - mnA);
            s[nt][1] = __expf(s[nt][1] - mnA);
            s[nt][2] = __expf(s[nt][2] - mnB);
            s[nt][3] = __expf(s[nt][3] - mnB);
            sA += s[nt][0] + s[nt][1];
            sB += s[nt][2] + s[nt][3];
        }
        sA += __shfl_xor_sync(0xffffffffu, sA, 1);
        sA += __shfl_xor_sync(0xffffffffu, sA, 2);
        sB += __shfl_xor_sync(0xffffffffu, sB, 1);
        sB += __shfl_xor_sync(0xffffffffu, sB, 2);
        l[0] = l[0] * fA + sA; m[0] = mnA;
        l[1] = l[1] * fB + sB; m[1] = mnB;
#pragma unroll
        for (int nt = 0; nt < 8; nt++) {
            o[nt][0] *= fA; o[nt][1] *= fA;
            o[nt][2] *= fB; o[nt][3] *= fB;
        }

        uint32_t pk[4][4];
#pragma unroll
        for (int i = 0; i < 4; i++) {
            pk[i][0] = pack_h2(s[2*i][0],   s[2*i][1]);
            pk[i][1] = pack_h2(s[2*i][2],   s[2*i][3]);
            pk[i][2] = pack_h2(s[2*i+1][0], s[2*i+1][1]);
            pk[i][3] = pack_h2(s[2*i+1][2], s[2*i+1][3]);
        }

        uint32_t vb = kb + 8192;
#pragma unroll
        for (int i = 0; i < 4; i++) {
            int vrow = i * 16 + (lane & 15);
#pragma unroll
            for (int hdp = 0; hdp < 4; hdp++) {
                uint32_t r4[4];
                int c = 2 * hdp + (lane >> 4);
                ldm_x4_t(r4, vb + swzR(vrow, c));
                mma_f16(o[2 * hdp],     pk[i], r4);
                mma_f16(o[2 * hdp + 1], pk[i], r4 + 2);
            }
        }
    }
#undef LOADQ
#undef LOADKV

    float iA = 1.f / l[0], iB = 1.f / l[1];
    size_t rowA = (size_t)(b * SEQ + qt * 64 + wrow + g);
    f16* oA = O + rowA * DM + h * HDIM;
    f16* oB = oA + (size_t)8 * DM;
#pragma unroll
    for (int nt = 0; nt < 8; nt++) {
        int cc = nt * 8 + 2 * tg;
        *(__half2*)(oA + cc) = __floats2half2_rn(o[nt][0] * iA, o[nt][1] * iA);
        *(__half2*)(oB + cc) = __floats2half2_rn(o[nt][2] * iB, o[nt][3] * iB);
    }
}

// -------------------- host orchestration ----------------------------------
#define SM128S (3 * (128 * 64 + 16384))   // 73728 (split)
#define SM64S  (3 * (64 * 64 + 16384))    // 61440 (split)
#define SM128N (3 * (128 * 64 + 8192))    // 49152 (no split)

extern "C" void kernel_launch(void* const* d_in, const int* in_sizes, int n_in,
                              void* d_out, int out_size) {
    const int*   ctx  = (const int*)  d_in[0];
    const float* tok  = (const float*)d_in[1];
    const float* pos  = (const float*)d_in[2];
    const float* Wq   = (const float*)d_in[3];
    const float* Wk   = (const float*)d_in[4];
    const float* Wv   = (const float*)d_in[5];
    const float* Wo   = (const float*)d_in[6];
    const float* bo   = (const float*)d_in[7];
    const float* ln1g = (const float*)d_in[8];
    const float* ln1b = (const float*)d_in[9];
    const float* W1   = (const float*)d_in[10];
    const float* b1   = (const float*)d_in[11];
    const float* W2   = (const float*)d_in[12];
    const float* b2   = (const float*)d_in[13];
    const float* ln2g = (const float*)d_in[14];
    const float* ln2b = (const float*)d_in[15];
    const float* lnfg = (const float*)d_in[16];
    const float* lnfb = (const float*)d_in[17];
    const float* Wout = (const float*)d_in[18];
    const float* bout = (const float*)d_in[19];

    float* px;
    f16 *pqkv, *ph, *pat, *pff;
    f16 *pwqkv_h, *pwqkv_l, *pwo_h, *pwo_l, *pw1_h, *pw1_l, *pw2_h, *pw2_l;
    f16 *pwout_h;
    cudaGetSymbolAddress((void**)&px,   g_x);
    cudaGetSymbolAddress((void**)&pqkv, g_qkv);
    cudaGetSymbolAddress((void**)&ph,   g_h);
    cudaGetSymbolAddress((void**)&pat,  g_at);
    cudaGetSymbolAddress((void**)&pff,  g_ff);
    cudaGetSymbolAddress((void**)&pwqkv_h, g_wqkv_h);
    cudaGetSymbolAddress((void**)&pwqkv_l, g_wqkv_l);
    cudaGetSymbolAddress((void**)&pwo_h, g_wo_h);
    cudaGetSymbolAddress((void**)&pwo_l, g_wo_l);
    cudaGetSymbolAddress((void**)&pw1_h, g_w1_h);
    cudaGetSymbolAddress((void**)&pw1_l, g_w1_l);
    cudaGetSymbolAddress((void**)&pw2_h, g_w2_h);
    cudaGetSymbolAddress((void**)&pw2_l, g_w2_l);
    cudaGetSymbolAddress((void**)&pwout_h, g_wout_h);

    cudaFuncSetAttribute(attn_f16,
                         cudaFuncAttributeMaxDynamicSharedMemorySize, ATT_SMEM);
    cudaFuncSetAttribute((const void*)hgemm<128, true>,
                         cudaFuncAttributeMaxDynamicSharedMemorySize, SM128S);
    cudaFuncSetAttribute((const void*)hgemm<64, true>,
                         cudaFuncAttributeMaxDynamicSharedMemorySize, SM64S);
    cudaFuncSetAttribute((const void*)hgemm<128, false>,
                         cudaFuncAttributeMaxDynamicSharedMemorySize, SM128N);

    // ---- weight splitting ----
    int t;
    t = NL * DM * DM / 8;
    wsplit<<<(t + 255) / 256, 256>>>(Wq, pwqkv_h, pwqkv_l, DM, QKVS, 0,      t);
    wsplit<<<(t + 255) / 256, 256>>>(Wk, pwqkv_h, pwqkv_l, DM, QKVS, DM,     t);
    wsplit<<<(t + 255) / 256, 256>>>(Wv, pwqkv_h, pwqkv_l, DM, QKVS, 2 * DM, t);
    wsplit<<<(t + 255) / 256, 256>>>(Wo, pwo_h, pwo_l, DM, DM, 0, t);
    t = NL * DM * DFF / 8;
    wsplit<<<(t + 255) / 256, 256>>>(W1, pw1_h, pw1_l, DFF, DFF, 0, t);
    wsplit<<<(t + 255) / 256, 256>>>(W2, pw2_h, pw2_l, DM, DM, 0, t);
    t = DM * NV / 8;
    wconv<<<(t + 255) / 256, 256>>>(Wout, pwout_h, t);

    embed_kernel<<<TOK, 256>>>(ctx, tok, pos);

    for (int l = 0; l < NL; l++) {
        size_t oqkv = (size_t)l * DM * QKVS;
        size_t owo  = (size_t)l * DM * DM;
        size_t ow1  = (size_t)l * DM * DFF;
        size_t ow2  = (size_t)l * DFF * DM;

        ln_half<<<TOK, 256>>>(px, ln1g + l * DM, ln1b + l * DM, ph);
        hgemm<128, true><<<dim3(16, 18), 256, SM128S>>>(
            ph, pwqkv_h + oqkv, pwqkv_l + oqkv,
            nullptr, nullptr, nullptr, pqkv, QKVS, DM, 0);
        attn_f16<<<dim3(SEQ / 64, NH, 2), 128, ATT_SMEM>>>(pqkv, pat);
        hgemm<64, true><<<dim3(32, 6), 256, SM64S>>>(
            pat, pwo_h + owo, pwo_l + owo,
            bo + l * DM, px, px, nullptr, DM, DM, 0);
        ln_half<<<TOK, 256>>>(px, ln2g + l * DM, ln2b + l * DM, ph);
        hgemm<128, true><<<dim3(16, 24), 256, SM128S>>>(
            ph, pw1_h + ow1, pw1_l + ow1,
            b1 + (size_t)l * DFF, nullptr, nullptr, pff, DFF, DM, 1);
        hgemm<64, true><<<dim3(32, 6), 256, SM64S>>>(
            pff, pw2_h + ow2, pw2_l + ow2,
            b2 + l * DM, px, px, nullptr, DM, DFF, 0);
    }

    ln_half<<<TOK, 256>>>(px, lnfg, lnfb, ph);
    hgemm<128, false><<<dim3(16, 250), 256, SM128N>>>(
        ph, pwout_h, nullptr,
        bout, nullptr, (float*)d_out, nullptr, NV, DM, 0);
}

// round 9
// speedup vs baseline: 6.7881x; 1.2973x over previous
#include <cuda_runtime.h>
#include <cuda_fp16.h>
#include <math.h>
#include <stdint.h>

// Problem constants
#define TOK   2048          // B*S
#define SEQ   1024
#define DM    768
#define DFF   3072
#define NH    12
#define HDIM  64
#define NV    32000
#define NL    6
#define QKVS  (3 * DM)      // 2304

typedef __half f16;

// -------------------- scratch (device globals; no allocation allowed) -----
__device__ __align__(16) float g_x  [TOK * DM];
__device__ __align__(16) f16   g_qkv[TOK * QKVS];
__device__ __align__(16) f16   g_h  [TOK * DM];
__device__ __align__(16) f16   g_at [TOK * DM];
__device__ __align__(16) f16   g_ff [TOK * DFF];
// converted weights [K,N] fp16
__device__ __align__(16) f16 g_wqkv[NL * DM * QKVS];
__device__ __align__(16) f16 g_wo  [NL * DM * DM];
__device__ __align__(16) f16 g_w1  [NL * DM * DFF];
__device__ __align__(16) f16 g_w2  [NL * DFF * DM];
__device__ __align__(16) f16 g_wout[DM * NV];

// -------------------- helpers ---------------------------------------------
__device__ __forceinline__ uint32_t cvta_smem(const void* p) {
    return (uint32_t)__cvta_generic_to_shared(p);
}
__device__ __forceinline__ void cp16(uint32_t s, const void* g) {
    asm volatile("cp.async.cg.shared.global [%0], [%1], 16;" :: "r"(s), "l"(g));
}
__device__ __forceinline__ void ldm_x4(uint32_t* r, uint32_t addr) {
    asm volatile("ldmatrix.sync.aligned.m8n8.x4.shared.b16 {%0,%1,%2,%3},[%4];"
                 : "=r"(r[0]), "=r"(r[1]), "=r"(r[2]), "=r"(r[3]) : "r"(addr));
}
__device__ __forceinline__ void ldm_x4_t(uint32_t* r, uint32_t addr) {
    asm volatile("ldmatrix.sync.aligned.m8n8.x4.trans.shared.b16 {%0,%1,%2,%3},[%4];"
                 : "=r"(r[0]), "=r"(r[1]), "=r"(r[2]), "=r"(r[3]) : "r"(addr));
}
__device__ __forceinline__ void mma_f16(float* c, const uint32_t* a, const uint32_t* b) {
    asm volatile(
        "mma.sync.aligned.m16n8k16.row.col.f32.f16.f16.f32 "
        "{%0,%1,%2,%3},{%4,%5,%6,%7},{%8,%9},{%0,%1,%2,%3};"
        : "+f"(c[0]), "+f"(c[1]), "+f"(c[2]), "+f"(c[3])
        : "r"(a[0]), "r"(a[1]), "r"(a[2]), "r"(a[3]), "r"(b[0]), "r"(b[1]));
}
__device__ __forceinline__ uint32_t pack_h2(float a, float b) {
    __half2 h = __floats2half2_rn(a, b);
    return *(uint32_t*)&h;
}

// -------------------- weight convert kernel ---------------------------------
// src [R, cols] fp32 -> dh [R, dst_stride] fp16 at column offset cofs
__global__ void wconv(const float* __restrict__ src, f16* __restrict__ dh,
                      int cols, int dst_stride, int cofs, int total8) {
    int i = blockIdx.x * 256 + threadIdx.x;
    if (i >= total8) return;
    size_t e = (size_t)i * 8;
    int r = (int)(e / cols), c = (int)(e - (size_t)r * cols);
    float4 v0 = *(const float4*)(src + e);
    float4 v1 = *(const float4*)(src + e + 4);
    size_t d = (size_t)r * dst_stride + cofs + c;
    f16 h[8];
    h[0] = __float2half_rn(v0.x); h[1] = __float2half_rn(v0.y);
    h[2] = __float2half_rn(v0.z); h[3] = __float2half_rn(v0.w);
    h[4] = __float2half_rn(v1.x); h[5] = __float2half_rn(v1.y);
    h[6] = __float2half_rn(v1.z); h[7] = __float2half_rn(v1.w);
    *(uint4*)(dh + d) = *(uint4*)h;
}

// -------------------- embedding -------------------------------------------
__global__ void embed_kernel(const int* __restrict__ ctx,
                             const float* __restrict__ tok,
                             const float* __restrict__ pos) {
    int t = blockIdx.x;
    int token = ctx[t];
    int s = t & (SEQ - 1);
#pragma unroll
    for (int i = 0; i < 3; i++) {
        int d = threadIdx.x + i * 256;
        g_x[t * DM + d] = tok[token * DM + d] + pos[s * DM + d];
    }
}

// -------------------- layernorm -> fp16 ------------------------------------
__global__ void ln_half(const float* __restrict__ in,
                        const float* __restrict__ gg,
                        const float* __restrict__ bb,
                        f16* __restrict__ out) {
    int row = blockIdx.x;
    const float* x = in + row * DM;
    float v[3];
    float s = 0.f, ss = 0.f;
#pragma unroll
    for (int i = 0; i < 3; i++) {
        v[i] = x[threadIdx.x + i * 256];
        s  += v[i];
        ss += v[i] * v[i];
    }
#pragma unroll
    for (int m = 16; m; m >>= 1) {
        s  += __shfl_xor_sync(0xffffffffu, s,  m);
        ss += __shfl_xor_sync(0xffffffffu, ss, m);
    }
    __shared__ float sa[8], sb[8];
    int w = threadIdx.x >> 5, lane = threadIdx.x & 31;
    if (lane == 0) { sa[w] = s; sb[w] = ss; }
    __syncthreads();
    s = 0.f; ss = 0.f;
#pragma unroll
    for (int i = 0; i < 8; i++) { s += sa[i]; ss += sb[i]; }
    float mean = s * (1.0f / DM);
    float var  = ss * (1.0f / DM) - mean * mean;
    float inv  = rsqrtf(var + 1e-5f);
#pragma unroll
    for (int i = 0; i < 3; i++) {
        int d = threadIdx.x + i * 256;
        float y = (v[i] - mean) * inv * gg[d] + bb[d];
        out[row * DM + d] = __float2half_rn(y);
    }
}

// -------------------- fp16 tensor-core GEMM (single-pass) -------------------
__device__ __forceinline__ uint32_t swzA(int row, int kc) {
    return (uint32_t)(row * 64 + ((kc ^ ((row >> 1) & 3)) << 4));
}
__device__ __forceinline__ uint32_t swzB(int k, int nc) {
    return (uint32_t)(k * 256 + ((((nc & 7) ^ (k & 7)) | (nc & 8)) << 4));
}

template<int BM>
__global__ __launch_bounds__(256, 2)
void hgemm(const f16* __restrict__ A, const f16* __restrict__ B,
           const float* __restrict__ bias, const float* __restrict__ res,
           float* __restrict__ C, f16* __restrict__ Oh,
           int N, int K, int relu) {
    constexpr int WM = BM / 2;
    constexpr int MT = WM / 16;
    constexpr int ABYTES = BM * 64;
    constexpr int STAGE  = ABYTES + 8192;
    constexpr int NA = BM / 64;

    extern __shared__ char smc[];
    uint32_t sbase = cvta_smem(smc);

    int tid  = threadIdx.x;
    int lane = tid & 31;
    int warp = tid >> 5;
    int wm = warp >> 2;
    int wn = warp & 3;
    int g  = lane >> 2;
    int tg = lane & 3;
    int bm = blockIdx.x, bn = blockIdx.y;

    float acc[MT][4][4];
#pragma unroll
    for (int mi = 0; mi < MT; mi++)
#pragma unroll
        for (int ni = 0; ni < 4; ni++)
#pragma unroll
            for (int j = 0; j < 4; j++) acc[mi][ni][j] = 0.f;

#define LOADSTAGE(IT)                                                         \
    {                                                                         \
        int _it = (IT);                                                       \
        uint32_t st = sbase + (_it % 3) * STAGE;                              \
        _Pragma("unroll")                                                     \
        for (int u = 0; u < NA; u++) {                                        \
            int cu = tid + u * 256;                                           \
            int arow = cu >> 2, akc = cu & 3;                                 \
            uint32_t so = st + swzA(arow, akc);                               \
            size_t go = (size_t)(bm * BM + arow) * K + _it * 32 + akc * 8;    \
            cp16(so, A + go);                                                 \
        }                                                                     \
        _Pragma("unroll")                                                     \
        for (int u = 0; u < 2; u++) {                                         \
            int cu = tid + u * 256;                                           \
            int bk = cu >> 4, bnc = cu & 15;                                  \
            uint32_t so = st + ABYTES + swzB(bk, bnc);                        \
            size_t go = (size_t)(_it * 32 + bk) * N + bn * 128 + bnc * 8;     \
            cp16(so, B + go);                                                 \
        }                                                                     \
    }

    int nIter = K >> 5;
    LOADSTAGE(0); asm volatile("cp.async.commit_group;");
    LOADSTAGE(1); asm volatile("cp.async.commit_group;");

    int a_lrow = wm * WM + (lane & 15);
    int a_koff = (lane >> 4) & 1;
    int b_lk   = lane & 15;
    int b_noff = (lane >> 4) & 1;

    for (int it = 0; it < nIter; it++) {
        asm volatile("cp.async.wait_group 1;");
        __syncthreads();
        uint32_t sb = sbase + (it % 3) * STAGE;

#pragma unroll
        for (int k16 = 0; k16 < 2; k16++) {
            uint32_t Af[MT][4], Bf[4][2];
            int kc = k16 * 2 + a_koff;
#pragma unroll
            for (int mi = 0; mi < MT; mi++)
                ldm_x4(Af[mi], sb + swzA(a_lrow + mi * 16, kc));
            int kk = k16 * 16 + b_lk;
#pragma unroll
            for (int p = 0; p < 2; p++) {
                uint32_t r4[4];
                ldm_x4_t(r4, sb + ABYTES + swzB(kk, wn * 4 + p * 2 + b_noff));
                Bf[p*2][0] = r4[0]; Bf[p*2][1] = r4[1];
                Bf[p*2+1][0] = r4[2]; Bf[p*2+1][1] = r4[3];
            }
#pragma unroll
            for (int mi = 0; mi < MT; mi++)
#pragma unroll
                for (int ni = 0; ni < 4; ni++) mma_f16(acc[mi][ni], Af[mi], Bf[ni]);
        }

        if (it + 2 < nIter) LOADSTAGE(it + 2);
        asm volatile("cp.async.commit_group;");
    }
#undef LOADSTAGE

#pragma unroll
    for (int mi = 0; mi < MT; mi++) {
        int row0 = bm * BM + wm * WM + mi * 16 + g;
#pragma unroll
        for (int ni = 0; ni < 4; ni++) {
            int col = bn * 128 + wn * 32 + ni * 8 + 2 * tg;
            float b0 = 0.f, b1 = 0.f;
            if (bias) { b0 = bias[col]; b1 = bias[col + 1]; }
#pragma unroll
            for (int half = 0; half < 2; half++) {
                int row = row0 + half * 8;
                float v0 = acc[mi][ni][half * 2 + 0] + b0;
                float v1 = acc[mi][ni][half * 2 + 1] + b1;
                if (relu) { v0 = fmaxf(v0, 0.f); v1 = fmaxf(v1, 0.f); }
                size_t idx = (size_t)row * N + col;
                if (Oh) {
                    *(__half2*)(Oh + idx) =
                        __half2(__float2half_rn(v0), __float2half_rn(v1));
                } else {
                    if (res) {
                        float2 r2 = *(const float2*)(res + idx);
                        v0 += r2.x; v1 += r2.y;
                    }
                    *(float2*)(C + idx) = make_float2(v0, v1);
                }
            }
        }
    }
}

// -------------------- fp16 tensor-core flash attention ----------------------
#define AQ_BYTES 8192
#define AKV_STAGE 16384
#define ATT_SMEM (AQ_BYTES + 3 * AKV_STAGE)

__device__ __forceinline__ uint32_t swzR(int row, int c) {   // 128B rows
    return (uint32_t)(row * 128 + ((c ^ (row & 7)) << 4));
}

__global__ __launch_bounds__(128)
void attn_f16(const f16* __restrict__ QKV, f16* __restrict__ O) {
    extern __shared__ char smc[];
    uint32_t sb = cvta_smem(smc);

    int qt = blockIdx.x, h = blockIdx.y, b = blockIdx.z;
    int tid = threadIdx.x, lane = tid & 31, warp = tid >> 5;
    int g = lane >> 2, tg = lane & 3;
    int wrow = warp * 16;
    int nT = qt + 1;

    const f16* Qg = QKV + (size_t)(b * SEQ + qt * 64) * QKVS + h * HDIM;

#define LOADQ()                                                               \
    {                                                                         \
        _Pragma("unroll")                                                     \
        for (int u = 0; u < 4; u++) {                                         \
            int idx = tid + u * 128;                                          \
            int row = idx >> 3, c = idx & 7;                                  \
            cp16(sb + swzR(row, c), Qg + (size_t)row * QKVS + c * 8);         \
        }                                                                     \
    }
#define LOADKV(SLOT, KT)                                                      \
    {                                                                         \
        uint32_t st = sb + AQ_BYTES + ((SLOT) % 3) * AKV_STAGE;               \
        const f16* Kg = QKV + (size_t)(b * SEQ + (KT) * 64) * QKVS            \
                        + DM + h * HDIM;                                      \
        _Pragma("unroll")                                                     \
        for (int u = 0; u < 4; u++) {                                         \
            int idx = tid + u * 128;                                          \
            int row = idx >> 3, c = idx & 7;                                  \
            uint32_t so = st + swzR(row, c);                                  \
            size_t go = (size_t)row * QKVS + c * 8;                           \
            cp16(so, Kg + go);                                                \
            cp16(so + 8192, Kg + DM + go);                                    \
        }                                                                     \
    }

    LOADQ(); LOADKV(0, 0);
    asm volatile("cp.async.commit_group;");
    if (1 < nT) LOADKV(1, 1);
    asm volatile("cp.async.commit_group;");

    float o[8][4];
#pragma unroll
    for (int nt = 0; nt < 8; nt++)
#pragma unroll
        for (int j = 0; j < 4; j++) o[nt][j] = 0.f;
    float m[2] = {-INFINITY, -INFINITY}, l[2] = {0.f, 0.f};
    uint32_t qf[4][4];

    for (int kt = 0; kt < nT; kt++) {
        asm volatile("cp.async.wait_group 1;");
        __syncthreads();

        if (kt == 0) {
#pragma unroll
            for (int i = 0; i < 4; i++) {
                int row = wrow + (lane & 15);
                int c = 2 * i + (lane >> 4);
                ldm_x4(qf[i], sb + swzR(row, c));
            }
        }

        if (kt + 2 < nT) LOADKV(kt + 2, kt + 2);
        asm volatile("cp.async.commit_group;");

        uint32_t kb = sb + AQ_BYTES + (kt % 3) * AKV_STAGE;
        float s[8][4];
#pragma unroll
        for (int nt = 0; nt < 8; nt++)
#pragma unroll
            for (int j = 0; j < 4; j++) s[nt][j] = 0.f;

#pragma unroll
        for (int ntp = 0; ntp < 4; ntp++) {
            int krow = ntp * 16 + (lane & 7) + ((lane >> 4) << 3);
#pragma unroll
            for (int i = 0; i < 4; i++) {
                uint32_t r4[4];
                int c = 2 * i + ((lane >> 3) & 1);
                ldm_x4(r4, kb + swzR(krow, c));
                mma_f16(s[2 * ntp],     qf[i], r4);
                mma_f16(s[2 * ntp + 1], qf[i], r4 + 2);
            }
        }

#pragma unroll
        for (int nt = 0; nt < 8; nt++)
#pragma unroll
            for (int j = 0; j < 4; j++) s[nt][j] *= 0.125f;
        if (kt == qt) {
            int rA = wrow + g, rB = rA + 8;
#pragma unroll
            for (int nt = 0; nt < 8; nt++) {
                int cc = nt * 8 + 2 * tg;
                if (cc     > rA) s[nt][0] = -1e30f;
                if (cc + 1 > rA) s[nt][1] = -1e30f;
                if (cc     > rB) s[nt][2] = -1e30f;
                if (cc + 1 > rB) s[nt][3] = -1e30f;
            }
        }

        float mxA = -1e30f, mxB = -1e30f;
#pragma unroll
        for (int nt = 0; nt < 8; nt++) {
            mxA = fmaxf(mxA, fmaxf(s[nt][0], s[nt][1]));
            mxB = fmaxf(mxB, fmaxf(s[nt][2], s[nt][3]));
        }
        mxA = fmaxf(mxA, __shfl_xor_sync(0xffffffffu, mxA, 1));
        mxA = fmaxf(mxA, __shfl_xor_sync(0xffffffffu, mxA, 2));
        mxB = fmaxf(mxB, __shfl_xor_sync(0xffffffffu, mxB, 1));
        mxB = fmaxf(mxB, __shfl_xor_sync(0xffffffffu, mxB, 2));
        float mnA = fmaxf(m[0], mxA), mnB = fmaxf(m[1], mxB);
        float fA = __expf(m[0] - mnA), fB = __expf(m[1] - mnB);
        float sA = 0.f, sB = 0.f;
#pragma unroll
        for (int nt = 0; nt < 8; nt++) {
            s[nt][0] = __expf(s[nt][0] - mnA);
            s[nt][1] = __expf(s[nt][1] - mnA);
            s[nt][2] = __expf(s[nt][2] - mnB);
            s[nt][3] = __expf(s[nt][3] - mnB);
            sA += s[nt][0] + s[nt][1];
            sB += s[nt][2] + s[nt][3];
        }
        sA += __shfl_xor_sync(0xffffffffu, sA, 1);
        sA += __shfl_xor_sync(0xffffffffu, sA, 2);
        sB += __shfl_xor_sync(0xffffffffu, sB, 1);
        sB += __shfl_xor_sync(0xffffffffu, sB, 2);
        l[0] = l[0] * fA + sA; m[0] = mnA;
        l[1] = l[1] * fB + sB; m[1] = mnB;
#pragma unroll
        for (int nt = 0; nt < 8; nt++) {
            o[nt][0] *= fA; o[nt][1] *= fA;
            o[nt][2] *= fB; o[nt][3] *= fB;
        }

        uint32_t pk[4][4];
#pragma unroll
        for (int i = 0; i < 4; i++) {
            pk[i][0] = pack_h2(s[2*i][0],   s[2*i][1]);
            pk[i][1] = pack_h2(s[2*i][2],   s[2*i][3]);
            pk[i][2] = pack_h2(s[2*i+1][0], s[2*i+1][1]);
            pk[i][3] = pack_h2(s[2*i+1][2], s[2*i+1][3]);
        }

        uint32_t vb = kb + 8192;
#pragma unroll
        for (int i = 0; i < 4; i++) {
            int vrow = i * 16 + (lane & 15);
#pragma unroll
            for (int hdp = 0; hdp < 4; hdp++) {
                uint32_t r4[4];
                int c = 2 * hdp + (lane >> 4);
                ldm_x4_t(r4, vb + swzR(vrow, c));
                mma_f16(o[2 * hdp],     pk[i], r4);
                mma_f16(o[2 * hdp + 1], pk[i], r4 + 2);
            }
        }
    }
#undef LOADQ
#undef LOADKV

    float iA = 1.f / l[0], iB = 1.f / l[1];
    size_t rowA = (size_t)(b * SEQ + qt * 64 + wrow + g);
    f16* oA = O + rowA * DM + h * HDIM;
    f16* oB = oA + (size_t)8 * DM;
#pragma unroll
    for (int nt = 0; nt < 8; nt++) {
        int cc = nt * 8 + 2 * tg;
        *(__half2*)(oA + cc) = __floats2half2_rn(o[nt][0] * iA, o[nt][1] * iA);
        *(__half2*)(oB + cc) = __floats2half2_rn(o[nt][2] * iB, o[nt][3] * iB);
    }
}

// -------------------- host orchestration ----------------------------------
#define SM128 (3 * (128 * 64 + 8192))    // 49152
#define SM64  (3 * (64 * 64 + 8192))     // 36864

extern "C" void kernel_launch(void* const* d_in, const int* in_sizes, int n_in,
                              void* d_out, int out_size) {
    const int*   ctx  = (const int*)  d_in[0];
    const float* tok  = (const float*)d_in[1];
    const float* pos  = (const float*)d_in[2];
    const float* Wq   = (const float*)d_in[3];
    const float* Wk   = (const float*)d_in[4];
    const float* Wv   = (const float*)d_in[5];
    const float* Wo   = (const float*)d_in[6];
    const float* bo   = (const float*)d_in[7];
    const float* ln1g = (const float*)d_in[8];
    const float* ln1b = (const float*)d_in[9];
    const float* W1   = (const float*)d_in[10];
    const float* b1   = (const float*)d_in[11];
    const float* W2   = (const float*)d_in[12];
    const float* b2   = (const float*)d_in[13];
    const float* ln2g = (const float*)d_in[14];
    const float* ln2b = (const float*)d_in[15];
    const float* lnfg = (const float*)d_in[16];
    const float* lnfb = (const float*)d_in[17];
    const float* Wout = (const float*)d_in[18];
    const float* bout = (const float*)d_in[19];

    float* px;
    f16 *pqkv, *ph, *pat, *pff;
    f16 *pwqkv, *pwo, *pw1, *pw2, *pwout;
    cudaGetSymbolAddress((void**)&px,   g_x);
    cudaGetSymbolAddress((void**)&pqkv, g_qkv);
    cudaGetSymbolAddress((void**)&ph,   g_h);
    cudaGetSymbolAddress((void**)&pat,  g_at);
    cudaGetSymbolAddress((void**)&pff,  g_ff);
    cudaGetSymbolAddress((void**)&pwqkv, g_wqkv);
    cudaGetSymbolAddress((void**)&pwo,   g_wo);
    cudaGetSymbolAddress((void**)&pw1,   g_w1);
    cudaGetSymbolAddress((void**)&pw2,   g_w2);
    cudaGetSymbolAddress((void**)&pwout, g_wout);

    cudaFuncSetAttribute(attn_f16,
                         cudaFuncAttributeMaxDynamicSharedMemorySize, ATT_SMEM);
    cudaFuncSetAttribute(hgemm<128>,
                         cudaFuncAttributeMaxDynamicSharedMemorySize, SM128);
    cudaFuncSetAttribute(hgemm<64>,
                         cudaFuncAttributeMaxDynamicSharedMemorySize, SM64);

    // ---- weight conversion (fp32 -> fp16) ----
    int t;
    t = NL * DM * DM / 8;
    wconv<<<(t + 255) / 256, 256>>>(Wq, pwqkv, DM, QKVS, 0,      t);
    wconv<<<(t + 255) / 256, 256>>>(Wk, pwqkv, DM, QKVS, DM,     t);
    wconv<<<(t + 255) / 256, 256>>>(Wv, pwqkv, DM, QKVS, 2 * DM, t);
    wconv<<<(t + 255) / 256, 256>>>(Wo, pwo, DM, DM, 0, t);
    t = NL * DM * DFF / 8;
    wconv<<<(t + 255) / 256, 256>>>(W1, pw1, DFF, DFF, 0, t);
    wconv<<<(t + 255) / 256, 256>>>(W2, pw2, DM, DM, 0, t);
    t = DM * NV / 8;
    wconv<<<(t + 255) / 256, 256>>>(Wout, pwout, NV, NV, 0, t);

    embed_kernel<<<TOK, 256>>>(ctx, tok, pos);

    for (int l = 0; l < NL; l++) {
        size_t oqkv = (size_t)l * DM * QKVS;
        size_t owo  = (size_t)l * DM * DM;
        size_t ow1  = (size_t)l * DM * DFF;
        size_t ow2  = (size_t)l * DFF * DM;

        ln_half<<<TOK, 256>>>(px, ln1g + l * DM, ln1b + l * DM, ph);
        hgemm<128><<<dim3(16, 18), 256, SM128>>>(
            ph, pwqkv + oqkv, nullptr, nullptr, nullptr, pqkv, QKVS, DM, 0);
        attn_f16<<<dim3(SEQ / 64, NH, 2), 128, ATT_SMEM>>>(pqkv, pat);
        hgemm<64><<<dim3(32, 6), 256, SM64>>>(
            pat, pwo + owo, bo + l * DM, px, px, nullptr, DM, DM, 0);
        ln_half<<<TOK, 256>>>(px, ln2g + l * DM, ln2b + l * DM, ph);
        hgemm<128><<<dim3(16, 24), 256, SM128>>>(
            ph, pw1 + ow1, b1 + (size_t)l * DFF, nullptr, nullptr, pff,
            DFF, DM, 1);
        hgemm<64><<<dim3(32, 6), 256, SM64>>>(
            pff, pw2 + ow2, b2 + l * DM, px, px, nullptr, DM, DFF, 0);
    }

    ln_half<<<TOK, 256>>>(px, lnfg, lnfb, ph);
    hgemm<128><<<dim3(16, 250), 256, SM128>>>(
        ph, pwout, bout, nullptr, (float*)d_out, nullptr, NV, DM, 0);
}

// round 10
// speedup vs baseline: 7.2259x; 1.0645x over previous
#include <cuda_runtime.h>
#include <cuda_fp16.h>
#include <math.h>
#include <stdint.h>

// Problem constants
#define TOK   2048          // B*S
#define SEQ   1024
#define DM    768
#define DFF   3072
#define NH    12
#define HDIM  64
#define NV    32000
#define NL    6
#define QKVS  (3 * DM)      // 2304

typedef __half f16;

// -------------------- scratch (device globals; no allocation allowed) -----
__device__ __align__(16) float g_x  [TOK * DM];
__device__ __align__(16) f16   g_qkv[TOK * QKVS];
__device__ __align__(16) f16   g_h  [TOK * DM];
__device__ __align__(16) f16   g_at [TOK * DM];
__device__ __align__(16) f16   g_ff [TOK * DFF];
// converted weights [K,N] fp16
__device__ __align__(16) f16 g_wqkv[NL * DM * QKVS];
__device__ __align__(16) f16 g_wo  [NL * DM * DM];
__device__ __align__(16) f16 g_w1  [NL * DM * DFF];
__device__ __align__(16) f16 g_w2  [NL * DFF * DM];
__device__ __align__(16) f16 g_wout[DM * NV];

// -------------------- helpers ---------------------------------------------
__device__ __forceinline__ uint32_t cvta_smem(const void* p) {
    return (uint32_t)__cvta_generic_to_shared(p);
}
__device__ __forceinline__ void cp16(uint32_t s, const void* g) {
    asm volatile("cp.async.cg.shared.global [%0], [%1], 16;" :: "r"(s), "l"(g));
}
__device__ __forceinline__ void ldm_x4(uint32_t* r, uint32_t addr) {
    asm volatile("ldmatrix.sync.aligned.m8n8.x4.shared.b16 {%0,%1,%2,%3},[%4];"
                 : "=r"(r[0]), "=r"(r[1]), "=r"(r[2]), "=r"(r[3]) : "r"(addr));
}
__device__ __forceinline__ void ldm_x4_t(uint32_t* r, uint32_t addr) {
    asm volatile("ldmatrix.sync.aligned.m8n8.x4.trans.shared.b16 {%0,%1,%2,%3},[%4];"
                 : "=r"(r[0]), "=r"(r[1]), "=r"(r[2]), "=r"(r[3]) : "r"(addr));
}
__device__ __forceinline__ void mma_f16(float* c, const uint32_t* a, const uint32_t* b) {
    asm volatile(
        "mma.sync.aligned.m16n8k16.row.col.f32.f16.f16.f32 "
        "{%0,%1,%2,%3},{%4,%5,%6,%7},{%8,%9},{%0,%1,%2,%3};"
        : "+f"(c[0]), "+f"(c[1]), "+f"(c[2]), "+f"(c[3])
        : "r"(a[0]), "r"(a[1]), "r"(a[2]), "r"(a[3]), "r"(b[0]), "r"(b[1]));
}
__device__ __forceinline__ uint32_t pack_h2(float a, float b) {
    __half2 h = __floats2half2_rn(a, b);
    return *(uint32_t*)&h;
}

// -------------------- weight convert kernel ---------------------------------
// src [R, cols] fp32 -> dh [R, dst_stride] fp16 at column offset cofs
// 16 elements per thread (4x LDG.128 in flight) for latency hiding.
__global__ void wconv(const float* __restrict__ src, f16* __restrict__ dh,
                      int cols, int dst_stride, int cofs, int total16) {
    int i = blockIdx.x * 256 + threadIdx.x;
    if (i >= total16) return;
    size_t e = (size_t)i * 16;
    int r = (int)(e / cols), c = (int)(e - (size_t)r * cols);
    float4 v0 = *(const float4*)(src + e);
    float4 v1 = *(const float4*)(src + e + 4);
    float4 v2 = *(const float4*)(src + e + 8);
    float4 v3 = *(const float4*)(src + e + 12);
    size_t d = (size_t)r * dst_stride + cofs + c;
    f16 h[16];
    h[0]  = __float2half_rn(v0.x); h[1]  = __float2half_rn(v0.y);
    h[2]  = __float2half_rn(v0.z); h[3]  = __float2half_rn(v0.w);
    h[4]  = __float2half_rn(v1.x); h[5]  = __float2half_rn(v1.y);
    h[6]  = __float2half_rn(v1.z); h[7]  = __float2half_rn(v1.w);
    h[8]  = __float2half_rn(v2.x); h[9]  = __float2half_rn(v2.y);
    h[10] = __float2half_rn(v2.z); h[11] = __float2half_rn(v2.w);
    h[12] = __float2half_rn(v3.x); h[13] = __float2half_rn(v3.y);
    h[14] = __float2half_rn(v3.z); h[15] = __float2half_rn(v3.w);
    *(uint4*)(dh + d)     = *(uint4*)h;
    *(uint4*)(dh + d + 8) = *(uint4*)(h + 8);
}

// -------------------- embedding -------------------------------------------
__global__ void embed_kernel(const int* __restrict__ ctx,
                             const float* __restrict__ tok,
                             const float* __restrict__ pos) {
    int t = blockIdx.x;
    int token = ctx[t];
    int s = t & (SEQ - 1);
#pragma unroll
    for (int i = 0; i < 3; i++) {
        int d = threadIdx.x + i * 256;
        g_x[t * DM + d] = tok[token * DM + d] + pos[s * DM + d];
    }
}

// -------------------- layernorm -> fp16 ------------------------------------
__global__ void ln_half(const float* __restrict__ in,
                        const float* __restrict__ gg,
                        const float* __restrict__ bb,
                        f16* __restrict__ out) {
    int row = blockIdx.x;
    const float* x = in + row * DM;
    float v[3];
    float s = 0.f, ss = 0.f;
#pragma unroll
    for (int i = 0; i < 3; i++) {
        v[i] = x[threadIdx.x + i * 256];
        s  += v[i];
        ss += v[i] * v[i];
    }
#pragma unroll
    for (int m = 16; m; m >>= 1) {
        s  += __shfl_xor_sync(0xffffffffu, s,  m);
        ss += __shfl_xor_sync(0xffffffffu, ss, m);
    }
    __shared__ float sa[8], sb[8];
    int w = threadIdx.x >> 5, lane = threadIdx.x & 31;
    if (lane == 0) { sa[w] = s; sb[w] = ss; }
    __syncthreads();
    s = 0.f; ss = 0.f;
#pragma unroll
    for (int i = 0; i < 8; i++) { s += sa[i]; ss += sb[i]; }
    float mean = s * (1.0f / DM);
    float var  = ss * (1.0f / DM) - mean * mean;
    float inv  = rsqrtf(var + 1e-5f);
#pragma unroll
    for (int i = 0; i < 3; i++) {
        int d = threadIdx.x + i * 256;
        float y = (v[i] - mean) * inv * gg[d] + bb[d];
        out[row * DM + d] = __float2half_rn(y);
    }
}

// -------------------- fp16 tensor-core GEMM (single-pass, BK=64) -----------
// A smem: BM rows x 128B (full 8-wide xor swizzle). B smem: 64 rows x 256B.
__device__ __forceinline__ uint32_t swzA(int row, int kc) {   // kc 0..7
    return (uint32_t)(row * 128 + ((kc ^ (row & 7)) << 4));
}
__device__ __forceinline__ uint32_t swzB(int k, int nc) {     // nc 0..15
    return (uint32_t)(k * 256 + ((((nc & 7) ^ (k & 7)) | (nc & 8)) << 4));
}

template<int BM>
__global__ __launch_bounds__(256, 2)
void hgemm(const f16* __restrict__ A, const f16* __restrict__ B,
           const float* __restrict__ bias, const float* __restrict__ res,
           float* __restrict__ C, f16* __restrict__ Oh,
           int N, int K, int relu) {
    constexpr int WM = BM / 2;
    constexpr int MT = WM / 16;
    constexpr int ABYTES = BM * 128;          // BM rows x 128B
    constexpr int STAGE  = ABYTES + 16384;    // + B (64 x 256B)
    constexpr int NA = BM / 32;               // A 16B chunks per thread

    extern __shared__ char smc[];
    uint32_t sbase = cvta_smem(smc);

    int tid  = threadIdx.x;
    int lane = tid & 31;
    int warp = tid >> 5;
    int wm = warp >> 2;
    int wn = warp & 3;
    int g  = lane >> 2;
    int tg = lane & 3;
    int bm = blockIdx.x, bn = blockIdx.y;

    float acc[MT][4][4];
#pragma unroll
    for (int mi = 0; mi < MT; mi++)
#pragma unroll
        for (int ni = 0; ni < 4; ni++)
#pragma unroll
            for (int j = 0; j < 4; j++) acc[mi][ni][j] = 0.f;

#define LOADSTAGE(IT)                                                         \
    {                                                                         \
        int _it = (IT);                                                       \
        uint32_t st = sbase + (_it % 3) * STAGE;                              \
        _Pragma("unroll")                                                     \
        for (int u = 0; u < NA; u++) {                                        \
            int cu = tid + u * 256;                                           \
            int arow = cu >> 3, akc = cu & 7;                                 \
            uint32_t so = st + swzA(arow, akc);                               \
            size_t go = (size_t)(bm * BM + arow) * K + _it * 64 + akc * 8;    \
            cp16(so, A + go);                                                 \
        }                                                                     \
        _Pragma("unroll")                                                     \
        for (int u = 0; u < 4; u++) {                                         \
            int cu = tid + u * 256;                                           \
            int bk = cu >> 4, bnc = cu & 15;                                  \
            uint32_t so = st + ABYTES + swzB(bk, bnc);                        \
            size_t go = (size_t)(_it * 64 + bk) * N + bn * 128 + bnc * 8;     \
            cp16(so, B + go);                                                 \
        }                                                                     \
    }

    int nIter = K >> 6;      // K is 768 or 3072 -> 12 or 48
    LOADSTAGE(0); asm volatile("cp.async.commit_group;");
    LOADSTAGE(1); asm volatile("cp.async.commit_group;");

    int a_lrow = wm * WM + (lane & 15);
    int a_koff = (lane >> 4) & 1;
    int b_lk   = lane & 15;
    int b_noff = (lane >> 4) & 1;

    for (int it = 0; it < nIter; it++) {
        asm volatile("cp.async.wait_group 1;");
        __syncthreads();
        uint32_t sb = sbase + (it % 3) * STAGE;

#pragma unroll
        for (int k16 = 0; k16 < 4; k16++) {
            uint32_t Af[MT][4], Bf[4][2];
            int kc = k16 * 2 + a_koff;
#pragma unroll
            for (int mi = 0; mi < MT; mi++)
                ldm_x4(Af[mi], sb + swzA(a_lrow + mi * 16, kc));
            int kk = k16 * 16 + b_lk;
#pragma unroll
            for (int p = 0; p < 2; p++) {
                uint32_t r4[4];
                ldm_x4_t(r4, sb + ABYTES + swzB(kk, wn * 4 + p * 2 + b_noff));
                Bf[p*2][0] = r4[0]; Bf[p*2][1] = r4[1];
                Bf[p*2+1][0] = r4[2]; Bf[p*2+1][1] = r4[3];
            }
#pragma unroll
            for (int mi = 0; mi < MT; mi++)
#pragma unroll
                for (int ni = 0; ni < 4; ni++) mma_f16(acc[mi][ni], Af[mi], Bf[ni]);
        }

        if (it + 2 < nIter) LOADSTAGE(it + 2);
        asm volatile("cp.async.commit_group;");
    }
#undef LOADSTAGE

#pragma unroll
    for (int mi = 0; mi < MT; mi++) {
        int row0 = bm * BM + wm * WM + mi * 16 + g;
#pragma unroll
        for (int ni = 0; ni < 4; ni++) {
            int col = bn * 128 + wn * 32 + ni * 8 + 2 * tg;
            float b0 = 0.f, b1 = 0.f;
            if (bias) { b0 = bias[col]; b1 = bias[col + 1]; }
#pragma unroll
            for (int half = 0; half < 2; half++) {
                int row = row0 + half * 8;
                float v0 = acc[mi][ni][half * 2 + 0] + b0;
                float v1 = acc[mi][ni][half * 2 + 1] + b1;
                if (relu) { v0 = fmaxf(v0, 0.f); v1 = fmaxf(v1, 0.f); }
                size_t idx = (size_t)row * N + col;
                if (Oh) {
                    *(__half2*)(Oh + idx) =
                        __half2(__float2half_rn(v0), __float2half_rn(v1));
                } else {
                    if (res) {
                        float2 r2 = *(const float2*)(res + idx);
                        v0 += r2.x; v1 += r2.y;
                    }
                    *(float2*)(C + idx) = make_float2(v0, v1);
                }
            }
        }
    }
}

// -------------------- fp16 tensor-core flash attention ----------------------
#define AQ_BYTES 8192
#define AKV_STAGE 16384
#define ATT_SMEM (AQ_BYTES + 3 * AKV_STAGE)

__device__ __forceinline__ uint32_t swzR(int row, int c) {   // 128B rows
    return (uint32_t)(row * 128 + ((c ^ (row & 7)) << 4));
}

__global__ __launch_bounds__(128)
void attn_f16(const f16* __restrict__ QKV, f16* __restrict__ O) {
    extern __shared__ char smc[];
    uint32_t sb = cvta_smem(smc);

    int qt = blockIdx.x, h = blockIdx.y, b = blockIdx.z;
    int tid = threadIdx.x, lane = tid & 31, warp = tid >> 5;
    int g = lane >> 2, tg = lane & 3;
    int wrow = warp * 16;
    int nT = qt + 1;

    const f16* Qg = QKV + (size_t)(b * SEQ + qt * 64) * QKVS + h * HDIM;

#define LOADQ()                                                               \
    {                                                                         \
        _Pragma("unroll")                                                     \
        for (int u = 0; u < 4; u++) {                                         \
            int idx = tid + u * 128;                                          \
            int row = idx >> 3, c = idx & 7;                                  \
            cp16(sb + swzR(row, c), Qg + (size_t)row * QKVS + c * 8);         \
        }                                                                     \
    }
#define LOADKV(SLOT, KT)                                                      \
    {                                                                         \
        uint32_t st = sb + AQ_BYTES + ((SLOT) % 3) * AKV_STAGE;               \
        const f16* Kg = QKV + (size_t)(b * SEQ + (KT) * 64) * QKVS            \
                        + DM + h * HDIM;                                      \
        _Pragma("unroll")                                                     \
        for (int u = 0; u < 4; u++) {                                         \
            int idx = tid + u * 128;                                          \
            int row = idx >> 3, c = idx & 7;                                  \
            uint32_t so = st + swzR(row, c);                                  \
            size_t go = (size_t)row * QKVS + c * 8;                           \
            cp16(so, Kg + go);                                                \
            cp16(so + 8192, Kg + DM + go);                                    \
        }                                                                     \
    }

    LOADQ(); LOADKV(0, 0);
    asm volatile("cp.async.commit_group;");
    if (1 < nT) LOADKV(1, 1);
    asm volatile("cp.async.commit_group;");

    float o[8][4];
#pragma unroll
    for (int nt = 0; nt < 8; nt++)
#pragma unroll
        for (int j = 0; j < 4; j++) o[nt][j] = 0.f;
    float m[2] = {-INFINITY, -INFINITY}, l[2] = {0.f, 0.f};
    uint32_t qf[4][4];

    for (int kt = 0; kt < nT; kt++) {
        asm volatile("cp.async.wait_group 1;");
        __syncthreads();

        if (kt == 0) {
#pragma unroll
            for (int i = 0; i < 4; i++) {
                int row = wrow + (lane & 15);
                int c = 2 * i + (lane >> 4);
                ldm_x4(qf[i], sb + swzR(row, c));
            }
        }

        if (kt + 2 < nT) LOADKV(kt + 2, kt + 2);
        asm volatile("cp.async.commit_group;");

        uint32_t kb = sb + AQ_BYTES + (kt % 3) * AKV_STAGE;
        float s[8][4];
#pragma unroll
        for (int nt = 0; nt < 8; nt++)
#pragma unroll
            for (int j = 0; j < 4; j++) s[nt][j] = 0.f;

#pragma unroll
        for (int ntp = 0; ntp < 4; ntp++) {
            int krow = ntp * 16 + (lane & 7) + ((lane >> 4) << 3);
#pragma unroll
            for (int i = 0; i < 4; i++) {
                uint32_t r4[4];
                int c = 2 * i + ((lane >> 3) & 1);
                ldm_x4(r4, kb + swzR(krow, c));
                mma_f16(s[2 * ntp],     qf[i], r4);
                mma_f16(s[2 * ntp + 1], qf[i], r4 + 2);
            }
        }

#pragma unroll
        for (int nt = 0; nt < 8; nt++)
#pragma unroll
            for (int j = 0; j < 4; j++) s[nt][j] *= 0.125f;
        if (kt == qt) {
            int rA = wrow + g, rB = rA + 8;
#pragma unroll
            for (int nt = 0; nt < 8; nt++) {
                int cc = nt * 8 + 2 * tg;
                if (cc     > rA) s[nt][0] = -1e30f;
                if (cc + 1 > rA) s[nt][1] = -1e30f;
                if (cc     > rB) s[nt][2] = -1e30f;
                if (cc + 1 > rB) s[nt][3] = -1e30f;
            }
        }

        float mxA = -1e30f, mxB = -1e30f;
#pragma unroll
        for (int nt = 0; nt < 8; nt++) {
            mxA = fmaxf(mxA, fmaxf(s[nt][0], s[nt][1]));
            mxB = fmaxf(mxB, fmaxf(s[nt][2], s[nt][3]));
        }
        mxA = fmaxf(mxA, __shfl_xor_sync(0xffffffffu, mxA, 1));
        mxA = fmaxf(mxA, __shfl_xor_sync(0xffffffffu, mxA, 2));
        mxB = fmaxf(mxB, __shfl_xor_sync(0xffffffffu, mxB, 1));
        mxB = fmaxf(mxB, __shfl_xor_sync(0xffffffffu, mxB, 2));
        float mnA = fmaxf(m[0], mxA), mnB = fmaxf(m[1], mxB);
        float fA = __expf(m[0] - mnA), fB = __expf(m[1] - mnB);
        float sA = 0.f, sB = 0.f;
#pragma unroll
        for (int nt = 0; nt < 8; nt++) {
            s[nt][0] = __expf(s[nt][0] - mnA);
            s[nt][1] = __expf(s[nt][1] - mnA);
            s[nt][2] = __expf(s[nt][2] - mnB);
            s[nt][3] = __expf(s[nt][3] - mnB);
            sA += s[nt][0] + s[nt][1];
            sB += s[nt][2] + s[nt][3];
        }
        sA += __shfl_xor_sync(0xffffffffu, sA, 1);
        sA += __shfl_xor_sync(0xffffffffu, sA, 2);
        sB += __shfl_xor_sync(0xffffffffu, sB, 1);
        sB += __shfl_xor_sync(0xffffffffu, sB, 2);
        l[0] = l[0] * fA + sA; m[0] = mnA;
        l[1] = l[1] * fB + sB; m[1] = mnB;
#pragma unroll
        for (int nt = 0; nt < 8; nt++) {
            o[nt][0] *= fA; o[nt][1] *= fA;
            o[nt][2] *= fB; o[nt][3] *= fB;
        }

        uint32_t pk[4][4];
#pragma unroll
        for (int i = 0; i < 4; i++) {
            pk[i][0] = pack_h2(s[2*i][0],   s[2*i][1]);
            pk[i][1] = pack_h2(s[2*i][2],   s[2*i][3]);
            pk[i][2] = pack_h2(s[2*i+1][0], s[2*i+1][1]);
            pk[i][3] = pack_h2(s[2*i+1][2], s[2*i+1][3]);
        }

        uint32_t vb = kb + 8192;
#pragma unroll
        for (int i = 0; i < 4; i++) {
            int vrow = i * 16 + (lane & 15);
#pragma unroll
            for (int hdp = 0; hdp < 4; hdp++) {
                uint32_t r4[4];
                int c = 2 * hdp + (lane >> 4);
                ldm_x4_t(r4, vb + swzR(vrow, c));
                mma_f16(o[2 * hdp],     pk[i], r4);
                mma_f16(o[2 * hdp + 1], pk[i], r4 + 2);
            }
        }
    }
#undef LOADQ
#undef LOADKV

    float iA = 1.f / l[0], iB = 1.f / l[1];
    size_t rowA = (size_t)(b * SEQ + qt * 64 + wrow + g);
    f16* oA = O + rowA * DM + h * HDIM;
    f16* oB = oA + (size_t)8 * DM;
#pragma unroll
    for (int nt = 0; nt < 8; nt++) {
        int cc = nt * 8 + 2 * tg;
        *(__half2*)(oA + cc) = __floats2half2_rn(o[nt][0] * iA, o[nt][1] * iA);
        *(__half2*)(oB + cc) = __floats2half2_rn(o[nt][2] * iB, o[nt][3] * iB);
    }
}

// -------------------- host orchestration ----------------------------------
#define SM128 (3 * (128 * 128 + 16384))   // 98304
#define SM64  (3 * (64 * 128 + 16384))    // 73728

extern "C" void kernel_launch(void* const* d_in, const int* in_sizes, int n_in,
                              void* d_out, int out_size) {
    const int*   ctx  = (const int*)  d_in[0];
    const float* tok  = (const float*)d_in[1];
    const float* pos  = (const float*)d_in[2];
    const float* Wq   = (const float*)d_in[3];
    const float* Wk   = (const float*)d_in[4];
    const float* Wv   = (const float*)d_in[5];
    const float* Wo   = (const float*)d_in[6];
    const float* bo   = (const float*)d_in[7];
    const float* ln1g = (const float*)d_in[8];
    const float* ln1b = (const float*)d_in[9];
    const float* W1   = (const float*)d_in[10];
    const float* b1   = (const float*)d_in[11];
    const float* W2   = (const float*)d_in[12];
    const float* b2   = (const float*)d_in[13];
    const float* ln2g = (const float*)d_in[14];
    const float* ln2b = (const float*)d_in[15];
    const float* lnfg = (const float*)d_in[16];
    const float* lnfb = (const float*)d_in[17];
    const float* Wout = (const float*)d_in[18];
    const float* bout = (const float*)d_in[19];

    float* px;
    f16 *pqkv, *ph, *pat, *pff;
    f16 *pwqkv, *pwo, *pw1, *pw2, *pwout;
    cudaGetSymbolAddress((void**)&px,   g_x);
    cudaGetSymbolAddress((void**)&pqkv, g_qkv);
    cudaGetSymbolAddress((void**)&ph,   g_h);
    cudaGetSymbolAddress((void**)&pat,  g_at);
    cudaGetSymbolAddress((void**)&pff,  g_ff);
    cudaGetSymbolAddress((void**)&pwqkv, g_wqkv);
    cudaGetSymbolAddress((void**)&pwo,   g_wo);
    cudaGetSymbolAddress((void**)&pw1,   g_w1);
    cudaGetSymbolAddress((void**)&pw2,   g_w2);
    cudaGetSymbolAddress((void**)&pwout, g_wout);

    cudaFuncSetAttribute(attn_f16,
                         cudaFuncAttributeMaxDynamicSharedMemorySize, ATT_SMEM);
    cudaFuncSetAttribute(hgemm<128>,
                         cudaFuncAttributeMaxDynamicSharedMemorySize, SM128);
    cudaFuncSetAttribute(hgemm<64>,
                         cudaFuncAttributeMaxDynamicSharedMemorySize, SM64);

    // ---- weight conversion (fp32 -> fp16), 16 elems/thread ----
    int t;
    t = NL * DM * DM / 16;
    wconv<<<(t + 255) / 256, 256>>>(Wq, pwqkv, DM, QKVS, 0,      t);
    wconv<<<(t + 255) / 256, 256>>>(Wk, pwqkv, DM, QKVS, DM,     t);
    wconv<<<(t + 255) / 256, 256>>>(Wv, pwqkv, DM, QKVS, 2 * DM, t);
    wconv<<<(t + 255) / 256, 256>>>(Wo, pwo, DM, DM, 0, t);
    t = NL * DM * DFF / 16;
    wconv<<<(t + 255) / 256, 256>>>(W1, pw1, DFF, DFF, 0, t);
    wconv<<<(t + 255) / 256, 256>>>(W2, pw2, DM, DM, 0, t);
    t = DM * NV / 16;
    wconv<<<(t + 255) / 256, 256>>>(Wout, pwout, NV, NV, 0, t);

    embed_kernel<<<TOK, 256>>>(ctx, tok, pos);

    for (int l = 0; l < NL; l++) {
        size_t oqkv = (size_t)l * DM * QKVS;
        size_t owo  = (size_t)l * DM * DM;
        size_t ow1  = (size_t)l * DM * DFF;
        size_t ow2  = (size_t)l * DFF * DM;

        ln_half<<<TOK, 256>>>(px, ln1g + l * DM, ln1b + l * DM, ph);
        hgemm<128><<<dim3(16, 18), 256, SM128>>>(
            ph, pwqkv + oqkv, nullptr, nullptr, nullptr, pqkv, QKVS, DM, 0);
        attn_f16<<<dim3(SEQ / 64, NH, 2), 128, ATT_SMEM>>>(pqkv, pat);
        hgemm<64><<<dim3(32, 6), 256, SM64>>>(
            pat, pwo + owo, bo + l * DM, px, px, nullptr, DM, DM, 0);
        ln_half<<<TOK, 256>>>(px, ln2g + l * DM, ln2b + l * DM, ph);
        hgemm<128><<<dim3(16, 24), 256, SM128>>>(
            ph, pw1 + ow1, b1 + (size_t)l * DFF, nullptr, nullptr, pff,
            DFF, DM, 1);
        hgemm<64><<<dim3(32, 6), 256, SM64>>>(
            pff, pw2 + ow2, b2 + l * DM, px, px, nullptr, DM, DFF, 0);
    }

    ln_half<<<TOK, 256>>>(px, lnfg, lnfb, ph);
    hgemm<128><<<dim3(16, 250), 256, SM128>>>(
        ph, pwout, bout, nullptr, (float*)d_out, nullptr, NV, DM, 0);
}

// round 11
// speedup vs baseline: 7.3437x; 1.0163x over previous
#include <cuda_runtime.h>
#include <cuda_fp16.h>
#include <math.h>
#include <stdint.h>

// Problem constants
#define TOK   2048          // B*S
#define SEQ   1024
#define DM    768
#define DFF   3072
#define NH    12
#define HDIM  64
#define NV    32000
#define NL    6
#define QKVS  (3 * DM)      // 2304

typedef __half f16;

// -------------------- scratch (device globals; no allocation allowed) -----
__device__ __align__(16) float g_x  [TOK * DM];
__device__ __align__(16) f16   g_qkv[TOK * QKVS];
__device__ __align__(16) f16   g_h  [TOK * DM];
__device__ __align__(16) f16   g_at [TOK * DM];
__device__ __align__(16) f16   g_ff [TOK * DFF];
// converted weights [K,N] fp16
__device__ __align__(16) f16 g_wqkv[NL * DM * QKVS];
__device__ __align__(16) f16 g_wo  [NL * DM * DM];
__device__ __align__(16) f16 g_w1  [NL * DM * DFF];
__device__ __align__(16) f16 g_w2  [NL * DFF * DM];
__device__ __align__(16) f16 g_wout[DM * NV];

// -------------------- helpers ---------------------------------------------
__device__ __forceinline__ uint32_t cvta_smem(const void* p) {
    return (uint32_t)__cvta_generic_to_shared(p);
}
__device__ __forceinline__ void cp16(uint32_t s, const void* g) {
    asm volatile("cp.async.cg.shared.global [%0], [%1], 16;" :: "r"(s), "l"(g));
}
__device__ __forceinline__ void ldm_x4(uint32_t* r, uint32_t addr) {
    asm volatile("ldmatrix.sync.aligned.m8n8.x4.shared.b16 {%0,%1,%2,%3},[%4];"
                 : "=r"(r[0]), "=r"(r[1]), "=r"(r[2]), "=r"(r[3]) : "r"(addr));
}
__device__ __forceinline__ void ldm_x4_t(uint32_t* r, uint32_t addr) {
    asm volatile("ldmatrix.sync.aligned.m8n8.x4.trans.shared.b16 {%0,%1,%2,%3},[%4];"
                 : "=r"(r[0]), "=r"(r[1]), "=r"(r[2]), "=r"(r[3]) : "r"(addr));
}
__device__ __forceinline__ void mma_f16(float* c, const uint32_t* a, const uint32_t* b) {
    asm volatile(
        "mma.sync.aligned.m16n8k16.row.col.f32.f16.f16.f32 "
        "{%0,%1,%2,%3},{%4,%5,%6,%7},{%8,%9},{%0,%1,%2,%3};"
        : "+f"(c[0]), "+f"(c[1]), "+f"(c[2]), "+f"(c[3])
        : "r"(a[0]), "r"(a[1]), "r"(a[2]), "r"(a[3]), "r"(b[0]), "r"(b[1]));
}
__device__ __forceinline__ uint32_t pack_h2(float a, float b) {
    __half2 h = __floats2half2_rn(a, b);
    return *(uint32_t*)&h;
}

// -------------------- weight convert kernel ---------------------------------
__global__ void wconv(const float* __restrict__ src, f16* __restrict__ dh,
                      int cols, int dst_stride, int cofs, int total16) {
    int i = blockIdx.x * 256 + threadIdx.x;
    if (i >= total16) return;
    size_t e = (size_t)i * 16;
    int r = (int)(e / cols), c = (int)(e - (size_t)r * cols);
    float4 v0 = *(const float4*)(src + e);
    float4 v1 = *(const float4*)(src + e + 4);
    float4 v2 = *(const float4*)(src + e + 8);
    float4 v3 = *(const float4*)(src + e + 12);
    size_t d = (size_t)r * dst_stride + cofs + c;
    f16 h[16];
    h[0]  = __float2half_rn(v0.x); h[1]  = __float2half_rn(v0.y);
    h[2]  = __float2half_rn(v0.z); h[3]  = __float2half_rn(v0.w);
    h[4]  = __float2half_rn(v1.x); h[5]  = __float2half_rn(v1.y);
    h[6]  = __float2half_rn(v1.z); h[7]  = __float2half_rn(v1.w);
    h[8]  = __float2half_rn(v2.x); h[9]  = __float2half_rn(v2.y);
    h[10] = __float2half_rn(v2.z); h[11] = __float2half_rn(v2.w);
    h[12] = __float2half_rn(v3.x); h[13] = __float2half_rn(v3.y);
    h[14] = __float2half_rn(v3.z); h[15] = __float2half_rn(v3.w);
    *(uint4*)(dh + d)     = *(uint4*)h;
    *(uint4*)(dh + d + 8) = *(uint4*)(h + 8);
}

// -------------------- embedding -------------------------------------------
__global__ void embed_kernel(const int* __restrict__ ctx,
                             const float* __restrict__ tok,
                             const float* __restrict__ pos) {
    int t = blockIdx.x;
    int token = ctx[t];
    int s = t & (SEQ - 1);
#pragma unroll
    for (int i = 0; i < 3; i++) {
        int d = threadIdx.x + i * 256;
        g_x[t * DM + d] = tok[token * DM + d] + pos[s * DM + d];
    }
}

// -------------------- layernorm -> fp16 ------------------------------------
__global__ void ln_half(const float* __restrict__ in,
                        const float* __restrict__ gg,
                        const float* __restrict__ bb,
                        f16* __restrict__ out) {
    int row = blockIdx.x;
    const float* x = in + row * DM;
    float v[3];
    float s = 0.f, ss = 0.f;
#pragma unroll
    for (int i = 0; i < 3; i++) {
        v[i] = x[threadIdx.x + i * 256];
        s  += v[i];
        ss += v[i] * v[i];
    }
#pragma unroll
    for (int m = 16; m; m >>= 1) {
        s  += __shfl_xor_sync(0xffffffffu, s,  m);
        ss += __shfl_xor_sync(0xffffffffu, ss, m);
    }
    __shared__ float sa[8], sb[8];
    int w = threadIdx.x >> 5, lane = threadIdx.x & 31;
    if (lane == 0) { sa[w] = s; sb[w] = ss; }
    __syncthreads();
    s = 0.f; ss = 0.f;
#pragma unroll
    for (int i = 0; i < 8; i++) { s += sa[i]; ss += sb[i]; }
    float mean = s * (1.0f / DM);
    float var  = ss * (1.0f / DM) - mean * mean;
    float inv  = rsqrtf(var + 1e-5f);
#pragma unroll
    for (int i = 0; i < 3; i++) {
        int d = threadIdx.x + i * 256;
        float y = (v[i] - mean) * inv * gg[d] + bb[d];
        out[row * DM + d] = __float2half_rn(y);
    }
}

// -------------------- fp16 tensor-core GEMM (BK=64, tiled BM x BN) ---------
// A smem: BM rows x 128B (8-wide xor swizzle). B smem: 64 rows x (BN*2)B.
__device__ __forceinline__ uint32_t swzA(int row, int kc) {   // kc 0..7
    return (uint32_t)(row * 128 + ((kc ^ (row & 7)) << 4));
}
template<int CR>   // chunks per B row: 16 (BN=128) or 8 (BN=64)
__device__ __forceinline__ uint32_t swzB(int k, int nc) {
    int c = (CR == 16) ? (((nc & 7) ^ (k & 7)) | (nc & 8)) : (nc ^ (k & 7));
    return (uint32_t)(k * (CR * 16) + (c << 4));
}

template<int BM, int BN, int OCC>
__global__ __launch_bounds__(256, OCC)
void hgemm(const f16* __restrict__ A, const f16* __restrict__ B,
           const float* __restrict__ bias, const float* __restrict__ res,
           float* __restrict__ C, f16* __restrict__ Oh,
           int N, int K, int relu) {
    constexpr int WM = BM / 2;
    constexpr int MT = WM / 16;
    constexpr int WN = BN / 4;
    constexpr int NT = WN / 8;            // 4 or 2
    constexpr int CR = BN / 8;            // B chunks per row
    constexpr int ABYTES = BM * 128;
    constexpr int BBYTES = 64 * BN * 2;
    constexpr int STAGE  = ABYTES + BBYTES;
    constexpr int NA = BM / 32;           // A 16B chunks per thread
    constexpr int NB = CR / 4;            // B 16B chunks per thread

    extern __shared__ char smc[];
    uint32_t sbase = cvta_smem(smc);

    int tid  = threadIdx.x;
    int lane = tid & 31;
    int warp = tid >> 5;
    int wm = warp >> 2;
    int wn = warp & 3;
    int g  = lane >> 2;
    int tg = lane & 3;
    int bm = blockIdx.x, bn = blockIdx.y;

    float acc[MT][NT][4];
#pragma unroll
    for (int mi = 0; mi < MT; mi++)
#pragma unroll
        for (int ni = 0; ni < NT; ni++)
#pragma unroll
            for (int j = 0; j < 4; j++) acc[mi][ni][j] = 0.f;

#define LOADSTAGE(IT)                                                         \
    {                                                                         \
        int _it = (IT);                                                       \
        uint32_t st = sbase + (_it % 3) * STAGE;                              \
        _Pragma("unroll")                                                     \
        for (int u = 0; u < NA; u++) {                                        \
            int cu = tid + u * 256;                                           \
            int arow = cu >> 3, akc = cu & 7;                                 \
            uint32_t so = st + swzA(arow, akc);                               \
            size_t go = (size_t)(bm * BM + arow) * K + _it * 64 + akc * 8;    \
            cp16(so, A + go);                                                 \
        }                                                                     \
        _Pragma("unroll")                                                     \
        for (int u = 0; u < NB; u++) {                                        \
            int cu = tid + u * 256;                                           \
            int bk = cu / CR, bnc = cu % CR;                                  \
            uint32_t so = st + ABYTES + swzB<CR>(bk, bnc);                    \
            size_t go = (size_t)(_it * 64 + bk) * N + bn * BN + bnc * 8;      \
            cp16(so, B + go);                                                 \
        }                                                                     \
    }

    int nIter = K >> 6;
    LOADSTAGE(0); asm volatile("cp.async.commit_group;");
    LOADSTAGE(1); asm volatile("cp.async.commit_group;");

    int a_lrow = wm * WM + (lane & 15);
    int a_koff = (lane >> 4) & 1;
    int b_lk   = lane & 15;
    int b_noff = (lane >> 4) & 1;

    for (int it = 0; it < nIter; it++) {
        asm volatile("cp.async.wait_group 1;");
        __syncthreads();
        uint32_t sb = sbase + (it % 3) * STAGE;

#pragma unroll
        for (int k16 = 0; k16 < 4; k16++) {
            uint32_t Af[MT][4], Bf[NT][2];
            int kc = k16 * 2 + a_koff;
#pragma unroll
            for (int mi = 0; mi < MT; mi++)
                ldm_x4(Af[mi], sb + swzA(a_lrow + mi * 16, kc));
            int kk = k16 * 16 + b_lk;
#pragma unroll
            for (int p = 0; p < NT / 2; p++) {
                uint32_t r4[4];
                ldm_x4_t(r4, sb + ABYTES + swzB<CR>(kk, wn * NT + 2 * p + b_noff));
                Bf[p*2][0] = r4[0]; Bf[p*2][1] = r4[1];
                Bf[p*2+1][0] = r4[2]; Bf[p*2+1][1] = r4[3];
            }
#pragma unroll
            for (int mi = 0; mi < MT; mi++)
#pragma unroll
                for (int ni = 0; ni < NT; ni++) mma_f16(acc[mi][ni], Af[mi], Bf[ni]);
        }

        if (it + 2 < nIter) LOADSTAGE(it + 2);
        asm volatile("cp.async.commit_group;");
    }
#undef LOADSTAGE

#pragma unroll
    for (int mi = 0; mi < MT; mi++) {
        int row0 = bm * BM + wm * WM + mi * 16 + g;
#pragma unroll
        for (int ni = 0; ni < NT; ni++) {
            int col = bn * BN + wn * WN + ni * 8 + 2 * tg;
            float b0 = 0.f, b1 = 0.f;
            if (bias) { b0 = bias[col]; b1 = bias[col + 1]; }
#pragma unroll
            for (int half = 0; half < 2; half++) {
                int row = row0 + half * 8;
                float v0 = acc[mi][ni][half * 2 + 0] + b0;
                float v1 = acc[mi][ni][half * 2 + 1] + b1;
                if (relu) { v0 = fmaxf(v0, 0.f); v1 = fmaxf(v1, 0.f); }
                size_t idx = (size_t)row * N + col;
                if (Oh) {
                    *(__half2*)(Oh + idx) =
                        __half2(__float2half_rn(v0), __float2half_rn(v1));
                } else {
                    if (res) {
                        float2 r2 = *(const float2*)(res + idx);
                        v0 += r2.x; v1 += r2.y;
                    }
                    *(float2*)(C + idx) = make_float2(v0, v1);
                }
            }
        }
    }
}

// -------------------- fp16 tensor-core flash attention ----------------------
#define AQ_BYTES 8192
#define AKV_STAGE 16384
#define ATT_SMEM (AQ_BYTES + 3 * AKV_STAGE)

__device__ __forceinline__ uint32_t swzR(int row, int c) {   // 128B rows
    return (uint32_t)(row * 128 + ((c ^ (row & 7)) << 4));
}

__global__ __launch_bounds__(128)
void attn_f16(const f16* __restrict__ QKV, f16* __restrict__ O) {
    extern __shared__ char smc[];
    uint32_t sb = cvta_smem(smc);

    // heavy tiles first: low blockIdx -> largest qt
    int qt = gridDim.x - 1 - blockIdx.x;
    int h = blockIdx.y, b = blockIdx.z;
    int tid = threadIdx.x, lane = tid & 31, warp = tid >> 5;
    int g = lane >> 2, tg = lane & 3;
    int wrow = warp * 16;
    int nT = qt + 1;

    const f16* Qg = QKV + (size_t)(b * SEQ + qt * 64) * QKVS + h * HDIM;

#define LOADQ()                                                               \
    {                                                                         \
        _Pragma("unroll")                                                     \
        for (int u = 0; u < 4; u++) {                                         \
            int idx = tid + u * 128;                                          \
            int row = idx >> 3, c = idx & 7;                                  \
            cp16(sb + swzR(row, c), Qg + (size_t)row * QKVS + c * 8);         \
        }                                                                     \
    }
#define LOADKV(SLOT, KT)                                                      \
    {                                                                         \
        uint32_t st = sb + AQ_BYTES + ((SLOT) % 3) * AKV_STAGE;               \
        const f16* Kg = QKV + (size_t)(b * SEQ + (KT) * 64) * QKVS            \
                        + DM + h * HDIM;                                      \
        _Pragma("unroll")                                                     \
        for (int u = 0; u < 4; u++) {                                         \
            int idx = tid + u * 128;                                          \
            int row = idx >> 3, c = idx & 7;                                  \
            uint32_t so = st + swzR(row, c);                                  \
            size_t go = (size_t)row * QKVS + c * 8;                           \
            cp16(so, Kg + go);                                                \
            cp16(so + 8192, Kg + DM + go);                                    \
        }                                                                     \
    }

    LOADQ(); LOADKV(0, 0);
    asm volatile("cp.async.commit_group;");
    if (1 < nT) LOADKV(1, 1);
    asm volatile("cp.async.commit_group;");

    float o[8][4];
#pragma unroll
    for (int nt = 0; nt < 8; nt++)
#pragma unroll
        for (int j = 0; j < 4; j++) o[nt][j] = 0.f;
    float m[2] = {-INFINITY, -INFINITY}, l[2] = {0.f, 0.f};
    uint32_t qf[4][4];

    for (int kt = 0; kt < nT; kt++) {
        asm volatile("cp.async.wait_group 1;");
        __syncthreads();

        if (kt == 0) {
#pragma unroll
            for (int i = 0; i < 4; i++) {
                int row = wrow + (lane & 15);
                int c = 2 * i + (lane >> 4);
                ldm_x4(qf[i], sb + swzR(row, c));
            }
        }

        if (kt + 2 < nT) LOADKV(kt + 2, kt + 2);
        asm volatile("cp.async.commit_group;");

        uint32_t kb = sb + AQ_BYTES + (kt % 3) * AKV_STAGE;
        float s[8][4];
#pragma unroll
        for (int nt = 0; nt < 8; nt++)
#pragma unroll
            for (int j = 0; j < 4; j++) s[nt][j] = 0.f;

#pragma unroll
        for (int ntp = 0; ntp < 4; ntp++) {
            int krow = ntp * 16 + (lane & 7) + ((lane >> 4) << 3);
#pragma unroll
            for (int i = 0; i < 4; i++) {
                uint32_t r4[4];
                int c = 2 * i + ((lane >> 3) & 1);
                ldm_x4(r4, kb + swzR(krow, c));
                mma_f16(s[2 * ntp],     qf[i], r4);
                mma_f16(s[2 * ntp + 1], qf[i], r4 + 2);
            }
        }

#pragma unroll
        for (int nt = 0; nt < 8; nt++)
#pragma unroll
            for (int j = 0; j < 4; j++) s[nt][j] *= 0.125f;
        if (kt == qt) {
            int rA = wrow + g, rB = rA + 8;
#pragma unroll
            for (int nt = 0; nt < 8; nt++) {
                int cc = nt * 8 + 2 * tg;
                if (cc     > rA) s[nt][0] = -1e30f;
                if (cc + 1 > rA) s[nt][1] = -1e30f;
                if (cc     > rB) s[nt][2] = -1e30f;
                if (cc + 1 > rB) s[nt][3] = -1e30f;
            }
        }

        float mxA = -1e30f, mxB = -1e30f;
#pragma unroll
        for (int nt = 0; nt < 8; nt++) {
            mxA = fmaxf(mxA, fmaxf(s[nt][0], s[nt][1]));
            mxB = fmaxf(mxB, fmaxf(s[nt][2], s[nt][3]));
        }
        mxA = fmaxf(mxA, __shfl_xor_sync(0xffffffffu, mxA, 1));
        mxA = fmaxf(mxA, __shfl_xor_sync(0xffffffffu, mxA, 2));
        mxB = fmaxf(mxB, __shfl_xor_sync(0xffffffffu, mxB, 1));
        mxB = fmaxf(mxB, __shfl_xor_sync(0xffffffffu, mxB, 2));
        float mnA = fmaxf(m[0], mxA), mnB = fmaxf(m[1], mxB);
        float fA = __expf(m[0] - mnA), fB = __expf(m[1] - mnB);
        float sA = 0.f, sB = 0.f;
#pragma unroll
        for (int nt = 0; nt < 8; nt++) {
            s[nt][0] = __expf(s[nt][0] - mnA);
            s[nt][1] = __expf(s[nt][1] - mnA);
            s[nt][2] = __expf(s[nt][2] - mnB);
            s[nt][3] = __expf(s[nt][3] - mnB);
            sA += s[nt][0] + s[nt][1];
            sB += s[nt][2] + s[nt][3];
        }
        sA += __shfl_xor_sync(0xffffffffu, sA, 1);
        sA += __shfl_xor_sync(0xffffffffu, sA, 2);
        sB += __shfl_xor_sync(0xffffffffu, sB, 1);
        sB += __shfl_xor_sync(0xffffffffu, sB, 2);
        l[0] = l[0] * fA + sA; m[0] = mnA;
        l[1] = l[1] * fB + sB; m[1] = mnB;
#pragma unroll
        for (int nt = 0; nt < 8; nt++) {
            o[nt][0] *= fA; o[nt][1] *= fA;
            o[nt][2] *= fB; o[nt][3] *= fB;
        }

        uint32_t pk[4][4];
#pragma unroll
        for (int i = 0; i < 4; i++) {
            pk[i][0] = pack_h2(s[2*i][0],   s[2*i][1]);
            pk[i][1] = pack_h2(s[2*i][2],   s[2*i][3]);
            pk[i][2] = pack_h2(s[2*i+1][0], s[2*i+1][1]);
            pk[i][3] = pack_h2(s[2*i+1][2], s[2*i+1][3]);
        }

        uint32_t vb = kb + 8192;
#pragma unroll
        for (int i = 0; i < 4; i++) {
            int vrow = i * 16 + (lane & 15);
#pragma unroll
            for (int hdp = 0; hdp < 4; hdp++) {
                uint32_t r4[4];
                int c = 2 * hdp + (lane >> 4);
                ldm_x4_t(r4, vb + swzR(vrow, c));
                mma_f16(o[2 * hdp],     pk[i], r4);
                mma_f16(o[2 * hdp + 1], pk[i], r4 + 2);
            }
        }
    }
#undef LOADQ
#undef LOADKV

    float iA = 1.f / l[0], iB = 1.f / l[1];
    size_t rowA = (size_t)(b * SEQ + qt * 64 + wrow + g);
    f16* oA = O + rowA * DM + h * HDIM;
    f16* oB = oA + (size_t)8 * DM;
#pragma unroll
    for (int nt = 0; nt < 8; nt++) {
        int cc = nt * 8 + 2 * tg;
        *(__half2*)(oA + cc) = __floats2half2_rn(o[nt][0] * iA, o[nt][1] * iA);
        *(__half2*)(oB + cc) = __floats2half2_rn(o[nt][2] * iB, o[nt][3] * iB);
    }
}

// -------------------- host orchestration ----------------------------------
#define SM128 (3 * (128 * 128 + 16384))   // 98304
#define SM6464 (3 * (64 * 128 + 8192))    // 49152

extern "C" void kernel_launch(void* const* d_in, const int* in_sizes, int n_in,
                              void* d_out, int out_size) {
    const int*   ctx  = (const int*)  d_in[0];
    const float* tok  = (const float*)d_in[1];
    const float* pos  = (const float*)d_in[2];
    const float* Wq   = (const float*)d_in[3];
    const float* Wk   = (const float*)d_in[4];
    const float* Wv   = (const float*)d_in[5];
    const float* Wo   = (const float*)d_in[6];
    const float* bo   = (const float*)d_in[7];
    const float* ln1g = (const float*)d_in[8];
    const float* ln1b = (const float*)d_in[9];
    const float* W1   = (const float*)d_in[10];
    const float* b1   = (const float*)d_in[11];
    const float* W2   = (const float*)d_in[12];
    const float* b2   = (const float*)d_in[13];
    const float* ln2g = (const float*)d_in[14];
    const float* ln2b = (const float*)d_in[15];
    const float* lnfg = (const float*)d_in[16];
    const float* lnfb = (const float*)d_in[17];
    const float* Wout = (const float*)d_in[18];
    const float* bout = (const float*)d_in[19];

    float* px;
    f16 *pqkv, *ph, *pat, *pff;
    f16 *pwqkv, *pwo, *pw1, *pw2, *pwout;
    cudaGetSymbolAddress((void**)&px,   g_x);
    cudaGetSymbolAddress((void**)&pqkv, g_qkv);
    cudaGetSymbolAddress((void**)&ph,   g_h);
    cudaGetSymbolAddress((void**)&pat,  g_at);
    cudaGetSymbolAddress((void**)&pff,  g_ff);
    cudaGetSymbolAddress((void**)&pwqkv, g_wqkv);
    cudaGetSymbolAddress((void**)&pwo,   g_wo);
    cudaGetSymbolAddress((void**)&pw1,   g_w1);
    cudaGetSymbolAddress((void**)&pw2,   g_w2);
    cudaGetSymbolAddress((void**)&pwout, g_wout);

    cudaFuncSetAttribute(attn_f16,
                         cudaFuncAttributeMaxDynamicSharedMemorySize, ATT_SMEM);
    cudaFuncSetAttribute((const void*)hgemm<128, 128, 2>,
                         cudaFuncAttributeMaxDynamicSharedMemorySize, SM128);
    cudaFuncSetAttribute((const void*)hgemm<64, 64, 3>,
                         cudaFuncAttributeMaxDynamicSharedMemorySize, SM6464);

    // ---- weight conversion (fp32 -> fp16), 16 elems/thread ----
    int t;
    t = NL * DM * DM / 16;
    wconv<<<(t + 255) / 256, 256>>>(Wq, pwqkv, DM, QKVS, 0,      t);
    wconv<<<(t + 255) / 256, 256>>>(Wk, pwqkv, DM, QKVS, DM,     t);
    wconv<<<(t + 255) / 256, 256>>>(Wv, pwqkv, DM, QKVS, 2 * DM, t);
    wconv<<<(t + 255) / 256, 256>>>(Wo, pwo, DM, DM, 0, t);
    t = NL * DM * DFF / 16;
    wconv<<<(t + 255) / 256, 256>>>(W1, pw1, DFF, DFF, 0, t);
    wconv<<<(t + 255) / 256, 256>>>(W2, pw2, DM, DM, 0, t);
    t = DM * NV / 16;
    wconv<<<(t + 255) / 256, 256>>>(Wout, pwout, NV, NV, 0, t);

    embed_kernel<<<TOK, 256>>>(ctx, tok, pos);

    for (int l = 0; l < NL; l++) {
        size_t oqkv = (size_t)l * DM * QKVS;
        size_t owo  = (size_t)l * DM * DM;
        size_t ow1  = (size_t)l * DM * DFF;
        size_t ow2  = (size_t)l * DFF * DM;

        ln_half<<<TOK, 256>>>(px, ln1g + l * DM, ln1b + l * DM, ph);
        hgemm<128, 128, 2><<<dim3(16, 18), 256, SM128>>>(
            ph, pwqkv + oqkv, nullptr, nullptr, nullptr, pqkv, QKVS, DM, 0);
        attn_f16<<<dim3(SEQ / 64, NH, 2), 128, ATT_SMEM>>>(pqkv, pat);
        hgemm<64, 64, 3><<<dim3(32, 12), 256, SM6464>>>(
            pat, pwo + owo, bo + l * DM, px, px, nullptr, DM, DM, 0);
        ln_half<<<TOK, 256>>>(px, ln2g + l * DM, ln2b + l * DM, ph);
        hgemm<128, 128, 2><<<dim3(16, 24), 256, SM128>>>(
            ph, pw1 + ow1, b1 + (size_t)l * DFF, nullptr, nullptr, pff,
            DFF, DM, 1);
        hgemm<64, 64, 3><<<dim3(32, 12), 256, SM6464>>>(
            pff, pw2 + ow2, b2 + l * DM, px, px, nullptr, DM, DFF, 0);
    }

    ln_half<<<TOK, 256>>>(px, lnfg, lnfb, ph);
    hgemm<128, 128, 2><<<dim3(16, 250), 256, SM128>>>(
        ph, pwout, bout, nullptr, (float*)d_out, nullptr, NV, DM, 0);
}

// round 12
// speedup vs baseline: 7.4135x; 1.0095x over previous
#include <cuda_runtime.h>
#include <cuda_fp16.h>
#include <math.h>
#include <stdint.h>

// Problem constants
#define TOK   2048          // B*S
#define SEQ   1024
#define DM    768
#define DFF   3072
#define NH    12
#define HDIM  64
#define NV    32000
#define NL    6
#define QKVS  (3 * DM)      // 2304

typedef __half f16;

// -------------------- scratch (device globals; no allocation allowed) -----
__device__ __align__(16) float g_x  [TOK * DM];
__device__ __align__(16) f16   g_qkv[TOK * QKVS];
__device__ __align__(16) f16   g_h  [TOK * DM];
__device__ __align__(16) f16   g_at [TOK * DM];
__device__ __align__(16) f16   g_ff [TOK * DFF];
// converted weights [K,N] fp16
__device__ __align__(16) f16 g_wqkv[NL * DM * QKVS];
__device__ __align__(16) f16 g_wo  [NL * DM * DM];
__device__ __align__(16) f16 g_w1  [NL * DM * DFF];
__device__ __align__(16) f16 g_w2  [NL * DFF * DM];
__device__ __align__(16) f16 g_wout[DM * NV];

// -------------------- helpers ---------------------------------------------
__device__ __forceinline__ uint32_t cvta_smem(const void* p) {
    return (uint32_t)__cvta_generic_to_shared(p);
}
__device__ __forceinline__ void cp16(uint32_t s, const void* g) {
    asm volatile("cp.async.cg.shared.global [%0], [%1], 16;" :: "r"(s), "l"(g));
}
__device__ __forceinline__ void ldm_x4(uint32_t* r, uint32_t addr) {
    asm volatile("ldmatrix.sync.aligned.m8n8.x4.shared.b16 {%0,%1,%2,%3},[%4];"
                 : "=r"(r[0]), "=r"(r[1]), "=r"(r[2]), "=r"(r[3]) : "r"(addr));
}
__device__ __forceinline__ void ldm_x4_t(uint32_t* r, uint32_t addr) {
    asm volatile("ldmatrix.sync.aligned.m8n8.x4.trans.shared.b16 {%0,%1,%2,%3},[%4];"
                 : "=r"(r[0]), "=r"(r[1]), "=r"(r[2]), "=r"(r[3]) : "r"(addr));
}
__device__ __forceinline__ void mma_f16(float* c, const uint32_t* a, const uint32_t* b) {
    asm volatile(
        "mma.sync.aligned.m16n8k16.row.col.f32.f16.f16.f32 "
        "{%0,%1,%2,%3},{%4,%5,%6,%7},{%8,%9},{%0,%1,%2,%3};"
        : "+f"(c[0]), "+f"(c[1]), "+f"(c[2]), "+f"(c[3])
        : "r"(a[0]), "r"(a[1]), "r"(a[2]), "r"(a[3]), "r"(b[0]), "r"(b[1]));
}
__device__ __forceinline__ uint32_t pack_h2(float a, float b) {
    __half2 h = __floats2half2_rn(a, b);
    return *(uint32_t*)&h;
}

// -------------------- fused weight convert kernel ---------------------------
// All 7 weight tensors in one launch: deep grid -> streaming bandwidth.
struct WCSeg {
    const float* src;
    f16* dst;
    int cols;
    int dstride;
    int cofs;
};
struct WCParams {
    WCSeg seg[7];
    unsigned start[8];   // prefix of 16-elem unit counts
};

__global__ void wconv_all(WCParams p, unsigned total16) {
    unsigned i = blockIdx.x * 256u + threadIdx.x;
    if (i >= total16) return;
    int s = 0;
#pragma unroll
    for (int j = 1; j < 7; j++) s += (i >= p.start[j]) ? 1 : 0;
    const float* src = p.seg[s].src;
    f16* dst = p.seg[s].dst;
    int cols = p.seg[s].cols;
    int dstride = p.seg[s].dstride;
    int cofs = p.seg[s].cofs;

    size_t e = (size_t)(i - p.start[s]) * 16;
    int r = (int)(e / (unsigned)cols), c = (int)(e - (size_t)r * cols);
    float4 v0 = *(const float4*)(src + e);
    float4 v1 = *(const float4*)(src + e + 4);
    float4 v2 = *(const float4*)(src + e + 8);
    float4 v3 = *(const float4*)(src + e + 12);
    size_t d = (size_t)r * dstride + cofs + c;
    f16 h[16];
    h[0]  = __float2half_rn(v0.x); h[1]  = __float2half_rn(v0.y);
    h[2]  = __float2half_rn(v0.z); h[3]  = __float2half_rn(v0.w);
    h[4]  = __float2half_rn(v1.x); h[5]  = __float2half_rn(v1.y);
    h[6]  = __float2half_rn(v1.z); h[7]  = __float2half_rn(v1.w);
    h[8]  = __float2half_rn(v2.x); h[9]  = __float2half_rn(v2.y);
    h[10] = __float2half_rn(v2.z); h[11] = __float2half_rn(v2.w);
    h[12] = __float2half_rn(v3.x); h[13] = __float2half_rn(v3.y);
    h[14] = __float2half_rn(v3.z); h[15] = __float2half_rn(v3.w);
    *(uint4*)(dst + d)     = *(uint4*)h;
    *(uint4*)(dst + d + 8) = *(uint4*)(h + 8);
}

// -------------------- embedding -------------------------------------------
__global__ void embed_kernel(const int* __restrict__ ctx,
                             const float* __restrict__ tok,
                             const float* __restrict__ pos) {
    int t = blockIdx.x;
    int token = ctx[t];
    int s = t & (SEQ - 1);
#pragma unroll
    for (int i = 0; i < 3; i++) {
        int d = threadIdx.x + i * 256;
        g_x[t * DM + d] = tok[token * DM + d] + pos[s * DM + d];
    }
}

// -------------------- layernorm -> fp16 ------------------------------------
__global__ void ln_half(const float* __restrict__ in,
                        const float* __restrict__ gg,
                        const float* __restrict__ bb,
                        f16* __restrict__ out) {
    int row = blockIdx.x;
    const float* x = in + row * DM;
    float v[3];
    float s = 0.f, ss = 0.f;
#pragma unroll
    for (int i = 0; i < 3; i++) {
        v[i] = x[threadIdx.x + i * 256];
        s  += v[i];
        ss += v[i] * v[i];
    }
#pragma unroll
    for (int m = 16; m; m >>= 1) {
        s  += __shfl_xor_sync(0xffffffffu, s,  m);
        ss += __shfl_xor_sync(0xffffffffu, ss, m);
    }
    __shared__ float sa[8], sb[8];
    int w = threadIdx.x >> 5, lane = threadIdx.x & 31;
    if (lane == 0) { sa[w] = s; sb[w] = ss; }
    __syncthreads();
    s = 0.f; ss = 0.f;
#pragma unroll
    for (int i = 0; i < 8; i++) { s += sa[i]; ss += sb[i]; }
    float mean = s * (1.0f / DM);
    float var  = ss * (1.0f / DM) - mean * mean;
    float inv  = rsqrtf(var + 1e-5f);
#pragma unroll
    for (int i = 0; i < 3; i++) {
        int d = threadIdx.x + i * 256;
        float y = (v[i] - mean) * inv * gg[d] + bb[d];
        out[row * DM + d] = __float2half_rn(y);
    }
}

// -------------------- fp16 tensor-core GEMM (BK=64, tiled BM x BN) ---------
__device__ __forceinline__ uint32_t swzA(int row, int kc) {   // kc 0..7
    return (uint32_t)(row * 128 + ((kc ^ (row & 7)) << 4));
}
template<int CR>   // chunks per B row: 16 (BN=128) or 8 (BN=64)
__device__ __forceinline__ uint32_t swzB(int k, int nc) {
    int c = (CR == 16) ? (((nc & 7) ^ (k & 7)) | (nc & 8)) : (nc ^ (k & 7));
    return (uint32_t)(k * (CR * 16) + (c << 4));
}

template<int BM, int BN, int OCC>
__global__ __launch_bounds__(256, OCC)
void hgemm(const f16* __restrict__ A, const f16* __restrict__ B,
           const float* __restrict__ bias, const float* __restrict__ res,
           float* __restrict__ C, f16* __restrict__ Oh,
           int N, int K, int relu) {
    constexpr int WM = BM / 2;
    constexpr int MT = WM / 16;
    constexpr int WN = BN / 4;
    constexpr int NT = WN / 8;
    constexpr int CR = BN / 8;
    constexpr int ABYTES = BM * 128;
    constexpr int BBYTES = 64 * BN * 2;
    constexpr int STAGE  = ABYTES + BBYTES;
    constexpr int NA = BM / 32;
    constexpr int NB = CR / 4;

    extern __shared__ char smc[];
    uint32_t sbase = cvta_smem(smc);

    int tid  = threadIdx.x;
    int lane = tid & 31;
    int warp = tid >> 5;
    int wm = warp >> 2;
    int wn = warp & 3;
    int g  = lane >> 2;
    int tg = lane & 3;
    int bm = blockIdx.x, bn = blockIdx.y;

    float acc[MT][NT][4];
#pragma unroll
    for (int mi = 0; mi < MT; mi++)
#pragma unroll
        for (int ni = 0; ni < NT; ni++)
#pragma unroll
            for (int j = 0; j < 4; j++) acc[mi][ni][j] = 0.f;

#define LOADSTAGE(IT)                                                         \
    {                                                                         \
        int _it = (IT);                                                       \
        uint32_t st = sbase + (_it % 3) * STAGE;                              \
        _Pragma("unroll")                                                     \
        for (int u = 0; u < NA; u++) {                                        \
            int cu = tid + u * 256;                                           \
            int arow = cu >> 3, akc = cu & 7;                                 \
            uint32_t so = st + swzA(arow, akc);                               \
            size_t go = (size_t)(bm * BM + arow) * K + _it * 64 + akc * 8;    \
            cp16(so, A + go);                                                 \
        }                                                                     \
        _Pragma("unroll")                                                     \
        for (int u = 0; u < NB; u++) {                                        \
            int cu = tid + u * 256;                                           \
            int bk = cu / CR, bnc = cu % CR;                                  \
            uint32_t so = st + ABYTES + swzB<CR>(bk, bnc);                    \
            size_t go = (size_t)(_it * 64 + bk) * N + bn * BN + bnc * 8;      \
            cp16(so, B + go);                                                 \
        }                                                                     \
    }

    int nIter = K >> 6;
    LOADSTAGE(0); asm volatile("cp.async.commit_group;");
    LOADSTAGE(1); asm volatile("cp.async.commit_group;");

    int a_lrow = wm * WM + (lane & 15);
    int a_koff = (lane >> 4) & 1;
    int b_lk   = lane & 15;
    int b_noff = (lane >> 4) & 1;

    for (int it = 0; it < nIter; it++) {
        asm volatile("cp.async.wait_group 1;");
        __syncthreads();
        uint32_t sb = sbase + (it % 3) * STAGE;

#pragma unroll
        for (int k16 = 0; k16 < 4; k16++) {
            uint32_t Af[MT][4], Bf[NT][2];
            int kc = k16 * 2 + a_koff;
#pragma unroll
            for (int mi = 0; mi < MT; mi++)
                ldm_x4(Af[mi], sb + swzA(a_lrow + mi * 16, kc));
            int kk = k16 * 16 + b_lk;
#pragma unroll
            for (int p = 0; p < NT / 2; p++) {
                uint32_t r4[4];
                ldm_x4_t(r4, sb + ABYTES + swzB<CR>(kk, wn * NT + 2 * p + b_noff));
                Bf[p*2][0] = r4[0]; Bf[p*2][1] = r4[1];
                Bf[p*2+1][0] = r4[2]; Bf[p*2+1][1] = r4[3];
            }
#pragma unroll
            for (int mi = 0; mi < MT; mi++)
#pragma unroll
                for (int ni = 0; ni < NT; ni++) mma_f16(acc[mi][ni], Af[mi], Bf[ni]);
        }

        if (it + 2 < nIter) LOADSTAGE(it + 2);
        asm volatile("cp.async.commit_group;");
    }
#undef LOADSTAGE

#pragma unroll
    for (int mi = 0; mi < MT; mi++) {
        int row0 = bm * BM + wm * WM + mi * 16 + g;
#pragma unroll
        for (int ni = 0; ni < NT; ni++) {
            int col = bn * BN + wn * WN + ni * 8 + 2 * tg;
            float b0 = 0.f, b1 = 0.f;
            if (bias) { b0 = bias[col]; b1 = bias[col + 1]; }
#pragma unroll
            for (int half = 0; half < 2; half++) {
                int row = row0 + half * 8;
                float v0 = acc[mi][ni][half * 2 + 0] + b0;
                float v1 = acc[mi][ni][half * 2 + 1] + b1;
                if (relu) { v0 = fmaxf(v0, 0.f); v1 = fmaxf(v1, 0.f); }
                size_t idx = (size_t)row * N + col;
                if (Oh) {
                    *(__half2*)(Oh + idx) =
                        __half2(__float2half_rn(v0), __float2half_rn(v1));
                } else {
                    if (res) {
                        float2 r2 = *(const float2*)(res + idx);
                        v0 += r2.x; v1 += r2.y;
                    }
                    *(float2*)(C + idx) = make_float2(v0, v1);
                }
            }
        }
    }
}

// -------------------- fp16 tensor-core flash attention ----------------------
#define AQ_BYTES 8192
#define AKV_STAGE 16384
#define ATT_SMEM (AQ_BYTES + 3 * AKV_STAGE)

__device__ __forceinline__ uint32_t swzR(int row, int c) {   // 128B rows
    return (uint32_t)(row * 128 + ((c ^ (row & 7)) << 4));
}

__global__ __launch_bounds__(128)
void attn_f16(const f16* __restrict__ QKV, f16* __restrict__ O) {
    extern __shared__ char smc[];
    uint32_t sb = cvta_smem(smc);

    int qt = gridDim.x - 1 - blockIdx.x;   // heavy tiles first
    int h = blockIdx.y, b = blockIdx.z;
    int tid = threadIdx.x, lane = tid & 31, warp = tid >> 5;
    int g = lane >> 2, tg = lane & 3;
    int wrow = warp * 16;
    int nT = qt + 1;

    const f16* Qg = QKV + (size_t)(b * SEQ + qt * 64) * QKVS + h * HDIM;

#define LOADQ()                                                               \
    {                                                                         \
        _Pragma("unroll")                                                     \
        for (int u = 0; u < 4; u++) {                                         \
            int idx = tid + u * 128;                                          \
            int row = idx >> 3, c = idx & 7;                                  \
            cp16(sb + swzR(row, c), Qg + (size_t)row * QKVS + c * 8);         \
        }                                                                     \
    }
#define LOADKV(SLOT, KT)                                                      \
    {                                                                         \
        uint32_t st = sb + AQ_BYTES + ((SLOT) % 3) * AKV_STAGE;               \
        const f16* Kg = QKV + (size_t)(b * SEQ + (KT) * 64) * QKVS            \
                        + DM + h * HDIM;                                      \
        _Pragma("unroll")                                                     \
        for (int u = 0; u < 4; u++) {                                         \
            int idx = tid + u * 128;                                          \
            int row = idx >> 3, c = idx & 7;                                  \
            uint32_t so = st + swzR(row, c);                                  \
            size_t go = (size_t)row * QKVS + c * 8;                           \
            cp16(so, Kg + go);                                                \
            cp16(so + 8192, Kg + DM + go);                                    \
        }                                                                     \
    }

    LOADQ(); LOADKV(0, 0);
    asm volatile("cp.async.commit_group;");
    if (1 < nT) LOADKV(1, 1);
    asm volatile("cp.async.commit_group;");

    float o[8][4];
#pragma unroll
    for (int nt = 0; nt < 8; nt++)
#pragma unroll
        for (int j = 0; j < 4; j++) o[nt][j] = 0.f;
    float m[2] = {-INFINITY, -INFINITY}, l[2] = {0.f, 0.f};
    uint32_t qf[4][4];

    for (int kt = 0; kt < nT; kt++) {
        asm volatile("cp.async.wait_group 1;");
        __syncthreads();

        if (kt == 0) {
#pragma unroll
            for (int i = 0; i < 4; i++) {
                int row = wrow + (lane & 15);
                int c = 2 * i + (lane >> 4);
                ldm_x4(qf[i], sb + swzR(row, c));
            }
        }

        if (kt + 2 < nT) LOADKV(kt + 2, kt + 2);
        asm volatile("cp.async.commit_group;");

        uint32_t kb = sb + AQ_BYTES + (kt % 3) * AKV_STAGE;
        float s[8][4];
#pragma unroll
        for (int nt = 0; nt < 8; nt++)
#pragma unroll
            for (int j = 0; j < 4; j++) s[nt][j] = 0.f;

#pragma unroll
        for (int ntp = 0; ntp < 4; ntp++) {
            int krow = ntp * 16 + (lane & 7) + ((lane >> 4) << 3);
#pragma unroll
            for (int i = 0; i < 4; i++) {
                uint32_t r4[4];
                int c = 2 * i + ((lane >> 3) & 1);
                ldm_x4(r4, kb + swzR(krow, c));
                mma_f16(s[2 * ntp],     qf[i], r4);
                mma_f16(s[2 * ntp + 1], qf[i], r4 + 2);
            }
        }

#pragma unroll
        for (int nt = 0; nt < 8; nt++)
#pragma unroll
            for (int j = 0; j < 4; j++) s[nt][j] *= 0.125f;
        if (kt == qt) {
            int rA = wrow + g, rB = rA + 8;
#pragma unroll
            for (int nt = 0; nt < 8; nt++) {
                int cc = nt * 8 + 2 * tg;
                if (cc     > rA) s[nt][0] = -1e30f;
                if (cc + 1 > rA) s[nt][1] = -1e30f;
                if (cc     > rB) s[nt][2] = -1e30f;
                if (cc + 1 > rB) s[nt][3] = -1e30f;
            }
        }

        float mxA = -1e30f, mxB = -1e30f;
#pragma unroll
        for (int nt = 0; nt < 8; nt++) {
            mxA = fmaxf(mxA, fmaxf(s[nt][0], s[nt][1]));
            mxB = fmaxf(mxB, fmaxf(s[nt][2], s[nt][3]));
        }
        mxA = fmaxf(mxA, __shfl_xor_sync(0xffffffffu, mxA, 1));
        mxA = fmaxf(mxA, __shfl_xor_sync(0xffffffffu, mxA, 2));
        mxB = fmaxf(mxB, __shfl_xor_sync(0xffffffffu, mxB, 1));
        mxB = fmaxf(mxB, __shfl_xor_sync(0xffffffffu, mxB, 2));
        float mnA = fmaxf(m[0], mxA), mnB = fmaxf(m[1], mxB);
        float fA = __expf(m[0] - mnA), fB = __expf(m[1] - mnB);
        float sA = 0.f, sB = 0.f;
#pragma unroll
        for (int nt = 0; nt < 8; nt++) {
            s[nt][0] = __expf(s[nt][0] - mnA);
            s[nt][1] = __expf(s[nt][1] - mnA);
            s[nt][2] = __expf(s[nt][2] - mnB);
            s[nt][3] = __expf(s[nt][3] - mnB);
            sA += s[nt][0] + s[nt][1];
            sB += s[nt][2] + s[nt][3];
        }
        sA += __shfl_xor_sync(0xffffffffu, sA, 1);
        sA += __shfl_xor_sync(0xffffffffu, sA, 2);
        sB += __shfl_xor_sync(0xffffffffu, sB, 1);
        sB += __shfl_xor_sync(0xffffffffu, sB, 2);
        l[0] = l[0] * fA + sA; m[0] = mnA;
        l[1] = l[1] * fB + sB; m[1] = mnB;
#pragma unroll
        for (int nt = 0; nt < 8; nt++) {
            o[nt][0] *= fA; o[nt][1] *= fA;
            o[nt][2] *= fB; o[nt][3] *= fB;
        }

        uint32_t pk[4][4];
#pragma unroll
        for (int i = 0; i < 4; i++) {
            pk[i][0] = pack_h2(s[2*i][0],   s[2*i][1]);
            pk[i][1] = pack_h2(s[2*i][2],   s[2*i][3]);
            pk[i][2] = pack_h2(s[2*i+1][0], s[2*i+1][1]);
            pk[i][3] = pack_h2(s[2*i+1][2], s[2*i+1][3]);
        }

        uint32_t vb = kb + 8192;
#pragma unroll
        for (int i = 0; i < 4; i++) {
            int vrow = i * 16 + (lane & 15);
#pragma unroll
            for (int hdp = 0; hdp < 4; hdp++) {
                uint32_t r4[4];
                int c = 2 * hdp + (lane >> 4);
                ldm_x4_t(r4, vb + swzR(vrow, c));
                mma_f16(o[2 * hdp],     pk[i], r4);
                mma_f16(o[2 * hdp + 1], pk[i], r4 + 2);
            }
        }
    }
#undef LOADQ
#undef LOADKV

    float iA = 1.f / l[0], iB = 1.f / l[1];
    size_t rowA = (size_t)(b * SEQ + qt * 64 + wrow + g);
    f16* oA = O + rowA * DM + h * HDIM;
    f16* oB = oA + (size_t)8 * DM;
#pragma unroll
    for (int nt = 0; nt < 8; nt++) {
        int cc = nt * 8 + 2 * tg;
        *(__half2*)(oA + cc) = __floats2half2_rn(o[nt][0] * iA, o[nt][1] * iA);
        *(__half2*)(oB + cc) = __floats2half2_rn(o[nt][2] * iB, o[nt][3] * iB);
    }
}

// -------------------- host orchestration ----------------------------------
#define SM128 (3 * (128 * 128 + 16384))   // 98304
#define SM6464 (3 * (64 * 128 + 8192))    // 49152

extern "C" void kernel_launch(void* const* d_in, const int* in_sizes, int n_in,
                              void* d_out, int out_size) {
    const int*   ctx  = (const int*)  d_in[0];
    const float* tok  = (const float*)d_in[1];
    const float* pos  = (const float*)d_in[2];
    const float* Wq   = (const float*)d_in[3];
    const float* Wk   = (const float*)d_in[4];
    const float* Wv   = (const float*)d_in[5];
    const float* Wo   = (const float*)d_in[6];
    const float* bo   = (const float*)d_in[7];
    const float* ln1g = (const float*)d_in[8];
    const float* ln1b = (const float*)d_in[9];
    const float* W1   = (const float*)d_in[10];
    const float* b1   = (const float*)d_in[11];
    const float* W2   = (const float*)d_in[12];
    const float* b2   = (const float*)d_in[13];
    const float* ln2g = (const float*)d_in[14];
    const float* ln2b = (const float*)d_in[15];
    const float* lnfg = (const float*)d_in[16];
    const float* lnfb = (const float*)d_in[17];
    const float* Wout = (const float*)d_in[18];
    const float* bout = (const float*)d_in[19];

    float* px;
    f16 *pqkv, *ph, *pat, *pff;
    f16 *pwqkv, *pwo, *pw1, *pw2, *pwout;
    cudaGetSymbolAddress((void**)&px,   g_x);
    cudaGetSymbolAddress((void**)&pqkv, g_qkv);
    cudaGetSymbolAddress((void**)&ph,   g_h);
    cudaGetSymbolAddress((void**)&pat,  g_at);
    cudaGetSymbolAddress((void**)&pff,  g_ff);
    cudaGetSymbolAddress((void**)&pwqkv, g_wqkv);
    cudaGetSymbolAddress((void**)&pwo,   g_wo);
    cudaGetSymbolAddress((void**)&pw1,   g_w1);
    cudaGetSymbolAddress((void**)&pw2,   g_w2);
    cudaGetSymbolAddress((void**)&pwout, g_wout);

    cudaFuncSetAttribute(attn_f16,
                         cudaFuncAttributeMaxDynamicSharedMemorySize, ATT_SMEM);
    cudaFuncSetAttribute((const void*)hgemm<128, 128, 2>,
                         cudaFuncAttributeMaxDynamicSharedMemorySize, SM128);
    cudaFuncSetAttribute((const void*)hgemm<64, 64, 3>,
                         cudaFuncAttributeMaxDynamicSharedMemorySize, SM6464);

    // ---- fused weight conversion (single launch) ----
    {
        WCParams p;
        unsigned nQ  = (unsigned)(NL * DM * DM / 16);     // per Q/K/V/Wo
        unsigned nF  = (unsigned)(NL * DM * DFF / 16);    // per W1/W2
        unsigned nO  = (unsigned)(DM * NV / 16);          // Wout
        p.seg[0] = {Wq,   pwqkv, DM,  QKVS, 0};
        p.seg[1] = {Wk,   pwqkv, DM,  QKVS, DM};
        p.seg[2] = {Wv,   pwqkv, DM,  QKVS, 2 * DM};
        p.seg[3] = {Wo,   pwo,   DM,  DM,   0};
        p.seg[4] = {W1,   pw1,   DFF, DFF,  0};
        p.seg[5] = {W2,   pw2,   DM,  DM,   0};
        p.seg[6] = {Wout, pwout, NV,  NV,   0};
        unsigned counts[7] = {nQ, nQ, nQ, nQ, nF, nF, nO};
        unsigned acc = 0;
        for (int i = 0; i < 7; i++) { p.start[i] = acc; acc += counts[i]; }
        p.start[7] = acc;
        wconv_all<<<(acc + 255) / 256, 256>>>(p, acc);
    }

    embed_kernel<<<TOK, 256>>>(ctx, tok, pos);

    for (int l = 0; l < NL; l++) {
        size_t oqkv = (size_t)l * DM * QKVS;
        size_t owo  = (size_t)l * DM * DM;
        size_t ow1  = (size_t)l * DM * DFF;
        size_t ow2  = (size_t)l * DFF * DM;

        ln_half<<<TOK, 256>>>(px, ln1g + l * DM, ln1b + l * DM, ph);
        hgemm<128, 128, 2><<<dim3(16, 18), 256, SM128>>>(
            ph, pwqkv + oqkv, nullptr, nullptr, nullptr, pqkv, QKVS, DM, 0);
        attn_f16<<<dim3(SEQ / 64, NH, 2), 128, ATT_SMEM>>>(pqkv, pat);
        hgemm<64, 64, 3><<<dim3(32, 12), 256, SM6464>>>(
            pat, pwo + owo, bo + l * DM, px, px, nullptr, DM, DM, 0);
        ln_half<<<TOK, 256>>>(px, ln2g + l * DM, ln2b + l * DM, ph);
        hgemm<128, 128, 2><<<dim3(16, 24), 256, SM128>>>(
            ph, pw1 + ow1, b1 + (size_t)l * DFF, nullptr, nullptr, pff,
            DFF, DM, 1);
        hgemm<64, 64, 3><<<dim3(32, 12), 256, SM6464>>>(
            pff, pw2 + ow2, b2 + l * DM, px, px, nullptr, DM, DFF, 0);
    }

    ln_half<<<TOK, 256>>>(px, lnfg, lnfb, ph);
    hgemm<128, 128, 2><<<dim3(16, 250), 256, SM128>>>(
        ph, pwout, bout, nullptr, (float*)d_out, nullptr, NV, DM, 0);
}